// round 8
// baseline (speedup 1.0000x reference)
#include <cuda_runtime.h>
#include <math.h>
#include <math_constants.h>

// Problem constants
#define Bz   2
#define Nn   4096
#define DIMM 1024
#define Hh   16
#define Dd   64
#define Mm   266
#define BHh  (Bz*Hh)        // 32
#define ROWS (Bz*Nn)        // 8192
#define LDP  288            // padded feature row length

#define NORMALIZER 0.35355339059327373f   // 64^-0.25
#define RATIO      0.061313933948496576f  // 266^-0.5
#define EPSV       1e-4f
#define LOG2E      1.4426950408889634f

#define PITCH   20
#define STAGES  5
#define STGW    (128*PITCH)                        // floats per operand stage
#define BOFFW   (STAGES*STGW)                      // float offset of B region
#define CORE_SMEM (STAGES*STGW*4*2)                // 102400 bytes

// ---------------- scratch -------------------------------------------------------
__device__ float g_q[ROWS*DIMM];
__device__ float g_k[ROWS*DIMM];
__device__ float g_v[ROWS*DIMM];
__device__ float g_attn[ROWS*DIMM];
__device__ float g_xr[ROWS*DIMM];                  // tf32-rounded x
__device__ float g_w4[4*DIMM*DIMM];                // tf32-rounded Wq,Wk,Wv,Wo
__device__ float g_projr[384*Dd];                  // rounded*NORMALIZER, padded
__device__ float g_qp[(size_t)BHh*Nn*LDP + 128];
__device__ float g_kp[(size_t)BHh*Nn*LDP + 128];   // +128 pad: ctx m-tile 2 over-reads
__device__ float g_kmax[BHh];
__device__ float g_kcum[BHh*LDP];
__device__ float g_ctxT[(size_t)BHh*128*LDP];      // ctx transposed [e][m], rows 64..127 stay 0
__device__ float g_dinv[BHh*Nn];

// ---------------- helpers -------------------------------------------------------
__device__ __forceinline__ unsigned smem_u32(const void* p) {
    unsigned a;
    asm("{ .reg .u64 t; cvta.to.shared.u64 t, %1; cvt.u32.u64 %0, t; }" : "=r"(a) : "l"(p));
    return a;
}
__device__ __forceinline__ float rna_tf32(float v) {
    unsigned u;
    asm("cvt.rna.tf32.f32 %0, %1;" : "=r"(u) : "f"(v));
    return __uint_as_float(u);
}
__device__ __forceinline__ float fexp(float x) {
    float y;
    asm("ex2.approx.f32 %0, %1;" : "=f"(y) : "f"(x * LOG2E));
    return y;
}
__device__ __forceinline__ void cp16(unsigned dst, const float* src) {
    asm volatile("cp.async.ca.shared.global [%0], [%1], 16;" :: "r"(dst), "l"(src));
}

__device__ __forceinline__ void mma_tf32(float c[4],
                                         unsigned a0, unsigned a1, unsigned a2, unsigned a3,
                                         unsigned b0, unsigned b1) {
    asm volatile(
        "mma.sync.aligned.m16n8k8.row.col.f32.tf32.tf32.f32 "
        "{%0,%1,%2,%3}, {%4,%5,%6,%7}, {%8,%9}, {%0,%1,%2,%3};"
        : "+f"(c[0]), "+f"(c[1]), "+f"(c[2]), "+f"(c[3])
        : "r"(a0), "r"(a1), "r"(a2), "r"(a3), "r"(b0), "r"(b1));
}

__device__ __forceinline__ void atomicMaxFloat(float* addr, float val) {
    int* a = (int*)addr;
    int old = *a;
    while (__int_as_float(old) < val) {
        int assumed = old;
        old = atomicCAS(a, assumed, __float_as_int(val));
        if (old == assumed) break;
    }
}

// ---------------- prep: init + proj rounding --------------------------------------
__global__ void prep_small(const float* __restrict__ proj) {
    size_t t = (size_t)blockIdx.x * blockDim.x + threadIdx.x;
    if (t < BHh) g_kmax[t] = -CUDART_INF_F;
    if (t < BHh * LDP) g_kcum[t] = 0.f;
    if (t < 384 * Dd) {
        int m = (int)(t >> 6);
        g_projr[t] = (m < Mm) ? rna_tf32(proj[t] * NORMALIZER) : 0.f;
    }
    if (t < (size_t)BHh * Dd * LDP) {
        size_t bh = t / (Dd * LDP);
        size_t rem = t - bh * (Dd * LDP);
        g_ctxT[bh * 128 * LDP + rem] = 0.f;
    }
}

__global__ void round_x_kernel(const float* __restrict__ in) {
    int i = blockIdx.x * blockDim.x + threadIdx.x;
    float4 v = ((const float4*)in)[i];
    v.x = rna_tf32(v.x); v.y = rna_tf32(v.y); v.z = rna_tf32(v.z); v.w = rna_tf32(v.w);
    ((float4*)g_xr)[i] = v;
}
__global__ void round_w_kernel(const float* __restrict__ w0, const float* __restrict__ w1,
                               const float* __restrict__ w2, const float* __restrict__ w3) {
    int z = blockIdx.y;
    const float* w = (z == 0) ? w0 : (z == 1) ? w1 : (z == 2) ? w2 : w3;
    int i = blockIdx.x * blockDim.x + threadIdx.x;
    float4 v = ((const float4*)w)[i];
    v.x = rna_tf32(v.x); v.y = rna_tf32(v.y); v.z = rna_tf32(v.z); v.w = rna_tf32(v.w);
    ((float4*)(g_w4 + (size_t)z * DIMM * DIMM))[i] = v;
}
// round ctxT rows 0..63 per bh, in place
__global__ void round_ctxT() {
    size_t i = (size_t)blockIdx.x * 256 + threadIdx.x;      // float4 index
    const size_t per_bh = (size_t)Dd * LDP / 4;             // 4608
    if (i >= (size_t)BHh * per_bh) return;
    size_t bh = i / per_bh;
    size_t rem = i - bh * per_bh;
    float4* p = (float4*)(g_ctxT + bh * 128 * LDP) + rem;
    float4 v = *p;
    v.x = rna_tf32(v.x); v.y = rna_tf32(v.y); v.z = rna_tf32(v.z); v.w = rna_tf32(v.w);
    *p = v;
}

// ---------------- mma core: 5-stage cp.async, single sync/wait per ktile ------------
// C[r][c] = sum_k A[r][k] * W[c][k] (+bias) (*rowscale[r]).  128x128, 8 warps 2m x 4n.
template<bool BIAS, bool RNAOUT>
__device__ __forceinline__ void mma_core(const float* __restrict__ A, int lda,
                                         const float* __restrict__ W, int ldb,
                                         float* __restrict__ C, int ldc,
                                         int K, int nvalid,
                                         const float* __restrict__ bias,
                                         const float* __restrict__ rowscale,
                                         float* __restrict__ maxout, int maxcols, int bhidx) {
    extern __shared__ float sm[];
    __shared__ float mred[8];
    float* Asp = sm;
    float* Bsp = sm + BOFFW;

    const int tid = threadIdx.x;
    const int wid = tid >> 5, lid = tid & 31;
    const int wm = wid >> 2;
    const int wn = wid & 3;
    const int g = lid >> 2, q = lid & 3;

    const int lr0 = tid >> 2;           // 0..63
    const int lr1 = lr0 + 64;
    const int lc0 = (tid & 3) << 2;

    const unsigned sbase = smem_u32(sm);
    const unsigned a0off = sbase + (unsigned)((lr0 * PITCH + lc0) * 4);
    const unsigned a1off = sbase + (unsigned)((lr1 * PITCH + lc0) * 4);
    const unsigned b0off = a0off + (unsigned)(BOFFW * 4);
    const unsigned b1off = a1off + (unsigned)(BOFFW * 4);
    const unsigned stgsz = (unsigned)(STGW * 4);

    const float* Ag0 = A + (size_t)lr0 * lda + lc0;
    const float* Ag1 = A + (size_t)lr1 * lda + lc0;
    const float* Wg0 = W + (size_t)lr0 * ldb + lc0;
    const float* Wg1 = W + (size_t)lr1 * ldb + lc0;

    float acc[4][4][4] = {};
    const int NT = K >> 4;

    // prologue: ktiles 0..3 -> stages 0..3, one group each (always commit)
    #pragma unroll
    for (int p = 0; p < 4; ++p) {
        if (p < NT) {
            const unsigned d = (unsigned)p * stgsz;
            const int kb = p * 16;
            cp16(a0off + d, Ag0 + kb); cp16(a1off + d, Ag1 + kb);
            cp16(b0off + d, Wg0 + kb); cp16(b1off + d, Wg1 + kb);
        }
        asm volatile("cp.async.commit_group;" ::: "memory");
    }

    int s = 0;
    for (int kt = 0; kt < NT; ++kt) {
        asm volatile("cp.async.wait_group 3;" ::: "memory");
        __syncthreads();   // stage s ready for all; all warps done reading stage (s-1)%5

        if (kt + 4 < NT) {
            int s4 = s - 1; if (s4 < 0) s4 = STAGES - 1;   // (s+4)%5
            const unsigned d = (unsigned)s4 * stgsz;
            const int kb = (kt + 4) * 16;
            cp16(a0off + d, Ag0 + kb); cp16(a1off + d, Ag1 + kb);
            cp16(b0off + d, Wg0 + kb); cp16(b1off + d, Wg1 + kb);
        }
        asm volatile("cp.async.commit_group;" ::: "memory");

        const float* As_ = Asp + s * STGW;
        const float* Bs_ = Bsp + s * STGW;

        #pragma unroll
        for (int ks = 0; ks < 16; ks += 8) {
            unsigned af[4][4], bf[4][2];
            #pragma unroll
            for (int mi = 0; mi < 4; ++mi) {
                const int rb = wm * 64 + mi * 16;
                af[mi][0] = __float_as_uint(As_[(rb + g) * PITCH + ks + q]);
                af[mi][1] = __float_as_uint(As_[(rb + g + 8) * PITCH + ks + q]);
                af[mi][2] = __float_as_uint(As_[(rb + g) * PITCH + ks + q + 4]);
                af[mi][3] = __float_as_uint(As_[(rb + g + 8) * PITCH + ks + q + 4]);
            }
            #pragma unroll
            for (int ni = 0; ni < 4; ++ni) {
                const int cb = wn * 32 + ni * 8;
                bf[ni][0] = __float_as_uint(Bs_[(cb + g) * PITCH + ks + q]);
                bf[ni][1] = __float_as_uint(Bs_[(cb + g) * PITCH + ks + q + 4]);
            }
            #pragma unroll
            for (int mi = 0; mi < 4; ++mi)
                #pragma unroll
                for (int ni = 0; ni < 4; ++ni)
                    mma_tf32(acc[mi][ni], af[mi][0], af[mi][1], af[mi][2], af[mi][3],
                             bf[ni][0], bf[ni][1]);
        }
        ++s; if (s == STAGES) s = 0;
    }
    asm volatile("cp.async.wait_group 0;" ::: "memory");

    #pragma unroll
    for (int mi = 0; mi < 4; ++mi) {
        const int r_ = wm * 64 + mi * 16 + g;
        float sc0 = 1.f, sc1 = 1.f;
        if (rowscale) { sc0 = rowscale[r_]; sc1 = rowscale[r_ + 8]; }
        #pragma unroll
        for (int ni = 0; ni < 4; ++ni) {
            const int crel = wn * 32 + ni * 8 + (q << 1);
            if (crel < nvalid) {
                float2 v0 = make_float2(acc[mi][ni][0], acc[mi][ni][1]);
                float2 v1 = make_float2(acc[mi][ni][2], acc[mi][ni][3]);
                if (BIAS) {
                    v0.x += bias[crel]; v0.y += bias[crel + 1];
                    v1.x += bias[crel]; v1.y += bias[crel + 1];
                }
                if (rowscale) {
                    v0.x *= sc0; v0.y *= sc0;
                    v1.x *= sc1; v1.y *= sc1;
                }
                if (RNAOUT) {
                    v0.x = rna_tf32(v0.x); v0.y = rna_tf32(v0.y);
                    v1.x = rna_tf32(v1.x); v1.y = rna_tf32(v1.y);
                }
                *(float2*)&C[(size_t)r_ * ldc + crel]       = v0;
                *(float2*)&C[(size_t)(r_ + 8) * ldc + crel] = v1;
            }
        }
    }

    if (maxout) {
        float mx = -CUDART_INF_F;
        #pragma unroll
        for (int mi = 0; mi < 4; ++mi)
            #pragma unroll
            for (int ni = 0; ni < 4; ++ni)
                #pragma unroll
                for (int e = 0; e < 4; ++e) {
                    int crel = wn * 32 + ni * 8 + (q << 1) + (e & 1);
                    if (crel < maxcols) mx = fmaxf(mx, acc[mi][ni][e]);
                }
        #pragma unroll
        for (int o = 16; o > 0; o >>= 1)
            mx = fmaxf(mx, __shfl_xor_sync(0xffffffffu, mx, o));
        if (lid == 0) mred[wid] = mx;
        __syncthreads();
        if (tid == 0) {
            float bm = mred[0];
            #pragma unroll
            for (int w = 1; w < 8; ++w) bm = fmaxf(bm, mred[w]);
            atomicMaxFloat(&maxout[bhidx], bm);
        }
    }
}

// ---------------- wrappers --------------------------------------------------------
__global__ void __launch_bounds__(256, 2) qkv_kernel() {
    const int z = blockIdx.z;
    const float* W = g_w4 + (size_t)z * DIMM * DIMM;
    float* C = (z == 0) ? g_q : (z == 1) ? g_k : g_v;
    const int row0 = blockIdx.y * 128, col0 = blockIdx.x * 128;
    mma_core<false, true>(g_xr + (size_t)row0 * DIMM, DIMM,
                    W + (size_t)col0 * DIMM, DIMM,
                    C + (size_t)row0 * DIMM + col0, DIMM, DIMM, 128,
                    nullptr, nullptr, nullptr, 0, 0);
}

__global__ void __launch_bounds__(256, 2) final_kernel(const float* __restrict__ bo,
                                                       float* __restrict__ out) {
    const int row0 = blockIdx.y * 128, col0 = blockIdx.x * 128;
    mma_core<true, false>(g_attn + (size_t)row0 * DIMM, DIMM,
                   g_w4 + 3 * (size_t)DIMM * DIMM + (size_t)col0 * DIMM, DIMM,
                   out + (size_t)row0 * DIMM + col0, DIMM, DIMM, 128,
                   bo + col0, nullptr, nullptr, 0, 0);
}

__global__ void __launch_bounds__(256, 2) dash_kernel() {
    const int z = blockIdx.z;                 // 0 = q, 1 = k
    const float* src = z ? g_k : g_q;
    float* dst = z ? g_kp : g_qp;
    const int bh = blockIdx.y >> 5, nc = blockIdx.y & 31;
    const int b = bh >> 4, h = bh & 15;
    const int col0 = blockIdx.x * 128;
    const int row0 = nc * 128;
    mma_core<false, false>(src + ((size_t)(b * Nn) + row0) * DIMM + h * Dd, DIMM,
                    g_projr + (size_t)col0 * Dd, Dd,
                    dst + ((size_t)bh * Nn + row0) * LDP + col0, LDP,
                    Dd, LDP - col0, nullptr, nullptr,
                    z ? g_kmax : nullptr, Mm - col0, bh);
}

// out[b,n,h,e] = Dinv[n] * sum_m qp[n,m] * ctxT[e,m]   (tensorized, K=288)
__global__ void __launch_bounds__(256, 2) out_mma() {
    const int t = blockIdx.y;
    const int bh = t >> 5, nt = t & 31;
    const int b = bh >> 4, h = bh & 15;
    const int row0 = nt * 128;
    mma_core<false, true>(g_qp + ((size_t)bh * Nn + row0) * LDP, LDP,
                    g_ctxT + (size_t)bh * 128 * LDP, LDP,
                    g_attn + ((size_t)(b * Nn) + row0) * DIMM + h * Dd, DIMM,
                    LDP, Dd, nullptr,
                    g_dinv + (size_t)bh * Nn + row0, nullptr, 0, 0);
}

// ---------------- ctx via tensor cores: ctx[m][e] = sum_n kp[n][m] * v[n][e] ----------
// 4-stage cp.async, single sync. 8 warps 4m x 2n, warp 32x32, transposed frag loads.
#define CPA 132
#define CPB 68
#define CSTAGES 4
#define CTX_SMEM (CSTAGES*16*(CPA+CPB)*4)          // 51200 bytes
__global__ void __launch_bounds__(256) ctx_mma() {
    extern __shared__ float csm[];
    float* sa = csm;
    float* sb = csm + CSTAGES * 16 * CPA;

    const int tid = threadIdx.x;
    const int wid = tid >> 5, lid = tid & 31;
    const int wm = wid >> 1, wn = wid & 1;      // 4m x 2n
    const int g = lid >> 2, q = lid & 3;
    const int bh = blockIdx.x, b = bh >> 4, h = bh & 15;
    const int m0 = blockIdx.y << 7;             // 0,128,256
    const int n0 = blockIdx.z << 9;             // 512-slabs

    const int ar0 = tid >> 5, ac0 = (tid & 31) << 2;         // rows 0..7
    const int ar1 = ar0 + 8;
    const int br0 = tid >> 4, bc0 = (tid & 15) << 2;

    const unsigned sab = smem_u32(sa);
    const unsigned sbb = smem_u32(sb);
    const unsigned a0off = sab + (unsigned)((ar0 * CPA + ac0) * 4);
    const unsigned a1off = sab + (unsigned)((ar1 * CPA + ac0) * 4);
    const unsigned boff  = sbb + (unsigned)((br0 * CPB + bc0) * 4);
    const unsigned stga = (unsigned)(16 * CPA * 4);
    const unsigned stgb = (unsigned)(16 * CPB * 4);

    const float* Ag0 = g_kp + ((size_t)bh * Nn + n0 + ar0) * LDP + m0 + ac0;
    const float* Ag1 = g_kp + ((size_t)bh * Nn + n0 + ar1) * LDP + m0 + ac0;
    const float* Bg  = g_v  + ((size_t)(b * Nn) + n0 + br0) * DIMM + h * Dd + bc0;

    float acc[2][4][4] = {};
    const int NT = 32;                           // 512 / 16

    #pragma unroll
    for (int p = 0; p < 3; ++p) {
        const int kb = p * 16;
        cp16(a0off + p * stga, Ag0 + (size_t)kb * LDP);
        cp16(a1off + p * stga, Ag1 + (size_t)kb * LDP);
        cp16(boff  + p * stgb, Bg  + (size_t)kb * DIMM);
        asm volatile("cp.async.commit_group;" ::: "memory");
    }

    int s = 0;
    for (int kt = 0; kt < NT; ++kt) {
        asm volatile("cp.async.wait_group 2;" ::: "memory");
        __syncthreads();

        if (kt + 3 < NT) {
            int s3 = s - 1; if (s3 < 0) s3 = CSTAGES - 1;   // (s+3)%4
            const int kb = (kt + 3) * 16;
            cp16(a0off + s3 * stga, Ag0 + (size_t)kb * LDP);
            cp16(a1off + s3 * stga, Ag1 + (size_t)kb * LDP);
            cp16(boff  + s3 * stgb, Bg  + (size_t)kb * DIMM);
        }
        asm volatile("cp.async.commit_group;" ::: "memory");

        const float* As_ = sa + s * 16 * CPA;
        const float* Bs_ = sb + s * 16 * CPB;

        #pragma unroll
        for (int ks = 0; ks < 16; ks += 8) {
            unsigned af[2][4], bf[4][2];
            #pragma unroll
            for (int mi = 0; mi < 2; ++mi) {
                const int rb = wm * 32 + mi * 16;
                af[mi][0] = __float_as_uint(As_[(ks + q) * CPA + rb + g]);
                af[mi][1] = __float_as_uint(As_[(ks + q) * CPA + rb + g + 8]);
                af[mi][2] = __float_as_uint(As_[(ks + q + 4) * CPA + rb + g]);
                af[mi][3] = __float_as_uint(As_[(ks + q + 4) * CPA + rb + g + 8]);
            }
            #pragma unroll
            for (int ni = 0; ni < 4; ++ni) {
                const int cb = wn * 32 + ni * 8;
                bf[ni][0] = __float_as_uint(Bs_[(ks + q) * CPB + cb + g]);
                bf[ni][1] = __float_as_uint(Bs_[(ks + q + 4) * CPB + cb + g]);
            }
            #pragma unroll
            for (int mi = 0; mi < 2; ++mi)
                #pragma unroll
                for (int ni = 0; ni < 4; ++ni)
                    mma_tf32(acc[mi][ni], af[mi][0], af[mi][1], af[mi][2], af[mi][3],
                             bf[ni][0], bf[ni][1]);
        }
        ++s; if (s == CSTAGES) s = 0;
    }
    asm volatile("cp.async.wait_group 0;" ::: "memory");

    #pragma unroll
    for (int mi = 0; mi < 2; ++mi) {
        const int mA = m0 + wm * 32 + mi * 16 + g;
        #pragma unroll
        for (int ni = 0; ni < 4; ++ni) {
            const int e0 = wn * 32 + ni * 8 + (q << 1);
            if (mA < Mm) {
                atomicAdd(&g_ctxT[((size_t)bh * 128 + e0) * LDP + mA], acc[mi][ni][0]);
                atomicAdd(&g_ctxT[((size_t)bh * 128 + e0 + 1) * LDP + mA], acc[mi][ni][1]);
            }
            if (mA + 8 < Mm) {
                atomicAdd(&g_ctxT[((size_t)bh * 128 + e0) * LDP + mA + 8], acc[mi][ni][2]);
                atomicAdd(&g_ctxT[((size_t)bh * 128 + e0 + 1) * LDP + mA + 8], acc[mi][ni][3]);
            }
        }
    }
}

// ---------------- exp_q: warp per row; rowmax + diag + exp; rounded store -------------
__global__ void __launch_bounds__(256) expq_kernel() {
    const int warp = threadIdx.x >> 5, lane = threadIdx.x & 31;
    const int r = blockIdx.x * 8 + warp;
    const int bh = r >> 12, n = r & 4095;
    const int b = bh >> 4, h = bh & 15;

    const float* qrow = g_q + ((size_t)(b * Nn) + n) * DIMM + h * Dd;
    float s = qrow[lane] * qrow[lane] + qrow[lane + 32] * qrow[lane + 32];
    #pragma unroll
    for (int o = 16; o > 0; o >>= 1) s += __shfl_xor_sync(0xffffffffu, s, o);
    const float diag = 0.0625f * s;

    float* row = g_qp + (size_t)r * LDP;
    float d[9];
    float mx = -CUDART_INF_F;
    #pragma unroll
    for (int i = 0; i < 9; ++i) {
        int m = lane + i * 32;
        d[i] = row[m];
        if (m < Mm) mx = fmaxf(mx, d[i]);
    }
    #pragma unroll
    for (int o = 16; o > 0; o >>= 1) mx = fmaxf(mx, __shfl_xor_sync(0xffffffffu, mx, o));
    const float sub = diag + mx;
    #pragma unroll
    for (int i = 0; i < 9; ++i) {
        int m = lane + i * 32;
        row[m] = (m < Mm) ? rna_tf32(RATIO * (fexp(d[i] - sub) + EPSV)) : 0.f;
    }
}

// ---------------- exp_k + fused k_cumsum; rounded store --------------------------------
__global__ void __launch_bounds__(256) expk_kernel() {
    __shared__ float sums[LDP];
    const int tid = threadIdx.x;
    for (int i = tid; i < LDP; i += 256) sums[i] = 0.f;
    __syncthreads();

    const int warp = tid >> 5, lane = tid & 31;
    const int r = blockIdx.x * 8 + warp;
    const int bh = r >> 12, n = r & 4095;
    const int b = bh >> 4, h = bh & 15;

    const float* krow = g_k + ((size_t)(b * Nn) + n) * DIMM + h * Dd;
    float s = krow[lane] * krow[lane] + krow[lane + 32] * krow[lane + 32];
    #pragma unroll
    for (int o = 16; o > 0; o >>= 1) s += __shfl_xor_sync(0xffffffffu, s, o);
    const float sub = 0.0625f * s + g_kmax[bh];

    float* row = g_kp + (size_t)r * LDP;
    #pragma unroll
    for (int i = 0; i < 9; ++i) {
        int m = lane + i * 32;
        float v = (m < Mm) ? rna_tf32(RATIO * (fexp(row[m] - sub) + EPSV)) : 0.f;
        row[m] = v;
        atomicAdd(&sums[m], v);
    }
    __syncthreads();
    for (int i = tid; i < LDP; i += 256)
        atomicAdd(&g_kcum[bh * LDP + i], sums[i]);
}

// ---------------- D_inv -----------------------------------------------------------------
__global__ void dinv_kernel() {
    int w = (blockIdx.x << 3) + (threadIdx.x >> 5);
    int lane = threadIdx.x & 31;
    int bh = w >> 12;
    float s = 0.f;
    size_t qbase = (size_t)w * LDP;
    int cbase = bh * LDP;
    #pragma unroll
    for (int i = 0; i < 9; ++i) {
        int m = lane + i * 32;
        s = fmaf(g_qp[qbase + m], g_kcum[cbase + m], s);
    }
    #pragma unroll
    for (int o = 16; o > 0; o >>= 1) s += __shfl_xor_sync(0xffffffffu, s, o);
    if (lane == 0) g_dinv[w] = 1.f / s;
}

// ---------------- launcher --------------------------------------------------------------
extern "C" void kernel_launch(void* const* d_in, const int* in_sizes, int n_in,
                              void* d_out, int out_size) {
    const float* x    = (const float*)d_in[0];
    const float* Wq   = (const float*)d_in[1];
    const float* Wk   = (const float*)d_in[2];
    const float* Wv   = (const float*)d_in[3];
    const float* Wo   = (const float*)d_in[4];
    const float* bo   = (const float*)d_in[5];
    const float* proj = (const float*)d_in[6];
    float* out = (float*)d_out;

    static int attr_done = 0;
    if (!attr_done) {
        cudaFuncSetAttribute(qkv_kernel,   cudaFuncAttributeMaxDynamicSharedMemorySize, CORE_SMEM);
        cudaFuncSetAttribute(final_kernel, cudaFuncAttributeMaxDynamicSharedMemorySize, CORE_SMEM);
        cudaFuncSetAttribute(dash_kernel,  cudaFuncAttributeMaxDynamicSharedMemorySize, CORE_SMEM);
        cudaFuncSetAttribute(out_mma,      cudaFuncAttributeMaxDynamicSharedMemorySize, CORE_SMEM);
        cudaFuncSetAttribute(ctx_mma,      cudaFuncAttributeMaxDynamicSharedMemorySize, CTX_SMEM);
        attr_done = 1;
    }

    prep_small<<<((unsigned)((size_t)BHh * Dd * LDP + 255) / 256), 256>>>(proj);
    round_x_kernel<<<ROWS * DIMM / 4 / 256, 256>>>(x);
    round_w_kernel<<<dim3(DIMM * DIMM / 4 / 256, 4), 256>>>(Wq, Wk, Wv, Wo);

    qkv_kernel<<<dim3(DIMM / 128, ROWS / 128, 3), 256, CORE_SMEM>>>();

    dash_kernel<<<dim3(3, BHh * 32, 2), 256, CORE_SMEM>>>();

    expq_kernel<<<BHh * Nn / 8, 256>>>();
    expk_kernel<<<BHh * Nn / 8, 256>>>();

    ctx_mma<<<dim3(BHh, 3, 8), 256, CTX_SMEM>>>();
    round_ctxT<<<(BHh * Dd * LDP / 4 + 255) / 256, 256>>>();
    dinv_kernel<<<BHh * Nn / 8, 256>>>();

    out_mma<<<dim3(1, BHh * 32), 256, CORE_SMEM>>>();

    final_kernel<<<dim3(DIMM / 128, ROWS / 128), 256, CORE_SMEM>>>(bo, out);
}

// round 9
// speedup vs baseline: 1.1793x; 1.1793x over previous
#include <cuda_runtime.h>
#include <math.h>
#include <math_constants.h>

// Problem constants
#define Bz   2
#define Nn   4096
#define DIMM 1024
#define Hh   16
#define Dd   64
#define Mm   266
#define BHh  (Bz*Hh)        // 32
#define ROWS (Bz*Nn)        // 8192
#define LDP  288            // padded feature row length

#define NORMALIZER 0.35355339059327373f   // 64^-0.25
#define RATIO      0.061313933948496576f  // 266^-0.5
#define EPSV       1e-4f
#define LOG2E      1.4426950408889634f

#define PITCH   20
#define STAGES  3
#define STGW    (128*PITCH)
#define BOFFW   (STAGES*STGW)
#define CORE_SMEM (STAGES*STGW*4*2)                // 61440 bytes

// ---------------- scratch -------------------------------------------------------
__device__ float g_q[ROWS*DIMM];
__device__ float g_k[ROWS*DIMM];
__device__ float g_v[ROWS*DIMM];
__device__ float g_attn[ROWS*DIMM];
__device__ float g_xr[ROWS*DIMM];                  // tf32-rounded x
__device__ float g_w4[4*DIMM*DIMM];                // tf32-rounded Wq,Wk,Wv,Wo
__device__ float g_projr[384*Dd];                  // rounded*NORMALIZER, padded
__device__ float g_qp[(size_t)BHh*Nn*LDP + 128];
__device__ float g_kp[(size_t)BHh*Nn*LDP + 128];   // +128 pad: ctx m-tile 2 over-reads
__device__ float g_kmax[BHh];
__device__ float g_kcum[BHh*LDP];
__device__ float g_ctxT[(size_t)BHh*128*LDP];      // ctx transposed [e][m], rows 64..127 stay 0
__device__ float g_dinv[BHh*Nn];

// ---------------- helpers -------------------------------------------------------
__device__ __forceinline__ unsigned smem_u32(const void* p) {
    unsigned a;
    asm("{ .reg .u64 t; cvta.to.shared.u64 t, %1; cvt.u32.u64 %0, t; }" : "=r"(a) : "l"(p));
    return a;
}
__device__ __forceinline__ float rna_tf32(float v) {
    unsigned u;
    asm("cvt.rna.tf32.f32 %0, %1;" : "=r"(u) : "f"(v));
    return __uint_as_float(u);
}
__device__ __forceinline__ float fexp(float x) {
    float y;
    asm("ex2.approx.f32 %0, %1;" : "=f"(y) : "f"(x * LOG2E));
    return y;
}
__device__ __forceinline__ void cp16(unsigned dst, const float* src) {
    asm volatile("cp.async.ca.shared.global [%0], [%1], 16;" :: "r"(dst), "l"(src));
}

__device__ __forceinline__ void mma_tf32(float c[4],
                                         unsigned a0, unsigned a1, unsigned a2, unsigned a3,
                                         unsigned b0, unsigned b1) {
    asm volatile(
        "mma.sync.aligned.m16n8k8.row.col.f32.tf32.tf32.f32 "
        "{%0,%1,%2,%3}, {%4,%5,%6,%7}, {%8,%9}, {%0,%1,%2,%3};"
        : "+f"(c[0]), "+f"(c[1]), "+f"(c[2]), "+f"(c[3])
        : "r"(a0), "r"(a1), "r"(a2), "r"(a3), "r"(b0), "r"(b1));
}

__device__ __forceinline__ void atomicMaxFloat(float* addr, float val) {
    int* a = (int*)addr;
    int old = *a;
    while (__int_as_float(old) < val) {
        int assumed = old;
        old = atomicCAS(a, assumed, __float_as_int(val));
        if (old == assumed) break;
    }
}

// ---------------- prep: init + proj rounding --------------------------------------
__global__ void prep_small(const float* __restrict__ proj) {
    size_t t = (size_t)blockIdx.x * blockDim.x + threadIdx.x;
    if (t < BHh) g_kmax[t] = -CUDART_INF_F;
    if (t < BHh * LDP) g_kcum[t] = 0.f;
    if (t < 384 * Dd) {
        int m = (int)(t >> 6);
        g_projr[t] = (m < Mm) ? rna_tf32(proj[t] * NORMALIZER) : 0.f;
    }
    if (t < (size_t)BHh * Dd * LDP) {
        size_t bh = t / (Dd * LDP);
        size_t rem = t - bh * (Dd * LDP);
        g_ctxT[bh * 128 * LDP + rem] = 0.f;
    }
}

__global__ void round_x_kernel(const float* __restrict__ in) {
    int i = blockIdx.x * blockDim.x + threadIdx.x;
    float4 v = ((const float4*)in)[i];
    v.x = rna_tf32(v.x); v.y = rna_tf32(v.y); v.z = rna_tf32(v.z); v.w = rna_tf32(v.w);
    ((float4*)g_xr)[i] = v;
}
__global__ void round_w_kernel(const float* __restrict__ w0, const float* __restrict__ w1,
                               const float* __restrict__ w2, const float* __restrict__ w3) {
    int z = blockIdx.y;
    const float* w = (z == 0) ? w0 : (z == 1) ? w1 : (z == 2) ? w2 : w3;
    int i = blockIdx.x * blockDim.x + threadIdx.x;
    float4 v = ((const float4*)w)[i];
    v.x = rna_tf32(v.x); v.y = rna_tf32(v.y); v.z = rna_tf32(v.z); v.w = rna_tf32(v.w);
    ((float4*)(g_w4 + (size_t)z * DIMM * DIMM))[i] = v;
}
// round ctxT rows 0..63 per bh, in place
__global__ void round_ctxT() {
    size_t i = (size_t)blockIdx.x * 256 + threadIdx.x;      // float4 index
    const size_t per_bh = (size_t)Dd * LDP / 4;             // 4608
    if (i >= (size_t)BHh * per_bh) return;
    size_t bh = i / per_bh;
    size_t rem = i - bh * per_bh;
    float4* p = (float4*)(g_ctxT + bh * 128 * LDP) + rem;
    float4 v = *p;
    v.x = rna_tf32(v.x); v.y = rna_tf32(v.y); v.z = rna_tf32(v.z); v.w = rna_tf32(v.w);
    *p = v;
}

// ---------------- mma core: cp.async 3-stage (round-7 structure) --------------------
// C[r][c] = sum_k A[r][k] * W[c][k] (+bias) (*rowscale[r]).  128x128, 8 warps 2m x 4n.
template<bool BIAS, bool RNAOUT>
__device__ __forceinline__ void mma_core(const float* __restrict__ A, int lda,
                                         const float* __restrict__ W, int ldb,
                                         float* __restrict__ C, int ldc,
                                         int K, int nvalid,
                                         const float* __restrict__ bias,
                                         const float* __restrict__ rowscale,
                                         float* __restrict__ maxout, int maxcols, int bhidx) {
    extern __shared__ float sm[];
    __shared__ float mred[8];
    float* Asp = sm;
    float* Bsp = sm + BOFFW;

    const int tid = threadIdx.x;
    const int wid = tid >> 5, lid = tid & 31;
    const int wm = wid >> 2;
    const int wn = wid & 3;
    const int g = lid >> 2, q = lid & 3;

    const int lr0 = tid >> 2;           // 0..63
    const int lr1 = lr0 + 64;
    const int lc0 = (tid & 3) << 2;

    const unsigned sbase = smem_u32(sm);
    const unsigned a0off = sbase + (unsigned)((lr0 * PITCH + lc0) * 4);
    const unsigned a1off = sbase + (unsigned)((lr1 * PITCH + lc0) * 4);
    const unsigned b0off = a0off + (unsigned)(BOFFW * 4);
    const unsigned b1off = a1off + (unsigned)(BOFFW * 4);
    const unsigned stgsz = (unsigned)(STGW * 4);

    const float* Ag0 = A + (size_t)lr0 * lda + lc0;
    const float* Ag1 = A + (size_t)lr1 * lda + lc0;
    const float* Wg0 = W + (size_t)lr0 * ldb + lc0;
    const float* Wg1 = W + (size_t)lr1 * ldb + lc0;

    float acc[4][4][4] = {};
    const int NT = K >> 4;

    {
        cp16(a0off, Ag0); cp16(a1off, Ag1);
        cp16(b0off, Wg0); cp16(b1off, Wg1);
        asm volatile("cp.async.commit_group;" ::: "memory");
        if (NT > 1) {
            cp16(a0off + stgsz, Ag0 + 16); cp16(a1off + stgsz, Ag1 + 16);
            cp16(b0off + stgsz, Wg0 + 16); cp16(b1off + stgsz, Wg1 + 16);
        }
        asm volatile("cp.async.commit_group;" ::: "memory");
    }

    int s = 0;
    for (int kt = 0; kt < NT; ++kt) {
        if (kt + 2 < NT) {
            int s2 = s + 2; if (s2 >= STAGES) s2 -= STAGES;
            const unsigned d = (unsigned)(s2 * stgsz);
            const int kb = (kt + 2) * 16;
            cp16(a0off + d, Ag0 + kb); cp16(a1off + d, Ag1 + kb);
            cp16(b0off + d, Wg0 + kb); cp16(b1off + d, Wg1 + kb);
        }
        asm volatile("cp.async.commit_group;" ::: "memory");
        asm volatile("cp.async.wait_group 2;" ::: "memory");
        __syncthreads();

        const float* As_ = Asp + s * STGW;
        const float* Bs_ = Bsp + s * STGW;

        #pragma unroll
        for (int ks = 0; ks < 16; ks += 8) {
            unsigned af[4][4], bf[4][2];
            #pragma unroll
            for (int mi = 0; mi < 4; ++mi) {
                const int rb = wm * 64 + mi * 16;
                af[mi][0] = __float_as_uint(As_[(rb + g) * PITCH + ks + q]);
                af[mi][1] = __float_as_uint(As_[(rb + g + 8) * PITCH + ks + q]);
                af[mi][2] = __float_as_uint(As_[(rb + g) * PITCH + ks + q + 4]);
                af[mi][3] = __float_as_uint(As_[(rb + g + 8) * PITCH + ks + q + 4]);
            }
            #pragma unroll
            for (int ni = 0; ni < 4; ++ni) {
                const int cb = wn * 32 + ni * 8;
                bf[ni][0] = __float_as_uint(Bs_[(cb + g) * PITCH + ks + q]);
                bf[ni][1] = __float_as_uint(Bs_[(cb + g) * PITCH + ks + q + 4]);
            }
            #pragma unroll
            for (int mi = 0; mi < 4; ++mi)
                #pragma unroll
                for (int ni = 0; ni < 4; ++ni)
                    mma_tf32(acc[mi][ni], af[mi][0], af[mi][1], af[mi][2], af[mi][3],
                             bf[ni][0], bf[ni][1]);
        }
        __syncthreads();
        ++s; if (s == STAGES) s = 0;
    }

    #pragma unroll
    for (int mi = 0; mi < 4; ++mi) {
        const int r_ = wm * 64 + mi * 16 + g;
        float sc0 = 1.f, sc1 = 1.f;
        if (rowscale) { sc0 = rowscale[r_]; sc1 = rowscale[r_ + 8]; }
        #pragma unroll
        for (int ni = 0; ni < 4; ++ni) {
            const int crel = wn * 32 + ni * 8 + (q << 1);
            if (crel < nvalid) {
                float2 v0 = make_float2(acc[mi][ni][0], acc[mi][ni][1]);
                float2 v1 = make_float2(acc[mi][ni][2], acc[mi][ni][3]);
                if (BIAS) {
                    v0.x += bias[crel]; v0.y += bias[crel + 1];
                    v1.x += bias[crel]; v1.y += bias[crel + 1];
                }
                if (rowscale) {
                    v0.x *= sc0; v0.y *= sc0;
                    v1.x *= sc1; v1.y *= sc1;
                }
                if (RNAOUT) {
                    v0.x = rna_tf32(v0.x); v0.y = rna_tf32(v0.y);
                    v1.x = rna_tf32(v1.x); v1.y = rna_tf32(v1.y);
                }
                *(float2*)&C[(size_t)r_ * ldc + crel]       = v0;
                *(float2*)&C[(size_t)(r_ + 8) * ldc + crel] = v1;
            }
        }
    }

    if (maxout) {
        float mx = -CUDART_INF_F;
        #pragma unroll
        for (int mi = 0; mi < 4; ++mi)
            #pragma unroll
            for (int ni = 0; ni < 4; ++ni)
                #pragma unroll
                for (int e = 0; e < 4; ++e) {
                    int crel = wn * 32 + ni * 8 + (q << 1) + (e & 1);
                    if (crel < maxcols) mx = fmaxf(mx, acc[mi][ni][e]);
                }
        #pragma unroll
        for (int o = 16; o > 0; o >>= 1)
            mx = fmaxf(mx, __shfl_xor_sync(0xffffffffu, mx, o));
        if (lid == 0) mred[wid] = mx;
        __syncthreads();
        if (tid == 0) {
            float bm = mred[0];
            #pragma unroll
            for (int w = 1; w < 8; ++w) bm = fmaxf(bm, mred[w]);
            atomicMaxFloat(&maxout[bhidx], bm);
        }
    }
}

// ---------------- wrappers --------------------------------------------------------
__global__ void __launch_bounds__(256, 2) qkv_kernel() {
    const int z = blockIdx.z;
    const float* W = g_w4 + (size_t)z * DIMM * DIMM;
    float* C = (z == 0) ? g_q : (z == 1) ? g_k : g_v;
    const int row0 = blockIdx.y * 128, col0 = blockIdx.x * 128;
    mma_core<false, true>(g_xr + (size_t)row0 * DIMM, DIMM,
                    W + (size_t)col0 * DIMM, DIMM,
                    C + (size_t)row0 * DIMM + col0, DIMM, DIMM, 128,
                    nullptr, nullptr, nullptr, 0, 0);
}

__global__ void __launch_bounds__(256, 2) final_kernel(const float* __restrict__ bo,
                                                       float* __restrict__ out) {
    const int row0 = blockIdx.y * 128, col0 = blockIdx.x * 128;
    mma_core<true, false>(g_attn + (size_t)row0 * DIMM, DIMM,
                   g_w4 + 3 * (size_t)DIMM * DIMM + (size_t)col0 * DIMM, DIMM,
                   out + (size_t)row0 * DIMM + col0, DIMM, DIMM, 128,
                   bo + col0, nullptr, nullptr, 0, 0);
}

__global__ void __launch_bounds__(256, 2) dash_kernel() {
    const int z = blockIdx.z;                 // 0 = q, 1 = k
    const float* src = z ? g_k : g_q;
    float* dst = z ? g_kp : g_qp;
    const int bh = blockIdx.y >> 5, nc = blockIdx.y & 31;
    const int b = bh >> 4, h = bh & 15;
    const int col0 = blockIdx.x * 128;
    const int row0 = nc * 128;
    mma_core<false, false>(src + ((size_t)(b * Nn) + row0) * DIMM + h * Dd, DIMM,
                    g_projr + (size_t)col0 * Dd, Dd,
                    dst + ((size_t)bh * Nn + row0) * LDP + col0, LDP,
                    Dd, LDP - col0, nullptr, nullptr,
                    z ? g_kmax : nullptr, Mm - col0, bh);
}

// out[b,n,h,e] = Dinv[n] * sum_m qp[n,m] * ctxT[e,m]   (tensorized, K=288)
__global__ void __launch_bounds__(256, 2) out_mma() {
    const int t = blockIdx.y;
    const int bh = t >> 5, nt = t & 31;
    const int b = bh >> 4, h = bh & 15;
    const int row0 = nt * 128;
    mma_core<false, true>(g_qp + ((size_t)bh * Nn + row0) * LDP, LDP,
                    g_ctxT + (size_t)bh * 128 * LDP, LDP,
                    g_attn + ((size_t)(b * Nn) + row0) * DIMM + h * Dd, DIMM,
                    LDP, Dd, nullptr,
                    g_dinv + (size_t)bh * Nn + row0, nullptr, 0, 0);
}

// ---------------- ctx via tensor cores (round-7 structure) ----------------------------
#define CPA 132
#define CPB 68
__global__ void __launch_bounds__(256) ctx_mma() {
    __shared__ float sa[3 * 16 * CPA];
    __shared__ float sb[3 * 16 * CPB];

    const int tid = threadIdx.x;
    const int wid = tid >> 5, lid = tid & 31;
    const int wm = wid >> 1, wn = wid & 1;      // 4m x 2n
    const int g = lid >> 2, q = lid & 3;
    const int bh = blockIdx.x, b = bh >> 4, h = bh & 15;
    const int m0 = blockIdx.y << 7;             // 0,128,256
    const int n0 = blockIdx.z << 9;             // 512-slabs

    const int ar0 = tid >> 5, ac0 = (tid & 31) << 2;         // rows 0..7
    const int ar1 = ar0 + 8;
    const int br0 = tid >> 4, bc0 = (tid & 15) << 2;

    const unsigned sab = smem_u32(sa);
    const unsigned sbb = smem_u32(sb);
    const unsigned a0off = sab + (unsigned)((ar0 * CPA + ac0) * 4);
    const unsigned a1off = sab + (unsigned)((ar1 * CPA + ac0) * 4);
    const unsigned boff  = sbb + (unsigned)((br0 * CPB + bc0) * 4);
    const unsigned stga = (unsigned)(16 * CPA * 4);
    const unsigned stgb = (unsigned)(16 * CPB * 4);

    const float* Ag0 = g_kp + ((size_t)bh * Nn + n0 + ar0) * LDP + m0 + ac0;
    const float* Ag1 = g_kp + ((size_t)bh * Nn + n0 + ar1) * LDP + m0 + ac0;
    const float* Bg  = g_v  + ((size_t)(b * Nn) + n0 + br0) * DIMM + h * Dd + bc0;

    float acc[2][4][4] = {};
    const int NT = 32;                           // 512 / 16

    {
        cp16(a0off, Ag0); cp16(a1off, Ag1); cp16(boff, Bg);
        asm volatile("cp.async.commit_group;" ::: "memory");
        cp16(a0off + stga, Ag0 + 16 * LDP); cp16(a1off + stga, Ag1 + 16 * LDP);
        cp16(boff + stgb, Bg + 16 * DIMM);
        asm volatile("cp.async.commit_group;" ::: "memory");
    }

    int s = 0;
    for (int kt = 0; kt < NT; ++kt) {
        if (kt + 2 < NT) {
            int s2 = s + 2; if (s2 >= 3) s2 -= 3;
            const int kb = (kt + 2) * 16;
            cp16(a0off + s2 * stga, Ag0 + (size_t)kb * LDP);
            cp16(a1off + s2 * stga, Ag1 + (size_t)kb * LDP);
            cp16(boff  + s2 * stgb, Bg  + (size_t)kb * DIMM);
        }
        asm volatile("cp.async.commit_group;" ::: "memory");
        asm volatile("cp.async.wait_group 2;" ::: "memory");
        __syncthreads();

        const float* As_ = sa + s * 16 * CPA;
        const float* Bs_ = sb + s * 16 * CPB;

        #pragma unroll
        for (int ks = 0; ks < 16; ks += 8) {
            unsigned af[2][4], bf[4][2];
            #pragma unroll
            for (int mi = 0; mi < 2; ++mi) {
                const int rb = wm * 32 + mi * 16;
                af[mi][0] = __float_as_uint(As_[(ks + q) * CPA + rb + g]);
                af[mi][1] = __float_as_uint(As_[(ks + q) * CPA + rb + g + 8]);
                af[mi][2] = __float_as_uint(As_[(ks + q + 4) * CPA + rb + g]);
                af[mi][3] = __float_as_uint(As_[(ks + q + 4) * CPA + rb + g + 8]);
            }
            #pragma unroll
            for (int ni = 0; ni < 4; ++ni) {
                const int cb = wn * 32 + ni * 8;
                bf[ni][0] = __float_as_uint(Bs_[(ks + q) * CPB + cb + g]);
                bf[ni][1] = __float_as_uint(Bs_[(ks + q + 4) * CPB + cb + g]);
            }
            #pragma unroll
            for (int mi = 0; mi < 2; ++mi)
                #pragma unroll
                for (int ni = 0; ni < 4; ++ni)
                    mma_tf32(acc[mi][ni], af[mi][0], af[mi][1], af[mi][2], af[mi][3],
                             bf[ni][0], bf[ni][1]);
        }
        __syncthreads();
        ++s; if (s == 3) s = 0;
    }

    #pragma unroll
    for (int mi = 0; mi < 2; ++mi) {
        const int mA = m0 + wm * 32 + mi * 16 + g;
        #pragma unroll
        for (int ni = 0; ni < 4; ++ni) {
            const int e0 = wn * 32 + ni * 8 + (q << 1);
            if (mA < Mm) {
                atomicAdd(&g_ctxT[((size_t)bh * 128 + e0) * LDP + mA], acc[mi][ni][0]);
                atomicAdd(&g_ctxT[((size_t)bh * 128 + e0 + 1) * LDP + mA], acc[mi][ni][1]);
            }
            if (mA + 8 < Mm) {
                atomicAdd(&g_ctxT[((size_t)bh * 128 + e0) * LDP + mA + 8], acc[mi][ni][2]);
                atomicAdd(&g_ctxT[((size_t)bh * 128 + e0 + 1) * LDP + mA + 8], acc[mi][ni][3]);
            }
        }
    }
}

// ---------------- exp_q: warp per row; rowmax + diag + exp; rounded store -------------
__global__ void __launch_bounds__(256) expq_kernel() {
    const int warp = threadIdx.x >> 5, lane = threadIdx.x & 31;
    const int r = blockIdx.x * 8 + warp;
    const int bh = r >> 12, n = r & 4095;
    const int b = bh >> 4, h = bh & 15;

    const float* qrow = g_q + ((size_t)(b * Nn) + n) * DIMM + h * Dd;
    float s = qrow[lane] * qrow[lane] + qrow[lane + 32] * qrow[lane + 32];
    #pragma unroll
    for (int o = 16; o > 0; o >>= 1) s += __shfl_xor_sync(0xffffffffu, s, o);
    const float diag = 0.0625f * s;

    float* row = g_qp + (size_t)r * LDP;
    float d[9];
    float mx = -CUDART_INF_F;
    #pragma unroll
    for (int i = 0; i < 9; ++i) {
        int m = lane + i * 32;
        d[i] = row[m];
        if (m < Mm) mx = fmaxf(mx, d[i]);
    }
    #pragma unroll
    for (int o = 16; o > 0; o >>= 1) mx = fmaxf(mx, __shfl_xor_sync(0xffffffffu, mx, o));
    const float sub = diag + mx;
    #pragma unroll
    for (int i = 0; i < 9; ++i) {
        int m = lane + i * 32;
        row[m] = (m < Mm) ? rna_tf32(RATIO * (fexp(d[i] - sub) + EPSV)) : 0.f;
    }
}

// ---------------- exp_k + fused k_cumsum; rounded store --------------------------------
__global__ void __launch_bounds__(256) expk_kernel() {
    __shared__ float sums[LDP];
    const int tid = threadIdx.x;
    for (int i = tid; i < LDP; i += 256) sums[i] = 0.f;
    __syncthreads();

    const int warp = tid >> 5, lane = tid & 31;
    const int r = blockIdx.x * 8 + warp;
    const int bh = r >> 12, n = r & 4095;
    const int b = bh >> 4, h = bh & 15;

    const float* krow = g_k + ((size_t)(b * Nn) + n) * DIMM + h * Dd;
    float s = krow[lane] * krow[lane] + krow[lane + 32] * krow[lane + 32];
    #pragma unroll
    for (int o = 16; o > 0; o >>= 1) s += __shfl_xor_sync(0xffffffffu, s, o);
    const float sub = 0.0625f * s + g_kmax[bh];

    float* row = g_kp + (size_t)r * LDP;
    #pragma unroll
    for (int i = 0; i < 9; ++i) {
        int m = lane + i * 32;
        float v = (m < Mm) ? rna_tf32(RATIO * (fexp(row[m] - sub) + EPSV)) : 0.f;
        row[m] = v;
        atomicAdd(&sums[m], v);
    }
    __syncthreads();
    for (int i = tid; i < LDP; i += 256)
        atomicAdd(&g_kcum[bh * LDP + i], sums[i]);
}

// ---------------- D_inv -----------------------------------------------------------------
__global__ void dinv_kernel() {
    int w = (blockIdx.x << 3) + (threadIdx.x >> 5);
    int lane = threadIdx.x & 31;
    int bh = w >> 12;
    float s = 0.f;
    size_t qbase = (size_t)w * LDP;
    int cbase = bh * LDP;
    #pragma unroll
    for (int i = 0; i < 9; ++i) {
        int m = lane + i * 32;
        s = fmaf(g_qp[qbase + m], g_kcum[cbase + m], s);
    }
    #pragma unroll
    for (int o = 16; o > 0; o >>= 1) s += __shfl_xor_sync(0xffffffffu, s, o);
    if (lane == 0) g_dinv[w] = 1.f / s;
}

// ---------------- launcher --------------------------------------------------------------
extern "C" void kernel_launch(void* const* d_in, const int* in_sizes, int n_in,
                              void* d_out, int out_size) {
    const float* x    = (const float*)d_in[0];
    const float* Wq   = (const float*)d_in[1];
    const float* Wk   = (const float*)d_in[2];
    const float* Wv   = (const float*)d_in[3];
    const float* Wo   = (const float*)d_in[4];
    const float* bo   = (const float*)d_in[5];
    const float* proj = (const float*)d_in[6];
    float* out = (float*)d_out;

    static int attr_done = 0;
    if (!attr_done) {
        cudaFuncSetAttribute(qkv_kernel,   cudaFuncAttributeMaxDynamicSharedMemorySize, CORE_SMEM);
        cudaFuncSetAttribute(final_kernel, cudaFuncAttributeMaxDynamicSharedMemorySize, CORE_SMEM);
        cudaFuncSetAttribute(dash_kernel,  cudaFuncAttributeMaxDynamicSharedMemorySize, CORE_SMEM);
        cudaFuncSetAttribute(out_mma,      cudaFuncAttributeMaxDynamicSharedMemorySize, CORE_SMEM);
        attr_done = 1;
    }

    prep_small<<<((unsigned)((size_t)BHh * Dd * LDP + 255) / 256), 256>>>(proj);
    round_x_kernel<<<ROWS * DIMM / 4 / 256, 256>>>(x);
    round_w_kernel<<<dim3(DIMM * DIMM / 4 / 256, 4), 256>>>(Wq, Wk, Wv, Wo);

    qkv_kernel<<<dim3(DIMM / 128, ROWS / 128, 3), 256, CORE_SMEM>>>();

    dash_kernel<<<dim3(3, BHh * 32, 2), 256, CORE_SMEM>>>();

    expq_kernel<<<BHh * Nn / 8, 256>>>();
    expk_kernel<<<BHh * Nn / 8, 256>>>();

    ctx_mma<<<dim3(BHh, 3, 8), 256>>>();
    round_ctxT<<<(BHh * Dd * LDP / 4 + 255) / 256, 256>>>();
    dinv_kernel<<<BHh * Nn / 8, 256>>>();

    out_mma<<<dim3(1, BHh * 32), 256, CORE_SMEM>>>();

    final_kernel<<<dim3(DIMM / 128, ROWS / 128), 256, CORE_SMEM>>>(bo, out);
}

// round 10
// speedup vs baseline: 1.2434x; 1.0543x over previous
#include <cuda_runtime.h>
#include <math.h>
#include <math_constants.h>

// Problem constants
#define Bz   2
#define Nn   4096
#define DIMM 1024
#define Hh   16
#define Dd   64
#define Mm   266
#define BHh  (Bz*Hh)        // 32
#define ROWS (Bz*Nn)        // 8192
#define LDP  288            // padded feature row length

#define NORMALIZER 0.35355339059327373f   // 64^-0.25
#define RATIO      0.061313933948496576f  // 266^-0.5
#define EPSV       1e-4f
#define LOG2E      1.4426950408889634f

#define PITCH   20
#define STAGES  4
#define STGW    (128*PITCH)
#define BOFFW   (STAGES*STGW)
#define CORE_SMEM (STAGES*STGW*4*2)                // 81920 bytes

// ---------------- scratch -------------------------------------------------------
__device__ float g_q[ROWS*DIMM];
__device__ float g_k[ROWS*DIMM];
__device__ float g_v[ROWS*DIMM];
__device__ float g_attn[ROWS*DIMM];
__device__ float g_xr[ROWS*DIMM];                  // tf32-rounded x
__device__ float g_w4[4*DIMM*DIMM];                // tf32-rounded Wq,Wk,Wv,Wo
__device__ float g_projr[384*Dd];                  // rounded*NORMALIZER, padded
__device__ float g_qp[(size_t)BHh*Nn*LDP + 128];
__device__ float g_kp[(size_t)BHh*Nn*LDP + 128];   // +128 pad: ctx m-tile 2 over-reads
__device__ float g_kmax[BHh];
__device__ float g_kcum[BHh*LDP];
__device__ float g_ctxT[(size_t)BHh*128*LDP];      // [e][m]; rows 0..63 ctx, row 64 kcum, 65..127 zero
// (device globals zero-init at load; rows 65..127 never written)

// ---------------- helpers -------------------------------------------------------
__device__ __forceinline__ unsigned smem_u32(const void* p) {
    unsigned a;
    asm("{ .reg .u64 t; cvta.to.shared.u64 t, %1; cvt.u32.u64 %0, t; }" : "=r"(a) : "l"(p));
    return a;
}
__device__ __forceinline__ float rna_tf32(float v) {
    unsigned u;
    asm("cvt.rna.tf32.f32 %0, %1;" : "=r"(u) : "f"(v));
    return __uint_as_float(u);
}
__device__ __forceinline__ float fexp(float x) {
    float y;
    asm("ex2.approx.f32 %0, %1;" : "=f"(y) : "f"(x * LOG2E));
    return y;
}
__device__ __forceinline__ void cp16(unsigned dst, const float* src) {
    asm volatile("cp.async.ca.shared.global [%0], [%1], 16;" :: "r"(dst), "l"(src));
}

__device__ __forceinline__ void mma_tf32(float c[4],
                                         unsigned a0, unsigned a1, unsigned a2, unsigned a3,
                                         unsigned b0, unsigned b1) {
    asm volatile(
        "mma.sync.aligned.m16n8k8.row.col.f32.tf32.tf32.f32 "
        "{%0,%1,%2,%3}, {%4,%5,%6,%7}, {%8,%9}, {%0,%1,%2,%3};"
        : "+f"(c[0]), "+f"(c[1]), "+f"(c[2]), "+f"(c[3])
        : "r"(a0), "r"(a1), "r"(a2), "r"(a3), "r"(b0), "r"(b1));
}

__device__ __forceinline__ void atomicMaxFloat(float* addr, float val) {
    int* a = (int*)addr;
    int old = *a;
    while (__int_as_float(old) < val) {
        int assumed = old;
        old = atomicCAS(a, assumed, __float_as_int(val));
        if (old == assumed) break;
    }
}

// ---------------- prep: init + proj rounding --------------------------------------
__global__ void prep_small(const float* __restrict__ proj) {
    size_t t = (size_t)blockIdx.x * blockDim.x + threadIdx.x;
    if (t < BHh) g_kmax[t] = -CUDART_INF_F;
    if (t < BHh * LDP) g_kcum[t] = 0.f;
    if (t < 384 * Dd) {
        int m = (int)(t >> 6);
        g_projr[t] = (m < Mm) ? rna_tf32(proj[t] * NORMALIZER) : 0.f;
    }
    if (t < (size_t)BHh * Dd * LDP) {       // zero ctx rows 0..63 per bh (atomics accumulate)
        size_t bh = t / (Dd * LDP);
        size_t rem = t - bh * (Dd * LDP);
        g_ctxT[bh * 128 * LDP + rem] = 0.f;
    }
}

__global__ void round_x_kernel(const float* __restrict__ in) {
    int i = blockIdx.x * blockDim.x + threadIdx.x;
    float4 v = ((const float4*)in)[i];
    v.x = rna_tf32(v.x); v.y = rna_tf32(v.y); v.z = rna_tf32(v.z); v.w = rna_tf32(v.w);
    ((float4*)g_xr)[i] = v;
}
__global__ void round_w_kernel(const float* __restrict__ w0, const float* __restrict__ w1,
                               const float* __restrict__ w2, const float* __restrict__ w3) {
    int z = blockIdx.y;
    const float* w = (z == 0) ? w0 : (z == 1) ? w1 : (z == 2) ? w2 : w3;
    int i = blockIdx.x * blockDim.x + threadIdx.x;
    float4 v = ((const float4*)w)[i];
    v.x = rna_tf32(v.x); v.y = rna_tf32(v.y); v.z = rna_tf32(v.z); v.w = rna_tf32(v.w);
    ((float4*)(g_w4 + (size_t)z * DIMM * DIMM))[i] = v;
}
// round ctxT rows 0..63 per bh in place
__global__ void round_ctxT() {
    size_t i = (size_t)blockIdx.x * 256 + threadIdx.x;      // float4 index
    const size_t per_bh = (size_t)Dd * LDP / 4;             // 4608
    if (i >= (size_t)BHh * per_bh) return;
    size_t bh = i / per_bh;
    size_t rem = i - bh * per_bh;
    float4* p = (float4*)(g_ctxT + bh * 128 * LDP) + rem;
    float4 v = *p;
    v.x = rna_tf32(v.x); v.y = rna_tf32(v.y); v.z = rna_tf32(v.z); v.w = rna_tf32(v.w);
    *p = v;
}
// write tf32-rounded kcum into ctxT row 64
__global__ void copy_kcum() {
    int i = blockIdx.x * 256 + threadIdx.x;
    if (i >= BHh * LDP) return;
    int bh = i / LDP, m = i - bh * LDP;
    g_ctxT[((size_t)bh * 128 + 64) * LDP + m] = rna_tf32(g_kcum[i]);
}

// ---------------- mma core: 4-stage cp.async, issue-before-wait, 1 sync/ktile --------
// C[r][c] = sum_k A[r][k] * W[c][k] (+bias).  DINV: col 64 of acc = D, scale rows by 1/D.
// 128x128 CTA tile, 8 warps 2m x 4n.
template<bool BIAS, bool RNAOUT, bool DINV>
__device__ __forceinline__ void mma_core(const float* __restrict__ A, int lda,
                                         const float* __restrict__ W, int ldb,
                                         float* __restrict__ C, int ldc,
                                         int K, int nvalid,
                                         const float* __restrict__ bias,
                                         float* __restrict__ maxout, int maxcols, int bhidx) {
    extern __shared__ float sm[];
    __shared__ float mred[8];
    __shared__ float Ds[128];
    float* Asp = sm;
    float* Bsp = sm + BOFFW;

    const int tid = threadIdx.x;
    const int wid = tid >> 5, lid = tid & 31;
    const int wm = wid >> 2;
    const int wn = wid & 3;
    const int g = lid >> 2, q = lid & 3;

    const int lr0 = tid >> 2;           // 0..63
    const int lr1 = lr0 + 64;
    const int lc0 = (tid & 3) << 2;

    const unsigned sbase = smem_u32(sm);
    const unsigned a0off = sbase + (unsigned)((lr0 * PITCH + lc0) * 4);
    const unsigned a1off = sbase + (unsigned)((lr1 * PITCH + lc0) * 4);
    const unsigned b0off = a0off + (unsigned)(BOFFW * 4);
    const unsigned b1off = a1off + (unsigned)(BOFFW * 4);
    const unsigned stgsz = (unsigned)(STGW * 4);

    const float* Ag0 = A + (size_t)lr0 * lda + lc0;
    const float* Ag1 = A + (size_t)lr1 * lda + lc0;
    const float* Wg0 = W + (size_t)lr0 * ldb + lc0;
    const float* Wg1 = W + (size_t)lr1 * ldb + lc0;

    float acc[4][4][4] = {};
    const int NT = K >> 4;

    {
        cp16(a0off, Ag0); cp16(a1off, Ag1);
        cp16(b0off, Wg0); cp16(b1off, Wg1);
        asm volatile("cp.async.commit_group;" ::: "memory");
        if (NT > 1) {
            cp16(a0off + stgsz, Ag0 + 16); cp16(a1off + stgsz, Ag1 + 16);
            cp16(b0off + stgsz, Wg0 + 16); cp16(b1off + stgsz, Wg1 + 16);
        }
        asm volatile("cp.async.commit_group;" ::: "memory");
    }

    int s = 0;
    for (int kt = 0; kt < NT; ++kt) {
        // issue ktile kt+2 into stage (kt+2)%4 — proven safe: barrier(kt-1) passed =>
        // all warps finished reading stage (kt-2)%4 == (kt+2)%4.
        if (kt + 2 < NT) {
            int s2 = s + 2; if (s2 >= STAGES) s2 -= STAGES;
            const unsigned d = (unsigned)(s2 * stgsz);
            const int kb = (kt + 2) * 16;
            cp16(a0off + d, Ag0 + kb); cp16(a1off + d, Ag1 + kb);
            cp16(b0off + d, Wg0 + kb); cp16(b1off + d, Wg1 + kb);
        }
        asm volatile("cp.async.commit_group;" ::: "memory");
        asm volatile("cp.async.wait_group 2;" ::: "memory");
        __syncthreads();

        const float* As_ = Asp + s * STGW;
        const float* Bs_ = Bsp + s * STGW;

        #pragma unroll
        for (int ks = 0; ks < 16; ks += 8) {
            unsigned af[4][4], bf[4][2];
            #pragma unroll
            for (int mi = 0; mi < 4; ++mi) {
                const int rb = wm * 64 + mi * 16;
                af[mi][0] = __float_as_uint(As_[(rb + g) * PITCH + ks + q]);
                af[mi][1] = __float_as_uint(As_[(rb + g + 8) * PITCH + ks + q]);
                af[mi][2] = __float_as_uint(As_[(rb + g) * PITCH + ks + q + 4]);
                af[mi][3] = __float_as_uint(As_[(rb + g + 8) * PITCH + ks + q + 4]);
            }
            #pragma unroll
            for (int ni = 0; ni < 4; ++ni) {
                const int cb = wn * 32 + ni * 8;
                bf[ni][0] = __float_as_uint(Bs_[(cb + g) * PITCH + ks + q]);
                bf[ni][1] = __float_as_uint(Bs_[(cb + g) * PITCH + ks + q + 4]);
            }
            #pragma unroll
            for (int mi = 0; mi < 4; ++mi)
                #pragma unroll
                for (int ni = 0; ni < 4; ++ni)
                    mma_tf32(acc[mi][ni], af[mi][0], af[mi][1], af[mi][2], af[mi][3],
                             bf[ni][0], bf[ni][1]);
        }
        ++s; if (s == STAGES) s = 0;
    }

    if (DINV) {
        // col 64 (warp wn==2, ni==0, q==0, element pair 0/2) holds D per row
        if (wn == 2 && q == 0) {
            #pragma unroll
            for (int mi = 0; mi < 4; ++mi) {
                Ds[wm * 64 + mi * 16 + g]     = acc[mi][0][0];
                Ds[wm * 64 + mi * 16 + g + 8] = acc[mi][0][2];
            }
        }
        __syncthreads();
    }

    #pragma unroll
    for (int mi = 0; mi < 4; ++mi) {
        const int r_ = wm * 64 + mi * 16 + g;
        float sc0 = 1.f, sc1 = 1.f;
        if (DINV) { sc0 = 1.f / Ds[r_]; sc1 = 1.f / Ds[r_ + 8]; }
        #pragma unroll
        for (int ni = 0; ni < 4; ++ni) {
            const int crel = wn * 32 + ni * 8 + (q << 1);
            if (crel < nvalid) {
                float2 v0 = make_float2(acc[mi][ni][0], acc[mi][ni][1]);
                float2 v1 = make_float2(acc[mi][ni][2], acc[mi][ni][3]);
                if (BIAS) {
                    v0.x += bias[crel]; v0.y += bias[crel + 1];
                    v1.x += bias[crel]; v1.y += bias[crel + 1];
                }
                if (DINV) {
                    v0.x *= sc0; v0.y *= sc0;
                    v1.x *= sc1; v1.y *= sc1;
                }
                if (RNAOUT) {
                    v0.x = rna_tf32(v0.x); v0.y = rna_tf32(v0.y);
                    v1.x = rna_tf32(v1.x); v1.y = rna_tf32(v1.y);
                }
                *(float2*)&C[(size_t)r_ * ldc + crel]       = v0;
                *(float2*)&C[(size_t)(r_ + 8) * ldc + crel] = v1;
            }
        }
    }

    if (maxout) {
        float mx = -CUDART_INF_F;
        #pragma unroll
        for (int mi = 0; mi < 4; ++mi)
            #pragma unroll
            for (int ni = 0; ni < 4; ++ni)
                #pragma unroll
                for (int e = 0; e < 4; ++e) {
                    int crel = wn * 32 + ni * 8 + (q << 1) + (e & 1);
                    if (crel < maxcols) mx = fmaxf(mx, acc[mi][ni][e]);
                }
        #pragma unroll
        for (int o = 16; o > 0; o >>= 1)
            mx = fmaxf(mx, __shfl_xor_sync(0xffffffffu, mx, o));
        if (lid == 0) mred[wid] = mx;
        __syncthreads();
        if (tid == 0) {
            float bm = mred[0];
            #pragma unroll
            for (int w = 1; w < 8; ++w) bm = fmaxf(bm, mred[w]);
            atomicMaxFloat(&maxout[bhidx], bm);
        }
    }
}

// ---------------- wrappers --------------------------------------------------------
__global__ void __launch_bounds__(256, 2) qkv_kernel() {
    const int z = blockIdx.z;
    const float* W = g_w4 + (size_t)z * DIMM * DIMM;
    float* C = (z == 0) ? g_q : (z == 1) ? g_k : g_v;
    const int row0 = blockIdx.y * 128, col0 = blockIdx.x * 128;
    mma_core<false, true, false>(g_xr + (size_t)row0 * DIMM, DIMM,
                    W + (size_t)col0 * DIMM, DIMM,
                    C + (size_t)row0 * DIMM + col0, DIMM, DIMM, 128,
                    nullptr, nullptr, 0, 0);
}

__global__ void __launch_bounds__(256, 2) final_kernel(const float* __restrict__ bo,
                                                       float* __restrict__ out) {
    const int row0 = blockIdx.y * 128, col0 = blockIdx.x * 128;
    mma_core<true, false, false>(g_attn + (size_t)row0 * DIMM, DIMM,
                   g_w4 + 3 * (size_t)DIMM * DIMM + (size_t)col0 * DIMM, DIMM,
                   out + (size_t)row0 * DIMM + col0, DIMM, DIMM, 128,
                   bo + col0, nullptr, 0, 0);
}

__global__ void __launch_bounds__(256, 2) dash_kernel() {
    const int z = blockIdx.z;                 // 0 = q, 1 = k
    const float* src = z ? g_k : g_q;
    float* dst = z ? g_kp : g_qp;
    const int bh = blockIdx.y >> 5, nc = blockIdx.y & 31;
    const int b = bh >> 4, h = bh & 15;
    const int col0 = blockIdx.x * 128;
    const int row0 = nc * 128;
    mma_core<false, false, false>(src + ((size_t)(b * Nn) + row0) * DIMM + h * Dd, DIMM,
                    g_projr + (size_t)col0 * Dd, Dd,
                    dst + ((size_t)bh * Nn + row0) * LDP + col0, LDP,
                    Dd, LDP - col0, nullptr,
                    z ? g_kmax : nullptr, Mm - col0, bh);
}

// out[b,n,h,e] = (1/D[n]) * sum_m qp[n,m] * ctxT[e,m];  D from ctxT row 64 (= kcum)
__global__ void __launch_bounds__(256, 2) out_mma() {
    const int t = blockIdx.y;
    const int bh = t >> 5, nt = t & 31;
    const int b = bh >> 4, h = bh & 15;
    const int row0 = nt * 128;
    mma_core<false, true, true>(g_qp + ((size_t)bh * Nn + row0) * LDP, LDP,
                    g_ctxT + (size_t)bh * 128 * LDP, LDP,
                    g_attn + ((size_t)(b * Nn) + row0) * DIMM + h * Dd, DIMM,
                    LDP, Dd, nullptr, nullptr, 0, 0);
}

// ---------------- ctx via tensor cores (4-stage, 1 sync) ------------------------------
#define CPA 132
#define CPB 68
#define CST 4
__global__ void __launch_bounds__(256) ctx_mma() {
    __shared__ float sa[CST * 16 * CPA];
    __shared__ float sb[CST * 16 * CPB];

    const int tid = threadIdx.x;
    const int wid = tid >> 5, lid = tid & 31;
    const int wm = wid >> 1, wn = wid & 1;      // 4m x 2n
    const int g = lid >> 2, q = lid & 3;
    const int bh = blockIdx.x, b = bh >> 4, h = bh & 15;
    const int m0 = blockIdx.y << 7;             // 0,128,256
    const int n0 = blockIdx.z << 9;             // 512-slabs

    const int ar0 = tid >> 5, ac0 = (tid & 31) << 2;         // rows 0..7
    const int ar1 = ar0 + 8;
    const int br0 = tid >> 4, bc0 = (tid & 15) << 2;

    const unsigned sab = smem_u32(sa);
    const unsigned sbb = smem_u32(sb);
    const unsigned a0off = sab + (unsigned)((ar0 * CPA + ac0) * 4);
    const unsigned a1off = sab + (unsigned)((ar1 * CPA + ac0) * 4);
    const unsigned boff  = sbb + (unsigned)((br0 * CPB + bc0) * 4);
    const unsigned stga = (unsigned)(16 * CPA * 4);
    const unsigned stgb = (unsigned)(16 * CPB * 4);

    const float* Ag0 = g_kp + ((size_t)bh * Nn + n0 + ar0) * LDP + m0 + ac0;
    const float* Ag1 = g_kp + ((size_t)bh * Nn + n0 + ar1) * LDP + m0 + ac0;
    const float* Bg  = g_v  + ((size_t)(b * Nn) + n0 + br0) * DIMM + h * Dd + bc0;

    float acc[2][4][4] = {};
    const int NT = 32;                           // 512 / 16

    {
        cp16(a0off, Ag0); cp16(a1off, Ag1); cp16(boff, Bg);
        asm volatile("cp.async.commit_group;" ::: "memory");
        cp16(a0off + stga, Ag0 + 16 * LDP); cp16(a1off + stga, Ag1 + 16 * LDP);
        cp16(boff + stgb, Bg + 16 * DIMM);
        asm volatile("cp.async.commit_group;" ::: "memory");
    }

    int s = 0;
    for (int kt = 0; kt < NT; ++kt) {
        if (kt + 2 < NT) {
            int s2 = s + 2; if (s2 >= CST) s2 -= CST;
            const int kb = (kt + 2) * 16;
            cp16(a0off + s2 * stga, Ag0 + (size_t)kb * LDP);
            cp16(a1off + s2 * stga, Ag1 + (size_t)kb * LDP);
            cp16(boff  + s2 * stgb, Bg  + (size_t)kb * DIMM);
        }
        asm volatile("cp.async.commit_group;" ::: "memory");
        asm volatile("cp.async.wait_group 2;" ::: "memory");
        __syncthreads();

        const float* As_ = sa + s * 16 * CPA;
        const float* Bs_ = sb + s * 16 * CPB;

        #pragma unroll
        for (int ks = 0; ks < 16; ks += 8) {
            unsigned af[2][4], bf[4][2];
            #pragma unroll
            for (int mi = 0; mi < 2; ++mi) {
                const int rb = wm * 32 + mi * 16;
                af[mi][0] = __float_as_uint(As_[(ks + q) * CPA + rb + g]);
                af[mi][1] = __float_as_uint(As_[(ks + q) * CPA + rb + g + 8]);
                af[mi][2] = __float_as_uint(As_[(ks + q + 4) * CPA + rb + g]);
                af[mi][3] = __float_as_uint(As_[(ks + q + 4) * CPA + rb + g + 8]);
            }
            #pragma unroll
            for (int ni = 0; ni < 4; ++ni) {
                const int cb = wn * 32 + ni * 8;
                bf[ni][0] = __float_as_uint(Bs_[(ks + q) * CPB + cb + g]);
                bf[ni][1] = __float_as_uint(Bs_[(ks + q + 4) * CPB + cb + g]);
            }
            #pragma unroll
            for (int mi = 0; mi < 2; ++mi)
                #pragma unroll
                for (int ni = 0; ni < 4; ++ni)
                    mma_tf32(acc[mi][ni], af[mi][0], af[mi][1], af[mi][2], af[mi][3],
                             bf[ni][0], bf[ni][1]);
        }
        ++s; if (s == CST) s = 0;
    }
    asm volatile("cp.async.wait_group 0;" ::: "memory");

    #pragma unroll
    for (int mi = 0; mi < 2; ++mi) {
        const int mA = m0 + wm * 32 + mi * 16 + g;
        #pragma unroll
        for (int ni = 0; ni < 4; ++ni) {
            const int e0 = wn * 32 + ni * 8 + (q << 1);
            if (mA < Mm) {
                atomicAdd(&g_ctxT[((size_t)bh * 128 + e0) * LDP + mA], acc[mi][ni][0]);
                atomicAdd(&g_ctxT[((size_t)bh * 128 + e0 + 1) * LDP + mA], acc[mi][ni][1]);
            }
            if (mA + 8 < Mm) {
                atomicAdd(&g_ctxT[((size_t)bh * 128 + e0) * LDP + mA + 8], acc[mi][ni][2]);
                atomicAdd(&g_ctxT[((size_t)bh * 128 + e0 + 1) * LDP + mA + 8], acc[mi][ni][3]);
            }
        }
    }
}

// ---------------- exp_q: warp per row; rowmax + diag + exp; rounded store -------------
__global__ void __launch_bounds__(256) expq_kernel() {
    const int warp = threadIdx.x >> 5, lane = threadIdx.x & 31;
    const int r = blockIdx.x * 8 + warp;
    const int bh = r >> 12, n = r & 4095;
    const int b = bh >> 4, h = bh & 15;

    const float* qrow = g_q + ((size_t)(b * Nn) + n) * DIMM + h * Dd;
    float s = qrow[lane] * qrow[lane] + qrow[lane + 32] * qrow[lane + 32];
    #pragma unroll
    for (int o = 16; o > 0; o >>= 1) s += __shfl_xor_sync(0xffffffffu, s, o);
    const float diag = 0.0625f * s;

    float* row = g_qp + (size_t)r * LDP;
    float d[9];
    float mx = -CUDART_INF_F;
    #pragma unroll
    for (int i = 0; i < 9; ++i) {
        int m = lane + i * 32;
        d[i] = row[m];
        if (m < Mm) mx = fmaxf(mx, d[i]);
    }
    #pragma unroll
    for (int o = 16; o > 0; o >>= 1) mx = fmaxf(mx, __shfl_xor_sync(0xffffffffu, mx, o));
    const float sub = diag + mx;
    #pragma unroll
    for (int i = 0; i < 9; ++i) {
        int m = lane + i * 32;
        row[m] = (m < Mm) ? rna_tf32(RATIO * (fexp(d[i] - sub) + EPSV)) : 0.f;
    }
}

// ---------------- exp_k + fused k_cumsum; rounded store --------------------------------
__global__ void __launch_bounds__(256) expk_kernel() {
    __shared__ float sums[LDP];
    const int tid = threadIdx.x;
    for (int i = tid; i < LDP; i += 256) sums[i] = 0.f;
    __syncthreads();

    const int warp = tid >> 5, lane = tid & 31;
    const int r = blockIdx.x * 8 + warp;
    const int bh = r >> 12, n = r & 4095;
    const int b = bh >> 4, h = bh & 15;

    const float* krow = g_k + ((size_t)(b * Nn) + n) * DIMM + h * Dd;
    float s = krow[lane] * krow[lane] + krow[lane + 32] * krow[lane + 32];
    #pragma unroll
    for (int o = 16; o > 0; o >>= 1) s += __shfl_xor_sync(0xffffffffu, s, o);
    const float sub = 0.0625f * s + g_kmax[bh];

    float* row = g_kp + (size_t)r * LDP;
    #pragma unroll
    for (int i = 0; i < 9; ++i) {
        int m = lane + i * 32;
        float v = (m < Mm) ? rna_tf32(RATIO * (fexp(row[m] - sub) + EPSV)) : 0.f;
        row[m] = v;
        atomicAdd(&sums[m], v);
    }
    __syncthreads();
    for (int i = tid; i < LDP; i += 256)
        atomicAdd(&g_kcum[bh * LDP + i], sums[i]);
}

// ---------------- launcher --------------------------------------------------------------
extern "C" void kernel_launch(void* const* d_in, const int* in_sizes, int n_in,
                              void* d_out, int out_size) {
    const float* x    = (const float*)d_in[0];
    const float* Wq   = (const float*)d_in[1];
    const float* Wk   = (const float*)d_in[2];
    const float* Wv   = (const float*)d_in[3];
    const float* Wo   = (const float*)d_in[4];
    const float* bo   = (const float*)d_in[5];
    const float* proj = (const float*)d_in[6];
    float* out = (float*)d_out;

    static int attr_done = 0;
    if (!attr_done) {
        cudaFuncSetAttribute(qkv_kernel,   cudaFuncAttributeMaxDynamicSharedMemorySize, CORE_SMEM);
        cudaFuncSetAttribute(final_kernel, cudaFuncAttributeMaxDynamicSharedMemorySize, CORE_SMEM);
        cudaFuncSetAttribute(dash_kernel,  cudaFuncAttributeMaxDynamicSharedMemorySize, CORE_SMEM);
        cudaFuncSetAttribute(out_mma,      cudaFuncAttributeMaxDynamicSharedMemorySize, CORE_SMEM);
        attr_done = 1;
    }

    prep_small<<<((unsigned)((size_t)BHh * Dd * LDP + 255) / 256), 256>>>(proj);
    round_x_kernel<<<ROWS * DIMM / 4 / 256, 256>>>(x);
    round_w_kernel<<<dim3(DIMM * DIMM / 4 / 256, 4), 256>>>(Wq, Wk, Wv, Wo);

    qkv_kernel<<<dim3(DIMM / 128, ROWS / 128, 3), 256, CORE_SMEM>>>();

    dash_kernel<<<dim3(3, BHh * 32, 2), 256, CORE_SMEM>>>();

    expq_kernel<<<BHh * Nn / 8, 256>>>();
    expk_kernel<<<BHh * Nn / 8, 256>>>();

    ctx_mma<<<dim3(BHh, 3, 8), 256>>>();
    round_ctxT<<<(BHh * Dd * LDP / 4 + 255) / 256, 256>>>();
    copy_kcum<<<(BHh * LDP + 255) / 256, 256>>>();

    out_mma<<<dim3(1, BHh * 32), 256, CORE_SMEM>>>();

    final_kernel<<<dim3(DIMM / 128, ROWS / 128), 256, CORE_SMEM>>>(bo, out);
}

// round 11
// speedup vs baseline: 1.3161x; 1.0585x over previous
#include <cuda_runtime.h>
#include <math.h>
#include <math_constants.h>

// Problem constants
#define Bz   2
#define Nn   4096
#define DIMM 1024
#define Hh   16
#define Dd   64
#define Mm   266
#define BHh  (Bz*Hh)        // 32
#define ROWS (Bz*Nn)        // 8192
#define LDP  288            // padded feature row length

#define NORMALIZER 0.35355339059327373f   // 64^-0.25
#define RATIO      0.061313933948496576f  // 266^-0.5
#define EPSV       1e-4f
#define LOG2E      1.4426950408889634f

#define PITCH   20
#define STAGES  4
#define STGW    (128*PITCH)
#define BOFFW   (STAGES*STGW)
#define CORE_SMEM (STAGES*STGW*4*2)                // 81920 bytes

// ---------------- scratch -------------------------------------------------------
__device__ float g_q[ROWS*DIMM];
__device__ float g_k[ROWS*DIMM];
__device__ float g_v[ROWS*DIMM];
__device__ float g_attn[ROWS*DIMM];
__device__ float g_xr[ROWS*DIMM];                  // tf32-rounded x
__device__ float g_w4[4*DIMM*DIMM];                // tf32-rounded Wq,Wk,Wv,Wo
__device__ float g_projr[384*Dd];                  // rounded*NORMALIZER, padded
__device__ float g_qp[(size_t)BHh*Nn*LDP + 128];
__device__ float g_kp[(size_t)BHh*Nn*LDP + 128];   // +128 pad: ctx m-tile 2 over-reads
__device__ float g_kmax[BHh];
__device__ float g_kcum[BHh*LDP];
__device__ float g_ctxT[(size_t)BHh*128*LDP];      // [e][m]; rows 0..63 ctx, row 64 kcum, 65..127 zero

// ---------------- helpers -------------------------------------------------------
__device__ __forceinline__ unsigned smem_u32(const void* p) {
    unsigned a;
    asm("{ .reg .u64 t; cvta.to.shared.u64 t, %1; cvt.u32.u64 %0, t; }" : "=r"(a) : "l"(p));
    return a;
}
__device__ __forceinline__ float rna_tf32(float v) {
    unsigned u;
    asm("cvt.rna.tf32.f32 %0, %1;" : "=r"(u) : "f"(v));
    return __uint_as_float(u);
}
__device__ __forceinline__ float fexp(float x) {
    float y;
    asm("ex2.approx.f32 %0, %1;" : "=f"(y) : "f"(x * LOG2E));
    return y;
}
__device__ __forceinline__ void cp16(unsigned dst, const float* src) {
    asm volatile("cp.async.ca.shared.global [%0], [%1], 16;" :: "r"(dst), "l"(src));
}

__device__ __forceinline__ void mma_tf32(float c[4],
                                         unsigned a0, unsigned a1, unsigned a2, unsigned a3,
                                         unsigned b0, unsigned b1) {
    asm volatile(
        "mma.sync.aligned.m16n8k8.row.col.f32.tf32.tf32.f32 "
        "{%0,%1,%2,%3}, {%4,%5,%6,%7}, {%8,%9}, {%0,%1,%2,%3};"
        : "+f"(c[0]), "+f"(c[1]), "+f"(c[2]), "+f"(c[3])
        : "r"(a0), "r"(a1), "r"(a2), "r"(a3), "r"(b0), "r"(b1));
}

__device__ __forceinline__ void atomicMaxFloat(float* addr, float val) {
    int* a = (int*)addr;
    int old = *a;
    while (__int_as_float(old) < val) {
        int assumed = old;
        old = atomicCAS(a, assumed, __float_as_int(val));
        if (old == assumed) break;
    }
}

// ---------------- prep: init + proj rounding --------------------------------------
__global__ void prep_small(const float* __restrict__ proj) {
    size_t t = (size_t)blockIdx.x * blockDim.x + threadIdx.x;
    if (t < BHh) g_kmax[t] = -CUDART_INF_F;
    if (t < BHh * LDP) g_kcum[t] = 0.f;
    if (t < 384 * Dd) {
        int m = (int)(t >> 6);
        g_projr[t] = (m < Mm) ? rna_tf32(proj[t] * NORMALIZER) : 0.f;
    }
    if (t < (size_t)BHh * Dd * LDP) {       // zero ctx rows 0..63 per bh (atomics accumulate)
        size_t bh = t / (Dd * LDP);
        size_t rem = t - bh * (Dd * LDP);
        g_ctxT[bh * 128 * LDP + rem] = 0.f;
    }
}

__global__ void round_x_kernel(const float* __restrict__ in) {
    int i = blockIdx.x * blockDim.x + threadIdx.x;
    float4 v = ((const float4*)in)[i];
    v.x = rna_tf32(v.x); v.y = rna_tf32(v.y); v.z = rna_tf32(v.z); v.w = rna_tf32(v.w);
    ((float4*)g_xr)[i] = v;
}
__global__ void round_w_kernel(const float* __restrict__ w0, const float* __restrict__ w1,
                               const float* __restrict__ w2, const float* __restrict__ w3) {
    int z = blockIdx.y;
    const float* w = (z == 0) ? w0 : (z == 1) ? w1 : (z == 2) ? w2 : w3;
    int i = blockIdx.x * blockDim.x + threadIdx.x;
    float4 v = ((const float4*)w)[i];
    v.x = rna_tf32(v.x); v.y = rna_tf32(v.y); v.z = rna_tf32(v.z); v.w = rna_tf32(v.w);
    ((float4*)(g_w4 + (size_t)z * DIMM * DIMM))[i] = v;
}
__global__ void round_ctxT() {
    size_t i = (size_t)blockIdx.x * 256 + threadIdx.x;
    const size_t per_bh = (size_t)Dd * LDP / 4;
    if (i >= (size_t)BHh * per_bh) return;
    size_t bh = i / per_bh;
    size_t rem = i - bh * per_bh;
    float4* p = (float4*)(g_ctxT + bh * 128 * LDP) + rem;
    float4 v = *p;
    v.x = rna_tf32(v.x); v.y = rna_tf32(v.y); v.z = rna_tf32(v.z); v.w = rna_tf32(v.w);
    *p = v;
}
__global__ void copy_kcum() {
    int i = blockIdx.x * 256 + threadIdx.x;
    if (i >= BHh * LDP) return;
    int bh = i / LDP, m = i - bh * LDP;
    g_ctxT[((size_t)bh * 128 + 64) * LDP + m] = rna_tf32(g_kcum[i]);
}

// ---------------- mma core: 128x128 CTA, 4 warps (64x64 each), 4-stage cp.async -------
// C[r][c] = sum_k A[r][k] * W[c][k] (+bias). DINV: col 64 of acc = D, scale rows by 1/D.
template<bool BIAS, bool RNAOUT, bool DINV>
__device__ __forceinline__ void mma_core(const float* __restrict__ A, int lda,
                                         const float* __restrict__ W, int ldb,
                                         float* __restrict__ C, int ldc,
                                         int K, int nvalid,
                                         const float* __restrict__ bias,
                                         float* __restrict__ maxout, int maxcols, int bhidx) {
    extern __shared__ float sm[];
    __shared__ float mred[4];
    __shared__ float Ds[128];
    float* Asp = sm;
    float* Bsp = sm + BOFFW;

    const int tid = threadIdx.x;        // 0..127
    const int wid = tid >> 5, lid = tid & 31;
    const int wm = wid >> 1;            // 0..1  (64-row slab)
    const int wn = wid & 1;             // 0..1  (64-col slab)
    const int g = lid >> 2, q = lid & 3;

    // loader: 4 rows per thread per operand (rows tid>>2 + 32*i), 16B each
    const int lr = tid >> 2;            // 0..31
    const int lc0 = (tid & 3) << 2;

    const unsigned sbase = smem_u32(sm);
    unsigned aoff[4], boff[4];
    #pragma unroll
    for (int i = 0; i < 4; ++i) {
        aoff[i] = sbase + (unsigned)(((lr + 32 * i) * PITCH + lc0) * 4);
        boff[i] = aoff[i] + (unsigned)(BOFFW * 4);
    }
    const unsigned stgsz = (unsigned)(STGW * 4);

    const float* Ag = A + (size_t)lr * lda + lc0;
    const float* Wg = W + (size_t)lr * ldb + lc0;
    const size_t a32 = (size_t)32 * lda;
    const size_t w32 = (size_t)32 * ldb;

    float acc[4][8][4] = {};
    const int NT = K >> 4;

    {   // prologue: stages 0,1
        #pragma unroll
        for (int i = 0; i < 4; ++i) { cp16(aoff[i], Ag + i * a32); cp16(boff[i], Wg + i * w32); }
        asm volatile("cp.async.commit_group;" ::: "memory");
        if (NT > 1) {
            #pragma unroll
            for (int i = 0; i < 4; ++i) { cp16(aoff[i] + stgsz, Ag + i * a32 + 16); cp16(boff[i] + stgsz, Wg + i * w32 + 16); }
        }
        asm volatile("cp.async.commit_group;" ::: "memory");
    }

    int s = 0;
    for (int kt = 0; kt < NT; ++kt) {
        // issue ktile kt+2 into stage (kt+2)%4 (safe: barrier(kt-1) => stage free)
        if (kt + 2 < NT) {
            int s2 = s + 2; if (s2 >= STAGES) s2 -= STAGES;
            const unsigned d = (unsigned)(s2 * stgsz);
            const int kb = (kt + 2) * 16;
            #pragma unroll
            for (int i = 0; i < 4; ++i) { cp16(aoff[i] + d, Ag + i * a32 + kb); cp16(boff[i] + d, Wg + i * w32 + kb); }
        }
        asm volatile("cp.async.commit_group;" ::: "memory");
        asm volatile("cp.async.wait_group 2;" ::: "memory");
        __syncthreads();

        const float* As_ = Asp + s * STGW;
        const float* Bs_ = Bsp + s * STGW;

        #pragma unroll
        for (int ks = 0; ks < 16; ks += 8) {
            unsigned af[4][4], bf[8][2];
            #pragma unroll
            for (int mi = 0; mi < 4; ++mi) {
                const int rb = wm * 64 + mi * 16;
                af[mi][0] = __float_as_uint(As_[(rb + g) * PITCH + ks + q]);
                af[mi][1] = __float_as_uint(As_[(rb + g + 8) * PITCH + ks + q]);
                af[mi][2] = __float_as_uint(As_[(rb + g) * PITCH + ks + q + 4]);
                af[mi][3] = __float_as_uint(As_[(rb + g + 8) * PITCH + ks + q + 4]);
            }
            #pragma unroll
            for (int ni = 0; ni < 8; ++ni) {
                const int cb = wn * 64 + ni * 8;
                bf[ni][0] = __float_as_uint(Bs_[(cb + g) * PITCH + ks + q]);
                bf[ni][1] = __float_as_uint(Bs_[(cb + g) * PITCH + ks + q + 4]);
            }
            #pragma unroll
            for (int mi = 0; mi < 4; ++mi)
                #pragma unroll
                for (int ni = 0; ni < 8; ++ni)
                    mma_tf32(acc[mi][ni], af[mi][0], af[mi][1], af[mi][2], af[mi][3],
                             bf[ni][0], bf[ni][1]);
        }
        ++s; if (s == STAGES) s = 0;
    }

    if (DINV) {
        // col 64: wn==1, ni==0, q==0; elements 0 (row r), 2 (row r+8)
        if (wn == 1 && q == 0) {
            #pragma unroll
            for (int mi = 0; mi < 4; ++mi) {
                Ds[wm * 64 + mi * 16 + g]     = acc[mi][0][0];
                Ds[wm * 64 + mi * 16 + g + 8] = acc[mi][0][2];
            }
        }
        __syncthreads();
    }

    #pragma unroll
    for (int mi = 0; mi < 4; ++mi) {
        const int r_ = wm * 64 + mi * 16 + g;
        float sc0 = 1.f, sc1 = 1.f;
        if (DINV) { sc0 = 1.f / Ds[r_]; sc1 = 1.f / Ds[r_ + 8]; }
        #pragma unroll
        for (int ni = 0; ni < 8; ++ni) {
            const int crel = wn * 64 + ni * 8 + (q << 1);
            if (crel < nvalid) {
                float2 v0 = make_float2(acc[mi][ni][0], acc[mi][ni][1]);
                float2 v1 = make_float2(acc[mi][ni][2], acc[mi][ni][3]);
                if (BIAS) {
                    v0.x += bias[crel]; v0.y += bias[crel + 1];
                    v1.x += bias[crel]; v1.y += bias[crel + 1];
                }
                if (DINV) {
                    v0.x *= sc0; v0.y *= sc0;
                    v1.x *= sc1; v1.y *= sc1;
                }
                if (RNAOUT) {
                    v0.x = rna_tf32(v0.x); v0.y = rna_tf32(v0.y);
                    v1.x = rna_tf32(v1.x); v1.y = rna_tf32(v1.y);
                }
                *(float2*)&C[(size_t)r_ * ldc + crel]       = v0;
                *(float2*)&C[(size_t)(r_ + 8) * ldc + crel] = v1;
            }
        }
    }

    if (maxout) {
        float mx = -CUDART_INF_F;
        #pragma unroll
        for (int mi = 0; mi < 4; ++mi)
            #pragma unroll
            for (int ni = 0; ni < 8; ++ni)
                #pragma unroll
                for (int e = 0; e < 4; ++e) {
                    int crel = wn * 64 + ni * 8 + (q << 1) + (e & 1);
                    if (crel < maxcols) mx = fmaxf(mx, acc[mi][ni][e]);
                }
        #pragma unroll
        for (int o = 16; o > 0; o >>= 1)
            mx = fmaxf(mx, __shfl_xor_sync(0xffffffffu, mx, o));
        if (lid == 0) mred[wid] = mx;
        __syncthreads();
        if (tid == 0) {
            float bm = fmaxf(fmaxf(mred[0], mred[1]), fmaxf(mred[2], mred[3]));
            atomicMaxFloat(&maxout[bhidx], bm);
        }
    }
}

// ---------------- wrappers (128 threads) --------------------------------------------
__global__ void __launch_bounds__(128, 2) qkv_kernel() {
    const int z = blockIdx.z;
    const float* W = g_w4 + (size_t)z * DIMM * DIMM;
    float* C = (z == 0) ? g_q : (z == 1) ? g_k : g_v;
    const int row0 = blockIdx.y * 128, col0 = blockIdx.x * 128;
    mma_core<false, true, false>(g_xr + (size_t)row0 * DIMM, DIMM,
                    W + (size_t)col0 * DIMM, DIMM,
                    C + (size_t)row0 * DIMM + col0, DIMM, DIMM, 128,
                    nullptr, nullptr, 0, 0);
}

__global__ void __launch_bounds__(128, 2) final_kernel(const float* __restrict__ bo,
                                                       float* __restrict__ out) {
    const int row0 = blockIdx.y * 128, col0 = blockIdx.x * 128;
    mma_core<true, false, false>(g_attn + (size_t)row0 * DIMM, DIMM,
                   g_w4 + 3 * (size_t)DIMM * DIMM + (size_t)col0 * DIMM, DIMM,
                   out + (size_t)row0 * DIMM + col0, DIMM, DIMM, 128,
                   bo + col0, nullptr, 0, 0);
}

__global__ void __launch_bounds__(128, 2) dash_kernel() {
    const int z = blockIdx.z;                 // 0 = q, 1 = k
    const float* src = z ? g_k : g_q;
    float* dst = z ? g_kp : g_qp;
    const int bh = blockIdx.y >> 5, nc = blockIdx.y & 31;
    const int b = bh >> 4, h = bh & 15;
    const int col0 = blockIdx.x * 128;
    const int row0 = nc * 128;
    mma_core<false, false, false>(src + ((size_t)(b * Nn) + row0) * DIMM + h * Dd, DIMM,
                    g_projr + (size_t)col0 * Dd, Dd,
                    dst + ((size_t)bh * Nn + row0) * LDP + col0, LDP,
                    Dd, LDP - col0, nullptr,
                    z ? g_kmax : nullptr, Mm - col0, bh);
}

// out[b,n,h,e] = (1/D[n]) * sum_m qp[n,m] * ctxT[e,m];  D from ctxT row 64 (= kcum)
__global__ void __launch_bounds__(128, 2) out_mma() {
    const int t = blockIdx.y;
    const int bh = t >> 5, nt = t & 31;
    const int b = bh >> 4, h = bh & 15;
    const int row0 = nt * 128;
    mma_core<false, true, true>(g_qp + ((size_t)bh * Nn + row0) * LDP, LDP,
                    g_ctxT + (size_t)bh * 128 * LDP, LDP,
                    g_attn + ((size_t)(b * Nn) + row0) * DIMM + h * Dd, DIMM,
                    LDP, Dd, nullptr, nullptr, 0, 0);
}

// ---------------- ctx via tensor cores (4-stage, 1 sync; 256 threads) -----------------
#define CPA 132
#define CPB 68
#define CST 4
__global__ void __launch_bounds__(256) ctx_mma() {
    __shared__ float sa[CST * 16 * CPA];
    __shared__ float sb[CST * 16 * CPB];

    const int tid = threadIdx.x;
    const int wid = tid >> 5, lid = tid & 31;
    const int wm = wid >> 1, wn = wid & 1;      // 4m x 2n
    const int g = lid >> 2, q = lid & 3;
    const int bh = blockIdx.x, b = bh >> 4, h = bh & 15;
    const int m0 = blockIdx.y << 7;             // 0,128,256
    const int n0 = blockIdx.z << 9;             // 512-slabs

    const int ar0 = tid >> 5, ac0 = (tid & 31) << 2;
    const int ar1 = ar0 + 8;
    const int br0 = tid >> 4, bc0 = (tid & 15) << 2;

    const unsigned sab = smem_u32(sa);
    const unsigned sbb = smem_u32(sb);
    const unsigned a0off = sab + (unsigned)((ar0 * CPA + ac0) * 4);
    const unsigned a1off = sab + (unsigned)((ar1 * CPA + ac0) * 4);
    const unsigned boff  = sbb + (unsigned)((br0 * CPB + bc0) * 4);
    const unsigned stga = (unsigned)(16 * CPA * 4);
    const unsigned stgb = (unsigned)(16 * CPB * 4);

    const float* Ag0 = g_kp + ((size_t)bh * Nn + n0 + ar0) * LDP + m0 + ac0;
    const float* Ag1 = g_kp + ((size_t)bh * Nn + n0 + ar1) * LDP + m0 + ac0;
    const float* Bg  = g_v  + ((size_t)(b * Nn) + n0 + br0) * DIMM + h * Dd + bc0;

    float acc[2][4][4] = {};
    const int NT = 32;

    {
        cp16(a0off, Ag0); cp16(a1off, Ag1); cp16(boff, Bg);
        asm volatile("cp.async.commit_group;" ::: "memory");
        cp16(a0off + stga, Ag0 + 16 * LDP); cp16(a1off + stga, Ag1 + 16 * LDP);
        cp16(boff + stgb, Bg + 16 * DIMM);
        asm volatile("cp.async.commit_group;" ::: "memory");
    }

    int s = 0;
    for (int kt = 0; kt < NT; ++kt) {
        if (kt + 2 < NT) {
            int s2 = s + 2; if (s2 >= CST) s2 -= CST;
            const int kb = (kt + 2) * 16;
            cp16(a0off + s2 * stga, Ag0 + (size_t)kb * LDP);
            cp16(a1off + s2 * stga, Ag1 + (size_t)kb * LDP);
            cp16(boff  + s2 * stgb, Bg  + (size_t)kb * DIMM);
        }
        asm volatile("cp.async.commit_group;" ::: "memory");
        asm volatile("cp.async.wait_group 2;" ::: "memory");
        __syncthreads();

        const float* As_ = sa + s * 16 * CPA;
        const float* Bs_ = sb + s * 16 * CPB;

        #pragma unroll
        for (int ks = 0; ks < 16; ks += 8) {
            unsigned af[2][4], bf[4][2];
            #pragma unroll
            for (int mi = 0; mi < 2; ++mi) {
                const int rb = wm * 32 + mi * 16;
                af[mi][0] = __float_as_uint(As_[(ks + q) * CPA + rb + g]);
                af[mi][1] = __float_as_uint(As_[(ks + q) * CPA + rb + g + 8]);
                af[mi][2] = __float_as_uint(As_[(ks + q + 4) * CPA + rb + g]);
                af[mi][3] = __float_as_uint(As_[(ks + q + 4) * CPA + rb + g + 8]);
            }
            #pragma unroll
            for (int ni = 0; ni < 4; ++ni) {
                const int cb = wn * 32 + ni * 8;
                bf[ni][0] = __float_as_uint(Bs_[(ks + q) * CPB + cb + g]);
                bf[ni][1] = __float_as_uint(Bs_[(ks + q + 4) * CPB + cb + g]);
            }
            #pragma unroll
            for (int mi = 0; mi < 2; ++mi)
                #pragma unroll
                for (int ni = 0; ni < 4; ++ni)
                    mma_tf32(acc[mi][ni], af[mi][0], af[mi][1], af[mi][2], af[mi][3],
                             bf[ni][0], bf[ni][1]);
        }
        ++s; if (s == CST) s = 0;
    }
    asm volatile("cp.async.wait_group 0;" ::: "memory");

    #pragma unroll
    for (int mi = 0; mi < 2; ++mi) {
        const int mA = m0 + wm * 32 + mi * 16 + g;
        #pragma unroll
        for (int ni = 0; ni < 4; ++ni) {
            const int e0 = wn * 32 + ni * 8 + (q << 1);
            if (mA < Mm) {
                atomicAdd(&g_ctxT[((size_t)bh * 128 + e0) * LDP + mA], acc[mi][ni][0]);
                atomicAdd(&g_ctxT[((size_t)bh * 128 + e0 + 1) * LDP + mA], acc[mi][ni][1]);
            }
            if (mA + 8 < Mm) {
                atomicAdd(&g_ctxT[((size_t)bh * 128 + e0) * LDP + mA + 8], acc[mi][ni][2]);
                atomicAdd(&g_ctxT[((size_t)bh * 128 + e0 + 1) * LDP + mA + 8], acc[mi][ni][3]);
            }
        }
    }
}

// ---------------- exp_q ------------------------------------------------------------
__global__ void __launch_bounds__(256) expq_kernel() {
    const int warp = threadIdx.x >> 5, lane = threadIdx.x & 31;
    const int r = blockIdx.x * 8 + warp;
    const int bh = r >> 12, n = r & 4095;
    const int b = bh >> 4, h = bh & 15;

    const float* qrow = g_q + ((size_t)(b * Nn) + n) * DIMM + h * Dd;
    float s = qrow[lane] * qrow[lane] + qrow[lane + 32] * qrow[lane + 32];
    #pragma unroll
    for (int o = 16; o > 0; o >>= 1) s += __shfl_xor_sync(0xffffffffu, s, o);
    const float diag = 0.0625f * s;

    float* row = g_qp + (size_t)r * LDP;
    float d[9];
    float mx = -CUDART_INF_F;
    #pragma unroll
    for (int i = 0; i < 9; ++i) {
        int m = lane + i * 32;
        d[i] = row[m];
        if (m < Mm) mx = fmaxf(mx, d[i]);
    }
    #pragma unroll
    for (int o = 16; o > 0; o >>= 1) mx = fmaxf(mx, __shfl_xor_sync(0xffffffffu, mx, o));
    const float sub = diag + mx;
    #pragma unroll
    for (int i = 0; i < 9; ++i) {
        int m = lane + i * 32;
        row[m] = (m < Mm) ? rna_tf32(RATIO * (fexp(d[i] - sub) + EPSV)) : 0.f;
    }
}

// ---------------- exp_k + fused k_cumsum ----------------------------------------------
__global__ void __launch_bounds__(256) expk_kernel() {
    __shared__ float sums[LDP];
    const int tid = threadIdx.x;
    for (int i = tid; i < LDP; i += 256) sums[i] = 0.f;
    __syncthreads();

    const int warp = tid >> 5, lane = tid & 31;
    const int r = blockIdx.x * 8 + warp;
    const int bh = r >> 12, n = r & 4095;
    const int b = bh >> 4, h = bh & 15;

    const float* krow = g_k + ((size_t)(b * Nn) + n) * DIMM + h * Dd;
    float s = krow[lane] * krow[lane] + krow[lane + 32] * krow[lane + 32];
    #pragma unroll
    for (int o = 16; o > 0; o >>= 1) s += __shfl_xor_sync(0xffffffffu, s, o);
    const float sub = 0.0625f * s + g_kmax[bh];

    float* row = g_kp + (size_t)r * LDP;
    #pragma unroll
    for (int i = 0; i < 9; ++i) {
        int m = lane + i * 32;
        float v = (m < Mm) ? rna_tf32(RATIO * (fexp(row[m] - sub) + EPSV)) : 0.f;
        row[m] = v;
        atomicAdd(&sums[m], v);
    }
    __syncthreads();
    for (int i = tid; i < LDP; i += 256)
        atomicAdd(&g_kcum[bh * LDP + i], sums[i]);
}

// ---------------- launcher --------------------------------------------------------------
extern "C" void kernel_launch(void* const* d_in, const int* in_sizes, int n_in,
                              void* d_out, int out_size) {
    const float* x    = (const float*)d_in[0];
    const float* Wq   = (const float*)d_in[1];
    const float* Wk   = (const float*)d_in[2];
    const float* Wv   = (const float*)d_in[3];
    const float* Wo   = (const float*)d_in[4];
    const float* bo   = (const float*)d_in[5];
    const float* proj = (const float*)d_in[6];
    float* out = (float*)d_out;

    static int attr_done = 0;
    if (!attr_done) {
        cudaFuncSetAttribute(qkv_kernel,   cudaFuncAttributeMaxDynamicSharedMemorySize, CORE_SMEM);
        cudaFuncSetAttribute(final_kernel, cudaFuncAttributeMaxDynamicSharedMemorySize, CORE_SMEM);
        cudaFuncSetAttribute(dash_kernel,  cudaFuncAttributeMaxDynamicSharedMemorySize, CORE_SMEM);
        cudaFuncSetAttribute(out_mma,      cudaFuncAttributeMaxDynamicSharedMemorySize, CORE_SMEM);
        attr_done = 1;
    }

    prep_small<<<((unsigned)((size_t)BHh * Dd * LDP + 255) / 256), 256>>>(proj);
    round_x_kernel<<<ROWS * DIMM / 4 / 256, 256>>>(x);
    round_w_kernel<<<dim3(DIMM * DIMM / 4 / 256, 4), 256>>>(Wq, Wk, Wv, Wo);

    qkv_kernel<<<dim3(DIMM / 128, ROWS / 128, 3), 128, CORE_SMEM>>>();

    dash_kernel<<<dim3(3, BHh * 32, 2), 128, CORE_SMEM>>>();

    expq_kernel<<<BHh * Nn / 8, 256>>>();
    expk_kernel<<<BHh * Nn / 8, 256>>>();

    ctx_mma<<<dim3(BHh, 3, 8), 256>>>();
    round_ctxT<<<(BHh * Dd * LDP / 4 + 255) / 256, 256>>>();
    copy_kcum<<<(BHh * LDP + 255) / 256, 256>>>();

    out_mma<<<dim3(1, BHh * 32), 128, CORE_SMEM>>>();

    final_kernel<<<dim3(DIMM / 128, ROWS / 128), 128, CORE_SMEM>>>(bo, out);
}

// round 12
// speedup vs baseline: 1.9403x; 1.4743x over previous
#include <cuda_runtime.h>
#include <cuda_fp16.h>
#include <math.h>
#include <math_constants.h>

// Problem constants
#define Bz   2
#define Nn   4096
#define DIMM 1024
#define Hh   16
#define Dd   64
#define Mm   266
#define BHh  (Bz*Hh)        // 32
#define ROWS (Bz*Nn)        // 8192
#define LDP  288            // padded feature row length

#define NORMALIZER 0.35355339059327373f   // 64^-0.25
#define RATIO      0.061313933948496576f  // 266^-0.5
#define EPSV       1e-4f
#define LOG2E      1.4426950408889634f

#define STAGES  4
#define PITCHH  40                                 // halfs per smem row
#define HSTGB   (128*PITCHH*2)                     // 10240 B per operand stage
#define HBOFFB  (STAGES*HSTGB)                     // 40960 B: B-operand region offset
#define CORE_SMEM (STAGES*HSTGB*2)                 // 81920 B

// ---------------- scratch -------------------------------------------------------
__device__ __half g_xh[ROWS*DIMM];                 // fp16 x
__device__ __half g_wh[4*(size_t)DIMM*DIMM];       // fp16 Wq,Wk,Wv,Wo
__device__ __half g_projh[384*Dd];                 // fp16 proj*NORMALIZER, padded
__device__ __half g_qh[ROWS*DIMM];                 // fp16 q
__device__ __half g_kh[ROWS*DIMM];                 // fp16 k
__device__ float  g_v [ROWS*DIMM];                 // fp32 (tf32-rounded) v for ctx
__device__ __half g_attnh[ROWS*DIMM];              // fp16 attn
__device__ float  g_qp[(size_t)BHh*Nn*LDP + 128];  // fp32 raw q dash
__device__ float  g_kp[(size_t)BHh*Nn*LDP + 128];  // fp32 dash -> tf32 kp (ctx A)
__device__ __half g_qph[(size_t)BHh*Nn*LDP];       // fp16 qp features (out A)
__device__ float  g_kmax[BHh];
__device__ float  g_kcum[BHh*LDP];
__device__ float  g_ctxT[(size_t)BHh*128*LDP];     // fp32 atomics target [e][m]
__device__ __half g_ctxTh[(size_t)BHh*128*LDP];    // fp16 [e][m]; row 64 = kcum; 65..127 stay 0

// ---------------- helpers -------------------------------------------------------
__device__ __forceinline__ unsigned smem_u32(const void* p) {
    unsigned a;
    asm("{ .reg .u64 t; cvta.to.shared.u64 t, %1; cvt.u32.u64 %0, t; }" : "=r"(a) : "l"(p));
    return a;
}
__device__ __forceinline__ float rna_tf32(float v) {
    unsigned u;
    asm("cvt.rna.tf32.f32 %0, %1;" : "=r"(u) : "f"(v));
    return __uint_as_float(u);
}
__device__ __forceinline__ float fexp(float x) {
    float y;
    asm("ex2.approx.f32 %0, %1;" : "=f"(y) : "f"(x * LOG2E));
    return y;
}
__device__ __forceinline__ void cp16(unsigned dst, const void* src) {
    asm volatile("cp.async.ca.shared.global [%0], [%1], 16;" :: "r"(dst), "l"(src));
}
__device__ __forceinline__ void mma_f16(float c[4],
                                        unsigned a0, unsigned a1, unsigned a2, unsigned a3,
                                        unsigned b0, unsigned b1) {
    asm volatile(
        "mma.sync.aligned.m16n8k16.row.col.f32.f16.f16.f32 "
        "{%0,%1,%2,%3}, {%4,%5,%6,%7}, {%8,%9}, {%0,%1,%2,%3};"
        : "+f"(c[0]), "+f"(c[1]), "+f"(c[2]), "+f"(c[3])
        : "r"(a0), "r"(a1), "r"(a2), "r"(a3), "r"(b0), "r"(b1));
}
__device__ __forceinline__ void mma_tf32(float c[4],
                                         unsigned a0, unsigned a1, unsigned a2, unsigned a3,
                                         unsigned b0, unsigned b1) {
    asm volatile(
        "mma.sync.aligned.m16n8k8.row.col.f32.tf32.tf32.f32 "
        "{%0,%1,%2,%3}, {%4,%5,%6,%7}, {%8,%9}, {%0,%1,%2,%3};"
        : "+f"(c[0]), "+f"(c[1]), "+f"(c[2]), "+f"(c[3])
        : "r"(a0), "r"(a1), "r"(a2), "r"(a3), "r"(b0), "r"(b1));
}
__device__ __forceinline__ void atomicMaxFloat(float* addr, float val) {
    int* a = (int*)addr;
    int old = *a;
    while (__int_as_float(old) < val) {
        int assumed = old;
        old = atomicCAS(a, assumed, __float_as_int(val));
        if (old == assumed) break;
    }
}

// ---------------- prep / conversion passes -----------------------------------------
__global__ void prep_small(const float* __restrict__ proj) {
    size_t t = (size_t)blockIdx.x * blockDim.x + threadIdx.x;
    if (t < BHh) g_kmax[t] = -CUDART_INF_F;
    if (t < BHh * LDP) g_kcum[t] = 0.f;
    if (t < 384 * Dd) {
        int m = (int)(t >> 6);
        g_projh[t] = (m < Mm) ? __float2half_rn(proj[t] * NORMALIZER) : __half(0.f);
    }
    if (t < (size_t)BHh * Dd * LDP) {       // zero ctx rows 0..63 per bh
        size_t bh = t / (Dd * LDP);
        size_t rem = t - bh * (Dd * LDP);
        g_ctxT[bh * 128 * LDP + rem] = 0.f;
    }
}
__global__ void round_xh(const float* __restrict__ in) {
    int i = blockIdx.x * blockDim.x + threadIdx.x;      // float4 index
    float4 v = ((const float4*)in)[i];
    ((__half2*)g_xh)[2*i]   = __floats2half2_rn(v.x, v.y);
    ((__half2*)g_xh)[2*i+1] = __floats2half2_rn(v.z, v.w);
}
__global__ void round_wh(const float* __restrict__ w0, const float* __restrict__ w1,
                         const float* __restrict__ w2, const float* __restrict__ w3) {
    int z = blockIdx.y;
    const float* w = (z == 0) ? w0 : (z == 1) ? w1 : (z == 2) ? w2 : w3;
    int i = blockIdx.x * blockDim.x + threadIdx.x;
    float4 v = ((const float4*)w)[i];
    __half2* o = (__half2*)(g_wh + (size_t)z * DIMM * DIMM);
    o[2*i]   = __floats2half2_rn(v.x, v.y);
    o[2*i+1] = __floats2half2_rn(v.z, v.w);
}
// ctxT rows 0..63 -> half, row 64 = half(kcum)
__global__ void fix_kernel() {
    size_t t = (size_t)blockIdx.x * 256 + threadIdx.x;
    const size_t per_bh = (size_t)65 * LDP;
    if (t >= (size_t)BHh * per_bh) return;
    size_t bh = t / per_bh;
    size_t rem = t - bh * per_bh;
    int row = (int)(rem / LDP), m = (int)(rem - (size_t)row * LDP);
    float v = (row < 64) ? g_ctxT[(bh * 128 + row) * LDP + m] : g_kcum[bh * LDP + m];
    g_ctxTh[(bh * 128 + row) * LDP + m] = __float2half_rn(v);
}

// ---------------- fp16 mma core: 128x128 CTA, 4 warps 64x64, 4-stage cp.async ---------
// C[r][c] = sum_k A[r][k]*W[c][k] (+bias). DINV: acc col 64 = D; rows scaled by 1/D.
// Output: Ch (half) if non-null else Cf (float; RNAF => tf32-rounded). K % 32 == 0.
template<bool BIAS, bool DINV, bool RNAF>
__device__ __forceinline__ void mma_core_h(const __half* __restrict__ A, int lda,
                                           const __half* __restrict__ W, int ldb,
                                           __half* __restrict__ Ch,
                                           float* __restrict__ Cf, int ldc,
                                           int K, int nvalid,
                                           const float* __restrict__ bias,
                                           float* __restrict__ maxout, int maxcols, int bhidx) {
    extern __shared__ char smc[];
    __shared__ float mred[4];
    __shared__ float Ds[128];

    const int tid = threadIdx.x;        // 0..127
    const int wid = tid >> 5, lid = tid & 31;
    const int wm = wid >> 1;            // 64-row slab
    const int wn = wid & 1;             // 64-col slab
    const int g = lid >> 2, q = lid & 3;

    const int lr = tid >> 2;            // 0..31
    const int lc0 = (tid & 3) << 3;     // half offset (8 halfs = 16B)

    const unsigned sbase = smem_u32(smc);
    unsigned aoff[4], boff[4];
    #pragma unroll
    for (int i = 0; i < 4; ++i) {
        aoff[i] = sbase + (unsigned)(((lr + 32 * i) * PITCHH + lc0) * 2);
        boff[i] = aoff[i] + (unsigned)HBOFFB;
    }

    const __half* Ag = A + (size_t)lr * lda + lc0;
    const __half* Wg = W + (size_t)lr * ldb + lc0;
    const size_t a32 = (size_t)32 * lda;
    const size_t w32 = (size_t)32 * ldb;

    float acc[4][8][4] = {};
    const int NT = K >> 5;              // ktile = 32 k

    {   // prologue: stages 0,1
        #pragma unroll
        for (int i = 0; i < 4; ++i) { cp16(aoff[i], Ag + i * a32); cp16(boff[i], Wg + i * w32); }
        asm volatile("cp.async.commit_group;" ::: "memory");
        if (NT > 1) {
            #pragma unroll
            for (int i = 0; i < 4; ++i) { cp16(aoff[i] + HSTGB, Ag + i * a32 + 32); cp16(boff[i] + HSTGB, Wg + i * w32 + 32); }
        }
        asm volatile("cp.async.commit_group;" ::: "memory");
    }

    int s = 0;
    for (int kt = 0; kt < NT; ++kt) {
        if (kt + 2 < NT) {
            int s2 = s + 2; if (s2 >= STAGES) s2 -= STAGES;
            const unsigned d = (unsigned)(s2 * HSTGB);
            const int kb = (kt + 2) * 32;
            #pragma unroll
            for (int i = 0; i < 4; ++i) { cp16(aoff[i] + d, Ag + i * a32 + kb); cp16(boff[i] + d, Wg + i * w32 + kb); }
        }
        asm volatile("cp.async.commit_group;" ::: "memory");
        asm volatile("cp.async.wait_group 2;" ::: "memory");
        __syncthreads();

        const __half* As_ = (const __half*)(smc + s * HSTGB);
        const __half* Bs_ = (const __half*)(smc + HBOFFB + s * HSTGB);

        #pragma unroll
        for (int ks = 0; ks < 32; ks += 16) {
            unsigned af[4][4], bf[8][2];
            #pragma unroll
            for (int mi = 0; mi < 4; ++mi) {
                const int rb = wm * 64 + mi * 16;
                af[mi][0] = *(const unsigned*)&As_[(rb + g) * PITCHH + ks + 2 * q];
                af[mi][1] = *(const unsigned*)&As_[(rb + g + 8) * PITCHH + ks + 2 * q];
                af[mi][2] = *(const unsigned*)&As_[(rb + g) * PITCHH + ks + 2 * q + 8];
                af[mi][3] = *(const unsigned*)&As_[(rb + g + 8) * PITCHH + ks + 2 * q + 8];
            }
            #pragma unroll
            for (int ni = 0; ni < 8; ++ni) {
                const int cb = wn * 64 + ni * 8;
                bf[ni][0] = *(const unsigned*)&Bs_[(cb + g) * PITCHH + ks + 2 * q];
                bf[ni][1] = *(const unsigned*)&Bs_[(cb + g) * PITCHH + ks + 2 * q + 8];
            }
            #pragma unroll
            for (int mi = 0; mi < 4; ++mi)
                #pragma unroll
                for (int ni = 0; ni < 8; ++ni)
                    mma_f16(acc[mi][ni], af[mi][0], af[mi][1], af[mi][2], af[mi][3],
                            bf[ni][0], bf[ni][1]);
        }
        ++s; if (s == STAGES) s = 0;
    }

    if (DINV) {
        if (wn == 1 && q == 0) {
            #pragma unroll
            for (int mi = 0; mi < 4; ++mi) {
                Ds[wm * 64 + mi * 16 + g]     = acc[mi][0][0];
                Ds[wm * 64 + mi * 16 + g + 8] = acc[mi][0][2];
            }
        }
        __syncthreads();
    }

    #pragma unroll
    for (int mi = 0; mi < 4; ++mi) {
        const int r_ = wm * 64 + mi * 16 + g;
        float sc0 = 1.f, sc1 = 1.f;
        if (DINV) { sc0 = 1.f / Ds[r_]; sc1 = 1.f / Ds[r_ + 8]; }
        #pragma unroll
        for (int ni = 0; ni < 8; ++ni) {
            const int crel = wn * 64 + ni * 8 + (q << 1);
            if (crel < nvalid) {
                float2 v0 = make_float2(acc[mi][ni][0], acc[mi][ni][1]);
                float2 v1 = make_float2(acc[mi][ni][2], acc[mi][ni][3]);
                if (BIAS) {
                    v0.x += bias[crel]; v0.y += bias[crel + 1];
                    v1.x += bias[crel]; v1.y += bias[crel + 1];
                }
                if (DINV) {
                    v0.x *= sc0; v0.y *= sc0;
                    v1.x *= sc1; v1.y *= sc1;
                }
                if (Ch) {
                    *(__half2*)&Ch[(size_t)r_ * ldc + crel]       = __floats2half2_rn(v0.x, v0.y);
                    *(__half2*)&Ch[(size_t)(r_ + 8) * ldc + crel] = __floats2half2_rn(v1.x, v1.y);
                } else {
                    if (RNAF) {
                        v0.x = rna_tf32(v0.x); v0.y = rna_tf32(v0.y);
                        v1.x = rna_tf32(v1.x); v1.y = rna_tf32(v1.y);
                    }
                    *(float2*)&Cf[(size_t)r_ * ldc + crel]       = v0;
                    *(float2*)&Cf[(size_t)(r_ + 8) * ldc + crel] = v1;
                }
            }
        }
    }

    if (maxout) {
        float mx = -CUDART_INF_F;
        #pragma unroll
        for (int mi = 0; mi < 4; ++mi)
            #pragma unroll
            for (int ni = 0; ni < 8; ++ni)
                #pragma unroll
                for (int e = 0; e < 4; ++e) {
                    int crel = wn * 64 + ni * 8 + (q << 1) + (e & 1);
                    if (crel < maxcols) mx = fmaxf(mx, acc[mi][ni][e]);
                }
        #pragma unroll
        for (int o = 16; o > 0; o >>= 1)
            mx = fmaxf(mx, __shfl_xor_sync(0xffffffffu, mx, o));
        if (lid == 0) mred[wid] = mx;
        __syncthreads();
        if (tid == 0) {
            float bm = fmaxf(fmaxf(mred[0], mred[1]), fmaxf(mred[2], mred[3]));
            atomicMaxFloat(&maxout[bhidx], bm);
        }
    }
}

// ---------------- wrappers (128 threads) --------------------------------------------
__global__ void __launch_bounds__(128, 2) qkv_h() {
    const int z = blockIdx.z;
    const __half* W = g_wh + (size_t)z * DIMM * DIMM;
    const int row0 = blockIdx.y * 128, col0 = blockIdx.x * 128;
    if (z < 2) {
        __half* C = (z == 0) ? g_qh : g_kh;
        mma_core_h<false, false, false>(g_xh + (size_t)row0 * DIMM, DIMM,
                        W + (size_t)col0 * DIMM, DIMM,
                        C + (size_t)row0 * DIMM + col0, nullptr, DIMM, DIMM, 128,
                        nullptr, nullptr, 0, 0);
    } else {
        mma_core_h<false, false, true>(g_xh + (size_t)row0 * DIMM, DIMM,
                        W + (size_t)col0 * DIMM, DIMM,
                        nullptr, g_v + (size_t)row0 * DIMM + col0, DIMM, DIMM, 128,
                        nullptr, nullptr, 0, 0);
    }
}

__global__ void __launch_bounds__(128, 2) final_h(const float* __restrict__ bo,
                                                  float* __restrict__ out) {
    const int row0 = blockIdx.y * 128, col0 = blockIdx.x * 128;
    mma_core_h<true, false, false>(g_attnh + (size_t)row0 * DIMM, DIMM,
                   g_wh + 3 * (size_t)DIMM * DIMM + (size_t)col0 * DIMM, DIMM,
                   nullptr, out + (size_t)row0 * DIMM + col0, DIMM, DIMM, 128,
                   bo + col0, nullptr, 0, 0);
}

__global__ void __launch_bounds__(128, 2) dash_h() {
    const int z = blockIdx.z;                 // 0 = q, 1 = k
    const __half* src = z ? g_kh : g_qh;
    float* dst = z ? g_kp : g_qp;
    const int bh = blockIdx.y >> 5, nc = blockIdx.y & 31;
    const int b = bh >> 4, h = bh & 15;
    const int col0 = blockIdx.x * 128;
    const int row0 = nc * 128;
    mma_core_h<false, false, false>(src + ((size_t)(b * Nn) + row0) * DIMM + h * Dd, DIMM,
                    g_projh + (size_t)col0 * Dd, Dd,
                    nullptr, dst + ((size_t)bh * Nn + row0) * LDP + col0, LDP,
                    Dd, LDP - col0, nullptr,
                    z ? g_kmax : nullptr, Mm - col0, bh);
}

// out[b,n,h,e] = (1/D[n]) * sum_m qp[n,m] * ctxT[e,m];  D from ctxTh row 64 (= kcum)
__global__ void __launch_bounds__(128, 2) out_mma_h() {
    const int t = blockIdx.y;
    const int bh = t >> 5, nt = t & 31;
    const int b = bh >> 4, h = bh & 15;
    const int row0 = nt * 128;
    mma_core_h<false, true, false>(g_qph + ((size_t)bh * Nn + row0) * LDP, LDP,
                    g_ctxTh + (size_t)bh * 128 * LDP, LDP,
                    g_attnh + ((size_t)(b * Nn) + row0) * DIMM + h * Dd, nullptr, DIMM,
                    LDP, Dd, nullptr, nullptr, 0, 0);
}

// ---------------- ctx via tensor cores (TF32, unchanged from round 11) ----------------
#define CPA 132
#define CPB 68
#define CST 4
__global__ void __launch_bounds__(256) ctx_mma() {
    __shared__ float sa[CST * 16 * CPA];
    __shared__ float sb[CST * 16 * CPB];

    const int tid = threadIdx.x;
    const int wid = tid >> 5, lid = tid & 31;
    const int wm = wid >> 1, wn = wid & 1;      // 4m x 2n
    const int g = lid >> 2, q = lid & 3;
    const int bh = blockIdx.x, b = bh >> 4, h = bh & 15;
    const int m0 = blockIdx.y << 7;             // 0,128,256
    const int n0 = blockIdx.z << 9;             // 512-slabs

    const int ar0 = tid >> 5, ac0 = (tid & 31) << 2;
    const int ar1 = ar0 + 8;
    const int br0 = tid >> 4, bc0 = (tid & 15) << 2;

    const unsigned sab = smem_u32(sa);
    const unsigned sbb = smem_u32(sb);
    const unsigned a0off = sab + (unsigned)((ar0 * CPA + ac0) * 4);
    const unsigned a1off = sab + (unsigned)((ar1 * CPA + ac0) * 4);
    const unsigned boff  = sbb + (unsigned)((br0 * CPB + bc0) * 4);
    const unsigned stga = (unsigned)(16 * CPA * 4);
    const unsigned stgb = (unsigned)(16 * CPB * 4);

    const float* Ag0 = g_kp + ((size_t)bh * Nn + n0 + ar0) * LDP + m0 + ac0;
    const float* Ag1 = g_kp + ((size_t)bh * Nn + n0 + ar1) * LDP + m0 + ac0;
    const float* Bg  = g_v  + ((size_t)(b * Nn) + n0 + br0) * DIMM + h * Dd + bc0;

    float acc[2][4][4] = {};
    const int NT = 32;

    {
        cp16(a0off, Ag0); cp16(a1off, Ag1); cp16(boff, Bg);
        asm volatile("cp.async.commit_group;" ::: "memory");
        cp16(a0off + stga, Ag0 + 16 * LDP); cp16(a1off + stga, Ag1 + 16 * LDP);
        cp16(boff + stgb, Bg + 16 * DIMM);
        asm volatile("cp.async.commit_group;" ::: "memory");
    }

    int s = 0;
    for (int kt = 0; kt < NT; ++kt) {
        if (kt + 2 < NT) {
            int s2 = s + 2; if (s2 >= CST) s2 -= CST;
            const int kb = (kt + 2) * 16;
            cp16(a0off + s2 * stga, Ag0 + (size_t)kb * LDP);
            cp16(a1off + s2 * stga, Ag1 + (size_t)kb * LDP);
            cp16(boff  + s2 * stgb, Bg  + (size_t)kb * DIMM);
        }
        asm volatile("cp.async.commit_group;" ::: "memory");
        asm volatile("cp.async.wait_group 2;" ::: "memory");
        __syncthreads();

        const float* As_ = sa + s * 16 * CPA;
        const float* Bs_ = sb + s * 16 * CPB;

        #pragma unroll
        for (int ks = 0; ks < 16; ks += 8) {
            unsigned af[2][4], bf[4][2];
            #pragma unroll
            for (int mi = 0; mi < 2; ++mi) {
                const int rb = wm * 32 + mi * 16;
                af[mi][0] = __float_as_uint(As_[(ks + q) * CPA + rb + g]);
                af[mi][1] = __float_as_uint(As_[(ks + q) * CPA + rb + g + 8]);
                af[mi][2] = __float_as_uint(As_[(ks + q + 4) * CPA + rb + g]);
                af[mi][3] = __float_as_uint(As_[(ks + q + 4) * CPA + rb + g + 8]);
            }
            #pragma unroll
            for (int ni = 0; ni < 4; ++ni) {
                const int cb = wn * 32 + ni * 8;
                bf[ni][0] = __float_as_uint(Bs_[(ks + q) * CPB + cb + g]);
                bf[ni][1] = __float_as_uint(Bs_[(ks + q + 4) * CPB + cb + g]);
            }
            #pragma unroll
            for (int mi = 0; mi < 2; ++mi)
                #pragma unroll
                for (int ni = 0; ni < 4; ++ni)
                    mma_tf32(acc[mi][ni], af[mi][0], af[mi][1], af[mi][2], af[mi][3],
                             bf[ni][0], bf[ni][1]);
        }
        ++s; if (s == CST) s = 0;
    }
    asm volatile("cp.async.wait_group 0;" ::: "memory");

    #pragma unroll
    for (int mi = 0; mi < 2; ++mi) {
        const int mA = m0 + wm * 32 + mi * 16 + g;
        #pragma unroll
        for (int ni = 0; ni < 4; ++ni) {
            const int e0 = wn * 32 + ni * 8 + (q << 1);
            if (mA < Mm) {
                atomicAdd(&g_ctxT[((size_t)bh * 128 + e0) * LDP + mA], acc[mi][ni][0]);
                atomicAdd(&g_ctxT[((size_t)bh * 128 + e0 + 1) * LDP + mA], acc[mi][ni][1]);
            }
            if (mA + 8 < Mm) {
                atomicAdd(&g_ctxT[((size_t)bh * 128 + e0) * LDP + mA + 8], acc[mi][ni][2]);
                atomicAdd(&g_ctxT[((size_t)bh * 128 + e0 + 1) * LDP + mA + 8], acc[mi][ni][3]);
            }
        }
    }
}

// ---------------- exp_q: rowmax + diag + exp; half feature store ------------------------
__global__ void __launch_bounds__(256) expq_kernel() {
    const int warp = threadIdx.x >> 5, lane = threadIdx.x & 31;
    const int r = blockIdx.x * 8 + warp;
    const int bh = r >> 12, n = r & 4095;
    const int b = bh >> 4, h = bh & 15;

    const __half* qrow = g_qh + ((size_t)(b * Nn) + n) * DIMM + h * Dd;
    float q0 = __half2float(qrow[lane]), q1 = __half2float(qrow[lane + 32]);
    float s = q0 * q0 + q1 * q1;
    #pragma unroll
    for (int o = 16; o > 0; o >>= 1) s += __shfl_xor_sync(0xffffffffu, s, o);
    const float diag = 0.0625f * s;

    const float* row = g_qp + (size_t)r * LDP;
    __half* orow = g_qph + (size_t)r * LDP;
    float d[9];
    float mx = -CUDART_INF_F;
    #pragma unroll
    for (int i = 0; i < 9; ++i) {
        int m = lane + i * 32;
        d[i] = row[m];
        if (m < Mm) mx = fmaxf(mx, d[i]);
    }
    #pragma unroll
    for (int o = 16; o > 0; o >>= 1) mx = fmaxf(mx, __shfl_xor_sync(0xffffffffu, mx, o));
    const float sub = diag + mx;
    #pragma unroll
    for (int i = 0; i < 9; ++i) {
        int m = lane + i * 32;
        orow[m] = (m < Mm) ? __float2half_rn(RATIO * (fexp(d[i] - sub) + EPSV)) : __half(0.f);
    }
}

// ---------------- exp_k + fused k_cumsum (kp stays fp32 tf32-rounded) -------------------
__global__ void __launch_bounds__(256) expk_kernel() {
    __shared__ float sums[LDP];
    const int tid = threadIdx.x;
    for (int i = tid; i < LDP; i += 256) sums[i] = 0.f;
    __syncthreads();

    const int warp = tid >> 5, lane = tid & 31;
    const int r = blockIdx.x * 8 + warp;
    const int bh = r >> 12, n = r & 4095;
    const int b = bh >> 4, h = bh & 15;

    const __half* krow = g_kh + ((size_t)(b * Nn) + n) * DIMM + h * Dd;
    float k0 = __half2float(krow[lane]), k1 = __half2float(krow[lane + 32]);
    float s = k0 * k0 + k1 * k1;
    #pragma unroll
    for (int o = 16; o > 0; o >>= 1) s += __shfl_xor_sync(0xffffffffu, s, o);
    const float sub = 0.0625f * s + g_kmax[bh];

    float* row = g_kp + (size_t)r * LDP;
    #pragma unroll
    for (int i = 0; i < 9; ++i) {
        int m = lane + i * 32;
        float v = (m < Mm) ? rna_tf32(RATIO * (fexp(row[m] - sub) + EPSV)) : 0.f;
        row[m] = v;
        atomicAdd(&sums[m], v);
    }
    __syncthreads();
    for (int i = tid; i < LDP; i += 256)
        atomicAdd(&g_kcum[bh * LDP + i], sums[i]);
}

// ---------------- launcher --------------------------------------------------------------
extern "C" void kernel_launch(void* const* d_in, const int* in_sizes, int n_in,
                              void* d_out, int out_size) {
    const float* x    = (const float*)d_in[0];
    const float* Wq   = (const float*)d_in[1];
    const float* Wk   = (const float*)d_in[2];
    const float* Wv   = (const float*)d_in[3];
    const float* Wo   = (const float*)d_in[4];
    const float* bo   = (const float*)d_in[5];
    const float* proj = (const float*)d_in[6];
    float* out = (float*)d_out;

    static int attr_done = 0;
    if (!attr_done) {
        cudaFuncSetAttribute(qkv_h,     cudaFuncAttributeMaxDynamicSharedMemorySize, CORE_SMEM);
        cudaFuncSetAttribute(final_h,   cudaFuncAttributeMaxDynamicSharedMemorySize, CORE_SMEM);
        cudaFuncSetAttribute(dash_h,    cudaFuncAttributeMaxDynamicSharedMemorySize, CORE_SMEM);
        cudaFuncSetAttribute(out_mma_h, cudaFuncAttributeMaxDynamicSharedMemorySize, CORE_SMEM);
        attr_done = 1;
    }

    prep_small<<<((unsigned)((size_t)BHh * Dd * LDP + 255) / 256), 256>>>(proj);
    round_xh<<<ROWS * DIMM / 4 / 256, 256>>>(x);
    round_wh<<<dim3(DIMM * DIMM / 4 / 256, 4), 256>>>(Wq, Wk, Wv, Wo);

    qkv_h<<<dim3(DIMM / 128, ROWS / 128, 3), 128, CORE_SMEM>>>();

    dash_h<<<dim3(3, BHh * 32, 2), 128, CORE_SMEM>>>();

    expq_kernel<<<BHh * Nn / 8, 256>>>();
    expk_kernel<<<BHh * Nn / 8, 256>>>();

    ctx_mma<<<dim3(BHh, 3, 8), 256>>>();
    fix_kernel<<<(unsigned)(((size_t)BHh * 65 * LDP + 255) / 256), 256>>>();

    out_mma_h<<<dim3(1, BHh * 32), 128, CORE_SMEM>>>();

    final_h<<<dim3(DIMM / 128, ROWS / 128), 128, CORE_SMEM>>>(bo, out);
}

// round 13
// speedup vs baseline: 2.1090x; 1.0870x over previous
#include <cuda_runtime.h>
#include <cuda_fp16.h>
#include <math.h>
#include <math_constants.h>

// Problem constants
#define Bz   2
#define Nn   4096
#define DIMM 1024
#define Hh   16
#define Dd   64
#define Mm   266
#define BHh  (Bz*Hh)        // 32
#define ROWS (Bz*Nn)        // 8192
#define LDP  288            // padded feature row length

#define NORMALIZER 0.35355339059327373f   // 64^-0.25
#define RATIO      0.061313933948496576f  // 266^-0.5
#define EPSV       1e-4f
#define LOG2E      1.4426950408889634f

#define STAGES  4
#define PITCHH  40                                 // halfs per smem row
#define HSTGB   (128*PITCHH*2)                     // 10240 B per operand stage
#define HBOFFB  (STAGES*HSTGB)                     // 40960 B: B-operand region offset
#define CORE_SMEM (STAGES*HSTGB*2)                 // 81920 B

// ---------------- scratch -------------------------------------------------------
__device__ __half g_xh[ROWS*DIMM];
__device__ __half g_wh[4*(size_t)DIMM*DIMM];
__device__ __half g_projh[384*Dd];
__device__ __half g_qh[ROWS*DIMM];
__device__ __half g_kh[ROWS*DIMM];
__device__ float  g_v [ROWS*DIMM];                 // fp32 (tf32-rounded) v for ctx
__device__ __half g_attnh[ROWS*DIMM];
__device__ float  g_qp[(size_t)BHh*Nn*LDP + 128];  // fp32 raw q dash
__device__ float  g_kp[(size_t)BHh*Nn*LDP + 128];  // fp32 dash -> tf32 kp (ctx A)
__device__ __half g_qph[(size_t)BHh*Nn*LDP];       // fp16 qp features (out A)
__device__ float  g_kmax[BHh];
__device__ float  g_kcum[BHh*LDP];
__device__ float  g_ctxT[(size_t)BHh*128*LDP];     // fp32 atomics target [e][m]
__device__ __half g_ctxTh[(size_t)BHh*128*LDP];    // fp16 [e][m]; row 64 = kcum; 65..127 stay 0

// ---------------- helpers -------------------------------------------------------
__device__ __forceinline__ unsigned smem_u32(const void* p) {
    unsigned a;
    asm("{ .reg .u64 t; cvta.to.shared.u64 t, %1; cvt.u32.u64 %0, t; }" : "=r"(a) : "l"(p));
    return a;
}
__device__ __forceinline__ float rna_tf32(float v) {
    unsigned u;
    asm("cvt.rna.tf32.f32 %0, %1;" : "=r"(u) : "f"(v));
    return __uint_as_float(u);
}
__device__ __forceinline__ float fexp(float x) {
    float y;
    asm("ex2.approx.f32 %0, %1;" : "=f"(y) : "f"(x * LOG2E));
    return y;
}
__device__ __forceinline__ void cp16(unsigned dst, const void* src) {
    asm volatile("cp.async.ca.shared.global [%0], [%1], 16;" :: "r"(dst), "l"(src));
}
__device__ __forceinline__ void ldsm4(unsigned& r0, unsigned& r1, unsigned& r2, unsigned& r3,
                                      unsigned addr) {
    asm volatile("ldmatrix.sync.aligned.m8n8.x4.shared.b16 {%0,%1,%2,%3}, [%4];"
        : "=r"(r0), "=r"(r1), "=r"(r2), "=r"(r3) : "r"(addr));
}
__device__ __forceinline__ void mma_f16(float c[4],
                                        unsigned a0, unsigned a1, unsigned a2, unsigned a3,
                                        unsigned b0, unsigned b1) {
    asm volatile(
        "mma.sync.aligned.m16n8k16.row.col.f32.f16.f16.f32 "
        "{%0,%1,%2,%3}, {%4,%5,%6,%7}, {%8,%9}, {%0,%1,%2,%3};"
        : "+f"(c[0]), "+f"(c[1]), "+f"(c[2]), "+f"(c[3])
        : "r"(a0), "r"(a1), "r"(a2), "r"(a3), "r"(b0), "r"(b1));
}
__device__ __forceinline__ void mma_tf32(float c[4],
                                         unsigned a0, unsigned a1, unsigned a2, unsigned a3,
                                         unsigned b0, unsigned b1) {
    asm volatile(
        "mma.sync.aligned.m16n8k8.row.col.f32.tf32.tf32.f32 "
        "{%0,%1,%2,%3}, {%4,%5,%6,%7}, {%8,%9}, {%0,%1,%2,%3};"
        : "+f"(c[0]), "+f"(c[1]), "+f"(c[2]), "+f"(c[3])
        : "r"(a0), "r"(a1), "r"(a2), "r"(a3), "r"(b0), "r"(b1));
}
__device__ __forceinline__ void atomicMaxFloat(float* addr, float val) {
    int* a = (int*)addr;
    int old = *a;
    while (__int_as_float(old) < val) {
        int assumed = old;
        old = atomicCAS(a, assumed, __float_as_int(val));
        if (old == assumed) break;
    }
}

// ---------------- prep / conversion passes -----------------------------------------
__global__ void prep_small(const float* __restrict__ proj) {
    size_t t = (size_t)blockIdx.x * blockDim.x + threadIdx.x;
    if (t < BHh) g_kmax[t] = -CUDART_INF_F;
    if (t < BHh * LDP) g_kcum[t] = 0.f;
    if (t < 384 * Dd) {
        int m = (int)(t >> 6);
        g_projh[t] = (m < Mm) ? __float2half_rn(proj[t] * NORMALIZER) : __half(0.f);
    }
    if (t < (size_t)BHh * Dd * LDP) {
        size_t bh = t / (Dd * LDP);
        size_t rem = t - bh * (Dd * LDP);
        g_ctxT[bh * 128 * LDP + rem] = 0.f;
    }
}
__global__ void round_xh(const float* __restrict__ in) {
    int i = blockIdx.x * blockDim.x + threadIdx.x;
    float4 v = ((const float4*)in)[i];
    ((__half2*)g_xh)[2*i]   = __floats2half2_rn(v.x, v.y);
    ((__half2*)g_xh)[2*i+1] = __floats2half2_rn(v.z, v.w);
}
__global__ void round_wh(const float* __restrict__ w0, const float* __restrict__ w1,
                         const float* __restrict__ w2, const float* __restrict__ w3) {
    int z = blockIdx.y;
    const float* w = (z == 0) ? w0 : (z == 1) ? w1 : (z == 2) ? w2 : w3;
    int i = blockIdx.x * blockDim.x + threadIdx.x;
    float4 v = ((const float4*)w)[i];
    __half2* o = (__half2*)(g_wh + (size_t)z * DIMM * DIMM);
    o[2*i]   = __floats2half2_rn(v.x, v.y);
    o[2*i+1] = __floats2half2_rn(v.z, v.w);
}
__global__ void fix_kernel() {
    size_t t = (size_t)blockIdx.x * 256 + threadIdx.x;
    const size_t per_bh = (size_t)65 * LDP;
    if (t >= (size_t)BHh * per_bh) return;
    size_t bh = t / per_bh;
    size_t rem = t - bh * per_bh;
    int row = (int)(rem / LDP), m = (int)(rem - (size_t)row * LDP);
    float v = (row < 64) ? g_ctxT[(bh * 128 + row) * LDP + m] : g_kcum[bh * LDP + m];
    g_ctxTh[(bh * 128 + row) * LDP + m] = __float2half_rn(v);
}

// ---------------- fp16 mma core: 128x128 CTA, 4 warps 64x64, ldmatrix fragments -------
template<bool BIAS, bool DINV, bool RNAF>
__device__ __forceinline__ void mma_core_h(const __half* __restrict__ A, int lda,
                                           const __half* __restrict__ W, int ldb,
                                           __half* __restrict__ Ch,
                                           float* __restrict__ Cf, int ldc,
                                           int K, int nvalid,
                                           const float* __restrict__ bias,
                                           float* __restrict__ maxout, int maxcols, int bhidx) {
    extern __shared__ char smc[];
    __shared__ float mred[4];
    __shared__ float Ds[128];

    const int tid = threadIdx.x;        // 0..127
    const int wid = tid >> 5, lid = tid & 31;
    const int wm = wid >> 1;
    const int wn = wid & 1;
    const int g = lid >> 2, q = lid & 3;

    // ldmatrix per-lane address pieces
    const int la  = lid & 15;                    // A row within 16
    const int lka = (lid >> 4) << 3;             // A k offset 0/8
    const int lb  = (lid & 7) + ((lid >> 4) << 3);   // B row within 16
    const int lkb = ((lid >> 3) & 1) << 3;       // B k offset 0/8

    const int lr = tid >> 2;            // loader row 0..31
    const int lc0 = (tid & 3) << 3;

    const unsigned sbase = smem_u32(smc);
    unsigned aoff[4], boff[4];
    #pragma unroll
    for (int i = 0; i < 4; ++i) {
        aoff[i] = sbase + (unsigned)(((lr + 32 * i) * PITCHH + lc0) * 2);
        boff[i] = aoff[i] + (unsigned)HBOFFB;
    }

    const __half* Ag = A + (size_t)lr * lda + lc0;
    const __half* Wg = W + (size_t)lr * ldb + lc0;
    const size_t a32 = (size_t)32 * lda;
    const size_t w32 = (size_t)32 * ldb;

    float acc[4][8][4] = {};
    const int NT = K >> 5;

    {   // prologue: stages 0,1
        #pragma unroll
        for (int i = 0; i < 4; ++i) { cp16(aoff[i], Ag + i * a32); cp16(boff[i], Wg + i * w32); }
        asm volatile("cp.async.commit_group;" ::: "memory");
        if (NT > 1) {
            #pragma unroll
            for (int i = 0; i < 4; ++i) { cp16(aoff[i] + HSTGB, Ag + i * a32 + 32); cp16(boff[i] + HSTGB, Wg + i * w32 + 32); }
        }
        asm volatile("cp.async.commit_group;" ::: "memory");
    }

    int s = 0;
    for (int kt = 0; kt < NT; ++kt) {
        if (kt + 2 < NT) {
            int s2 = s + 2; if (s2 >= STAGES) s2 -= STAGES;
            const unsigned d = (unsigned)(s2 * HSTGB);
            const int kb = (kt + 2) * 32;
            #pragma unroll
            for (int i = 0; i < 4; ++i) { cp16(aoff[i] + d, Ag + i * a32 + kb); cp16(boff[i] + d, Wg + i * w32 + kb); }
        }
        asm volatile("cp.async.commit_group;" ::: "memory");
        asm volatile("cp.async.wait_group 2;" ::: "memory");
        __syncthreads();

        const unsigned sA = sbase + (unsigned)(s * HSTGB);
        const unsigned sB = sA + (unsigned)HBOFFB;

        #pragma unroll
        for (int ks = 0; ks < 32; ks += 16) {
            unsigned af[4][4], bf[8][2];
            #pragma unroll
            for (int mi = 0; mi < 4; ++mi) {
                const int rb = wm * 64 + mi * 16;
                unsigned addr = sA + (unsigned)((((rb + la) * PITCHH) + ks + lka) * 2);
                ldsm4(af[mi][0], af[mi][1], af[mi][2], af[mi][3], addr);
            }
            #pragma unroll
            for (int ni = 0; ni < 8; ni += 2) {
                const int cb = wn * 64 + ni * 8;
                unsigned addr = sB + (unsigned)((((cb + lb) * PITCHH) + ks + lkb) * 2);
                ldsm4(bf[ni][0], bf[ni][1], bf[ni + 1][0], bf[ni + 1][1], addr);
            }
            #pragma unroll
            for (int mi = 0; mi < 4; ++mi)
                #pragma unroll
                for (int ni = 0; ni < 8; ++ni)
                    mma_f16(acc[mi][ni], af[mi][0], af[mi][1], af[mi][2], af[mi][3],
                            bf[ni][0], bf[ni][1]);
        }
        ++s; if (s == STAGES) s = 0;
    }

    if (DINV) {
        if (wn == 1 && q == 0) {
            #pragma unroll
            for (int mi = 0; mi < 4; ++mi) {
                Ds[wm * 64 + mi * 16 + g]     = acc[mi][0][0];
                Ds[wm * 64 + mi * 16 + g + 8] = acc[mi][0][2];
            }
        }
        __syncthreads();
    }

    #pragma unroll
    for (int mi = 0; mi < 4; ++mi) {
        const int r_ = wm * 64 + mi * 16 + g;
        float sc0 = 1.f, sc1 = 1.f;
        if (DINV) { sc0 = 1.f / Ds[r_]; sc1 = 1.f / Ds[r_ + 8]; }
        #pragma unroll
        for (int ni = 0; ni < 8; ++ni) {
            const int crel = wn * 64 + ni * 8 + (q << 1);
            if (crel < nvalid) {
                float2 v0 = make_float2(acc[mi][ni][0], acc[mi][ni][1]);
                float2 v1 = make_float2(acc[mi][ni][2], acc[mi][ni][3]);
                if (BIAS) {
                    v0.x += bias[crel]; v0.y += bias[crel + 1];
                    v1.x += bias[crel]; v1.y += bias[crel + 1];
                }
                if (DINV) {
                    v0.x *= sc0; v0.y *= sc0;
                    v1.x *= sc1; v1.y *= sc1;
                }
                if (Ch) {
                    *(__half2*)&Ch[(size_t)r_ * ldc + crel]       = __floats2half2_rn(v0.x, v0.y);
                    *(__half2*)&Ch[(size_t)(r_ + 8) * ldc + crel] = __floats2half2_rn(v1.x, v1.y);
                } else {
                    if (RNAF) {
                        v0.x = rna_tf32(v0.x); v0.y = rna_tf32(v0.y);
                        v1.x = rna_tf32(v1.x); v1.y = rna_tf32(v1.y);
                    }
                    *(float2*)&Cf[(size_t)r_ * ldc + crel]       = v0;
                    *(float2*)&Cf[(size_t)(r_ + 8) * ldc + crel] = v1;
                }
            }
        }
    }

    if (maxout) {
        float mx = -CUDART_INF_F;
        #pragma unroll
        for (int mi = 0; mi < 4; ++mi)
            #pragma unroll
            for (int ni = 0; ni < 8; ++ni)
                #pragma unroll
                for (int e = 0; e < 4; ++e) {
                    int crel = wn * 64 + ni * 8 + (q << 1) + (e & 1);
                    if (crel < maxcols) mx = fmaxf(mx, acc[mi][ni][e]);
                }
        #pragma unroll
        for (int o = 16; o > 0; o >>= 1)
            mx = fmaxf(mx, __shfl_xor_sync(0xffffffffu, mx, o));
        if (lid == 0) mred[wid] = mx;
        __syncthreads();
        if (tid == 0) {
            float bm = fmaxf(fmaxf(mred[0], mred[1]), fmaxf(mred[2], mred[3]));
            atomicMaxFloat(&maxout[bhidx], bm);
        }
    }
}

// ---------------- wrappers (128 threads) --------------------------------------------
__global__ void __launch_bounds__(128, 2) qkv_h() {
    const int z = blockIdx.z;
    const __half* W = g_wh + (size_t)z * DIMM * DIMM;
    const int row0 = blockIdx.y * 128, col0 = blockIdx.x * 128;
    if (z < 2) {
        __half* C = (z == 0) ? g_qh : g_kh;
        mma_core_h<false, false, false>(g_xh + (size_t)row0 * DIMM, DIMM,
                        W + (size_t)col0 * DIMM, DIMM,
                        C + (size_t)row0 * DIMM + col0, nullptr, DIMM, DIMM, 128,
                        nullptr, nullptr, 0, 0);
    } else {
        mma_core_h<false, false, true>(g_xh + (size_t)row0 * DIMM, DIMM,
                        W + (size_t)col0 * DIMM, DIMM,
                        nullptr, g_v + (size_t)row0 * DIMM + col0, DIMM, DIMM, 128,
                        nullptr, nullptr, 0, 0);
    }
}

__global__ void __launch_bounds__(128, 2) final_h(const float* __restrict__ bo,
                                                  float* __restrict__ out) {
    const int row0 = blockIdx.y * 128, col0 = blockIdx.x * 128;
    mma_core_h<true, false, false>(g_attnh + (size_t)row0 * DIMM, DIMM,
                   g_wh + 3 * (size_t)DIMM * DIMM + (size_t)col0 * DIMM, DIMM,
                   nullptr, out + (size_t)row0 * DIMM + col0, DIMM, DIMM, 128,
                   bo + col0, nullptr, 0, 0);
}

__global__ void __launch_bounds__(128, 2) dash_h() {
    const int z = blockIdx.z;                 // 0 = q, 1 = k
    const __half* src = z ? g_kh : g_qh;
    float* dst = z ? g_kp : g_qp;
    const int bh = blockIdx.y >> 5, nc = blockIdx.y & 31;
    const int b = bh >> 4, h = bh & 15;
    const int col0 = blockIdx.x * 128;
    const int row0 = nc * 128;
    mma_core_h<false, false, false>(src + ((size_t)(b * Nn) + row0) * DIMM + h * Dd, DIMM,
                    g_projh + (size_t)col0 * Dd, Dd,
                    nullptr, dst + ((size_t)bh * Nn + row0) * LDP + col0, LDP,
                    Dd, LDP - col0, nullptr,
                    z ? g_kmax : nullptr, Mm - col0, bh);
}

__global__ void __launch_bounds__(128, 2) out_mma_h() {
    const int t = blockIdx.y;
    const int bh = t >> 5, nt = t & 31;
    const int b = bh >> 4, h = bh & 15;
    const int row0 = nt * 128;
    mma_core_h<false, true, false>(g_qph + ((size_t)bh * Nn + row0) * LDP, LDP,
                    g_ctxTh + (size_t)bh * 128 * LDP, LDP,
                    g_attnh + ((size_t)(b * Nn) + row0) * DIMM + h * Dd, nullptr, DIMM,
                    LDP, Dd, nullptr, nullptr, 0, 0);
}

// ---------------- ctx via tensor cores (TF32, unchanged) ------------------------------
#define CPA 132
#define CPB 68
#define CST 4
__global__ void __launch_bounds__(256) ctx_mma() {
    __shared__ float sa[CST * 16 * CPA];
    __shared__ float sb[CST * 16 * CPB];

    const int tid = threadIdx.x;
    const int wid = tid >> 5, lid = tid & 31;
    const int wm = wid >> 1, wn = wid & 1;
    const int g = lid >> 2, q = lid & 3;
    const int bh = blockIdx.x, b = bh >> 4, h = bh & 15;
    const int m0 = blockIdx.y << 7;
    const int n0 = blockIdx.z << 9;

    const int ar0 = tid >> 5, ac0 = (tid & 31) << 2;
    const int ar1 = ar0 + 8;
    const int br0 = tid >> 4, bc0 = (tid & 15) << 2;

    const unsigned sab = smem_u32(sa);
    const unsigned sbb = smem_u32(sb);
    const unsigned a0off = sab + (unsigned)((ar0 * CPA + ac0) * 4);
    const unsigned a1off = sab + (unsigned)((ar1 * CPA + ac0) * 4);
    const unsigned boff  = sbb + (unsigned)((br0 * CPB + bc0) * 4);
    const unsigned stga = (unsigned)(16 * CPA * 4);
    const unsigned stgb = (unsigned)(16 * CPB * 4);

    const float* Ag0 = g_kp + ((size_t)bh * Nn + n0 + ar0) * LDP + m0 + ac0;
    const float* Ag1 = g_kp + ((size_t)bh * Nn + n0 + ar1) * LDP + m0 + ac0;
    const float* Bg  = g_v  + ((size_t)(b * Nn) + n0 + br0) * DIMM + h * Dd + bc0;

    float acc[2][4][4] = {};
    const int NT = 32;

    {
        cp16(a0off, Ag0); cp16(a1off, Ag1); cp16(boff, Bg);
        asm volatile("cp.async.commit_group;" ::: "memory");
        cp16(a0off + stga, Ag0 + 16 * LDP); cp16(a1off + stga, Ag1 + 16 * LDP);
        cp16(boff + stgb, Bg + 16 * DIMM);
        asm volatile("cp.async.commit_group;" ::: "memory");
    }

    int s = 0;
    for (int kt = 0; kt < NT; ++kt) {
        if (kt + 2 < NT) {
            int s2 = s + 2; if (s2 >= CST) s2 -= CST;
            const int kb = (kt + 2) * 16;
            cp16(a0off + s2 * stga, Ag0 + (size_t)kb * LDP);
            cp16(a1off + s2 * stga, Ag1 + (size_t)kb * LDP);
            cp16(boff  + s2 * stgb, Bg  + (size_t)kb * DIMM);
        }
        asm volatile("cp.async.commit_group;" ::: "memory");
        asm volatile("cp.async.wait_group 2;" ::: "memory");
        __syncthreads();

        const float* As_ = sa + s * 16 * CPA;
        const float* Bs_ = sb + s * 16 * CPB;

        #pragma unroll
        for (int ks = 0; ks < 16; ks += 8) {
            unsigned af[2][4], bf[4][2];
            #pragma unroll
            for (int mi = 0; mi < 2; ++mi) {
                const int rb = wm * 32 + mi * 16;
                af[mi][0] = __float_as_uint(As_[(ks + q) * CPA + rb + g]);
                af[mi][1] = __float_as_uint(As_[(ks + q) * CPA + rb + g + 8]);
                af[mi][2] = __float_as_uint(As_[(ks + q + 4) * CPA + rb + g]);
                af[mi][3] = __float_as_uint(As_[(ks + q + 4) * CPA + rb + g + 8]);
            }
            #pragma unroll
            for (int ni = 0; ni < 4; ++ni) {
                const int cb = wn * 32 + ni * 8;
                bf[ni][0] = __float_as_uint(Bs_[(ks + q) * CPB + cb + g]);
                bf[ni][1] = __float_as_uint(Bs_[(ks + q + 4) * CPB + cb + g]);
            }
            #pragma unroll
            for (int mi = 0; mi < 2; ++mi)
                #pragma unroll
                for (int ni = 0; ni < 4; ++ni)
                    mma_tf32(acc[mi][ni], af[mi][0], af[mi][1], af[mi][2], af[mi][3],
                             bf[ni][0], bf[ni][1]);
        }
        ++s; if (s == CST) s = 0;
    }
    asm volatile("cp.async.wait_group 0;" ::: "memory");

    #pragma unroll
    for (int mi = 0; mi < 2; ++mi) {
        const int mA = m0 + wm * 32 + mi * 16 + g;
        #pragma unroll
        for (int ni = 0; ni < 4; ++ni) {
            const int e0 = wn * 32 + ni * 8 + (q << 1);
            if (mA < Mm) {
                atomicAdd(&g_ctxT[((size_t)bh * 128 + e0) * LDP + mA], acc[mi][ni][0]);
                atomicAdd(&g_ctxT[((size_t)bh * 128 + e0 + 1) * LDP + mA], acc[mi][ni][1]);
            }
            if (mA + 8 < Mm) {
                atomicAdd(&g_ctxT[((size_t)bh * 128 + e0) * LDP + mA + 8], acc[mi][ni][2]);
                atomicAdd(&g_ctxT[((size_t)bh * 128 + e0 + 1) * LDP + mA + 8], acc[mi][ni][3]);
            }
        }
    }
}

// ---------------- exp_q ------------------------------------------------------------
__global__ void __launch_bounds__(256) expq_kernel() {
    const int warp = threadIdx.x >> 5, lane = threadIdx.x & 31;
    const int r = blockIdx.x * 8 + warp;
    const int bh = r >> 12, n = r & 4095;
    const int b = bh >> 4, h = bh & 15;

    const __half* qrow = g_qh + ((size_t)(b * Nn) + n) * DIMM + h * Dd;
    float q0 = __half2float(qrow[lane]), q1 = __half2float(qrow[lane + 32]);
    float s = q0 * q0 + q1 * q1;
    #pragma unroll
    for (int o = 16; o > 0; o >>= 1) s += __shfl_xor_sync(0xffffffffu, s, o);
    const float diag = 0.0625f * s;

    const float* row = g_qp + (size_t)r * LDP;
    __half* orow = g_qph + (size_t)r * LDP;
    float d[9];
    float mx = -CUDART_INF_F;
    #pragma unroll
    for (int i = 0; i < 9; ++i) {
        int m = lane + i * 32;
        d[i] = row[m];
        if (m < Mm) mx = fmaxf(mx, d[i]);
    }
    #pragma unroll
    for (int o = 16; o > 0; o >>= 1) mx = fmaxf(mx, __shfl_xor_sync(0xffffffffu, mx, o));
    const float sub = diag + mx;
    #pragma unroll
    for (int i = 0; i < 9; ++i) {
        int m = lane + i * 32;
        orow[m] = (m < Mm) ? __float2half_rn(RATIO * (fexp(d[i] - sub) + EPSV)) : __half(0.f);
    }
}

// ---------------- exp_k + fused k_cumsum ----------------------------------------------
__global__ void __launch_bounds__(256) expk_kernel() {
    __shared__ float sums[LDP];
    const int tid = threadIdx.x;
    for (int i = tid; i < LDP; i += 256) sums[i] = 0.f;
    __syncthreads();

    const int warp = tid >> 5, lane = tid & 31;
    const int r = blockIdx.x * 8 + warp;
    const int bh = r >> 12, n = r & 4095;
    const int b = bh >> 4, h = bh & 15;

    const __half* krow = g_kh + ((size_t)(b * Nn) + n) * DIMM + h * Dd;
    float k0 = __half2float(krow[lane]), k1 = __half2float(krow[lane + 32]);
    float s = k0 * k0 + k1 * k1;
    #pragma unroll
    for (int o = 16; o > 0; o >>= 1) s += __shfl_xor_sync(0xffffffffu, s, o);
    const float sub = 0.0625f * s + g_kmax[bh];

    float* row = g_kp + (size_t)r * LDP;
    #pragma unroll
    for (int i = 0; i < 9; ++i) {
        int m = lane + i * 32;
        float v = (m < Mm) ? rna_tf32(RATIO * (fexp(row[m] - sub) + EPSV)) : 0.f;
        row[m] = v;
        atomicAdd(&sums[m], v);
    }
    __syncthreads();
    for (int i = tid; i < LDP; i += 256)
        atomicAdd(&g_kcum[bh * LDP + i], sums[i]);
}

// ---------------- launcher --------------------------------------------------------------
extern "C" void kernel_launch(void* const* d_in, const int* in_sizes, int n_in,
                              void* d_out, int out_size) {
    const float* x    = (const float*)d_in[0];
    const float* Wq   = (const float*)d_in[1];
    const float* Wk   = (const float*)d_in[2];
    const float* Wv   = (const float*)d_in[3];
    const float* Wo   = (const float*)d_in[4];
    const float* bo   = (const float*)d_in[5];
    const float* proj = (const float*)d_in[6];
    float* out = (float*)d_out;

    static int attr_done = 0;
    if (!attr_done) {
        cudaFuncSetAttribute(qkv_h,     cudaFuncAttributeMaxDynamicSharedMemorySize, CORE_SMEM);
        cudaFuncSetAttribute(final_h,   cudaFuncAttributeMaxDynamicSharedMemorySize, CORE_SMEM);
        cudaFuncSetAttribute(dash_h,    cudaFuncAttributeMaxDynamicSharedMemorySize, CORE_SMEM);
        cudaFuncSetAttribute(out_mma_h, cudaFuncAttributeMaxDynamicSharedMemorySize, CORE_SMEM);
        attr_done = 1;
    }

    prep_small<<<((unsigned)((size_t)BHh * Dd * LDP + 255) / 256), 256>>>(proj);
    round_xh<<<ROWS * DIMM / 4 / 256, 256>>>(x);
    round_wh<<<dim3(DIMM * DIMM / 4 / 256, 4), 256>>>(Wq, Wk, Wv, Wo);

    qkv_h<<<dim3(DIMM / 128, ROWS / 128, 3), 128, CORE_SMEM>>>();

    dash_h<<<dim3(3, BHh * 32, 2), 128, CORE_SMEM>>>();

    expq_kernel<<<BHh * Nn / 8, 256>>>();
    expk_kernel<<<BHh * Nn / 8, 256>>>();

    ctx_mma<<<dim3(BHh, 3, 8), 256>>>();
    fix_kernel<<<(unsigned)(((size_t)BHh * 65 * LDP + 255) / 256), 256>>>();

    out_mma_h<<<dim3(1, BHh * 32), 128, CORE_SMEM>>>();

    final_h<<<dim3(DIMM / 128, ROWS / 128), 128, CORE_SMEM>>>(bo, out);
}

// round 14
// speedup vs baseline: 2.2105x; 1.0481x over previous
#include <cuda_runtime.h>
#include <cuda_fp16.h>
#include <math.h>
#include <math_constants.h>

// Problem constants
#define Bz   2
#define Nn   4096
#define DIMM 1024
#define Hh   16
#define Dd   64
#define Mm   266
#define BHh  (Bz*Hh)        // 32
#define ROWS (Bz*Nn)        // 8192
#define LDP  288            // padded feature row length

#define NORMALIZER 0.35355339059327373f   // 64^-0.25
#define RATIO      0.061313933948496576f  // 266^-0.5
#define EPSV       1e-4f
#define LOG2E      1.4426950408889634f

#define STAGES  4
#define PITCHH  40
#define HSTGB   (128*PITCHH*2)                     // 10240 B per operand stage
#define HBOFFB  (STAGES*HSTGB)                     // 40960 B
#define CORE_SMEM (STAGES*HSTGB*2)                 // 81920 B

// ---------------- scratch -------------------------------------------------------
__device__ __half g_xh[ROWS*DIMM];
__device__ __half g_wh[4*(size_t)DIMM*DIMM];
__device__ __half g_projh[384*Dd];
__device__ __half g_qh[ROWS*DIMM];
__device__ __half g_kh[ROWS*DIMM];
__device__ float  g_v [ROWS*DIMM];                 // fp32 (tf32-rounded) v for ctx
__device__ __half g_attnh[ROWS*DIMM];
__device__ float  g_qp[(size_t)BHh*Nn*LDP + 128];
__device__ float  g_kp[(size_t)BHh*Nn*LDP + 128];
__device__ __half g_qph[(size_t)BHh*Nn*LDP];
__device__ float  g_kmax[BHh];
__device__ float  g_kcum[BHh*LDP];
__device__ float  g_ctxT[(size_t)BHh*128*LDP];
__device__ __half g_ctxTh[(size_t)BHh*128*LDP];    // row 64 = kcum; 65..127 stay 0

// ---------------- helpers -------------------------------------------------------
__device__ __forceinline__ unsigned smem_u32(const void* p) {
    unsigned a;
    asm("{ .reg .u64 t; cvta.to.shared.u64 t, %1; cvt.u32.u64 %0, t; }" : "=r"(a) : "l"(p));
    return a;
}
__device__ __forceinline__ float rna_tf32(float v) {
    unsigned u;
    asm("cvt.rna.tf32.f32 %0, %1;" : "=r"(u) : "f"(v));
    return __uint_as_float(u);
}
__device__ __forceinline__ float fexp(float x) {
    float y;
    asm("ex2.approx.f32 %0, %1;" : "=f"(y) : "f"(x * LOG2E));
    return y;
}
__device__ __forceinline__ void cp16(unsigned dst, const void* src) {
    asm volatile("cp.async.ca.shared.global [%0], [%1], 16;" :: "r"(dst), "l"(src));
}
__device__ __forceinline__ void ldsm4(unsigned& r0, unsigned& r1, unsigned& r2, unsigned& r3,
                                      unsigned addr) {
    asm volatile("ldmatrix.sync.aligned.m8n8.x4.shared.b16 {%0,%1,%2,%3}, [%4];"
        : "=r"(r0), "=r"(r1), "=r"(r2), "=r"(r3) : "r"(addr));
}
__device__ __forceinline__ void mma_f16(float c[4],
                                        unsigned a0, unsigned a1, unsigned a2, unsigned a3,
                                        unsigned b0, unsigned b1) {
    asm volatile(
        "mma.sync.aligned.m16n8k16.row.col.f32.f16.f16.f32 "
        "{%0,%1,%2,%3}, {%4,%5,%6,%7}, {%8,%9}, {%0,%1,%2,%3};"
        : "+f"(c[0]), "+f"(c[1]), "+f"(c[2]), "+f"(c[3])
        : "r"(a0), "r"(a1), "r"(a2), "r"(a3), "r"(b0), "r"(b1));
}
__device__ __forceinline__ void mma_tf32(float c[4],
                                         unsigned a0, unsigned a1, unsigned a2, unsigned a3,
                                         unsigned b0, unsigned b1) {
    asm volatile(
        "mma.sync.aligned.m16n8k8.row.col.f32.tf32.tf32.f32 "
        "{%0,%1,%2,%3}, {%4,%5,%6,%7}, {%8,%9}, {%0,%1,%2,%3};"
        : "+f"(c[0]), "+f"(c[1]), "+f"(c[2]), "+f"(c[3])
        : "r"(a0), "r"(a1), "r"(a2), "r"(a3), "r"(b0), "r"(b1));
}
__device__ __forceinline__ void atomicMaxFloat(float* addr, float val) {
    int* a = (int*)addr;
    int old = *a;
    while (__int_as_float(old) < val) {
        int assumed = old;
        old = atomicCAS(a, assumed, __float_as_int(val));
        if (old == assumed) break;
    }
}

// ---------------- prep / conversion passes -----------------------------------------
__global__ void prep_small(const float* __restrict__ proj) {
    size_t t = (size_t)blockIdx.x * blockDim.x + threadIdx.x;
    if (t < BHh) g_kmax[t] = -CUDART_INF_F;
    if (t < BHh * LDP) g_kcum[t] = 0.f;
    if (t < 384 * Dd) {
        int m = (int)(t >> 6);
        g_projh[t] = (m < Mm) ? __float2half_rn(proj[t] * NORMALIZER) : __half(0.f);
    }
    if (t < (size_t)BHh * Dd * LDP) {
        size_t bh = t / (Dd * LDP);
        size_t rem = t - bh * (Dd * LDP);
        g_ctxT[bh * 128 * LDP + rem] = 0.f;
    }
}
__global__ void round_xh(const float* __restrict__ in) {
    int i = blockIdx.x * blockDim.x + threadIdx.x;
    float4 v = ((const float4*)in)[i];
    ((__half2*)g_xh)[2*i]   = __floats2half2_rn(v.x, v.y);
    ((__half2*)g_xh)[2*i+1] = __floats2half2_rn(v.z, v.w);
}
__global__ void round_wh(const float* __restrict__ w0, const float* __restrict__ w1,
                         const float* __restrict__ w2, const float* __restrict__ w3) {
    int z = blockIdx.y;
    const float* w = (z == 0) ? w0 : (z == 1) ? w1 : (z == 2) ? w2 : w3;
    int i = blockIdx.x * blockDim.x + threadIdx.x;
    float4 v = ((const float4*)w)[i];
    __half2* o = (__half2*)(g_wh + (size_t)z * DIMM * DIMM);
    o[2*i]   = __floats2half2_rn(v.x, v.y);
    o[2*i+1] = __floats2half2_rn(v.z, v.w);
}
__global__ void fix_kernel() {
    size_t t = (size_t)blockIdx.x * 256 + threadIdx.x;
    const size_t per_bh = (size_t)65 * LDP;
    if (t >= (size_t)BHh * per_bh) return;
    size_t bh = t / per_bh;
    size_t rem = t - bh * per_bh;
    int row = (int)(rem / LDP), m = (int)(rem - (size_t)row * LDP);
    float v = (row < 64) ? g_ctxT[(bh * 128 + row) * LDP + m] : g_kcum[bh * LDP + m];
    g_ctxTh[(bh * 128 + row) * LDP + m] = __float2half_rn(v);
}

// ---------------- fp16 mma core (round-13, unchanged) ----------------------------------
template<bool BIAS, bool DINV, bool RNAF>
__device__ __forceinline__ void mma_core_h(const __half* __restrict__ A, int lda,
                                           const __half* __restrict__ W, int ldb,
                                           __half* __restrict__ Ch,
                                           float* __restrict__ Cf, int ldc,
                                           int K, int nvalid,
                                           const float* __restrict__ bias,
                                           float* __restrict__ maxout, int maxcols, int bhidx) {
    extern __shared__ char smc[];
    __shared__ float mred[4];
    __shared__ float Ds[128];

    const int tid = threadIdx.x;
    const int wid = tid >> 5, lid = tid & 31;
    const int wm = wid >> 1;
    const int wn = wid & 1;
    const int g = lid >> 2, q = lid & 3;

    const int la  = lid & 15;
    const int lka = (lid >> 4) << 3;
    const int lb  = (lid & 7) + ((lid >> 4) << 3);
    const int lkb = ((lid >> 3) & 1) << 3;

    const int lr = tid >> 2;
    const int lc0 = (tid & 3) << 3;

    const unsigned sbase = smem_u32(smc);
    unsigned aoff[4], boff[4];
    #pragma unroll
    for (int i = 0; i < 4; ++i) {
        aoff[i] = sbase + (unsigned)(((lr + 32 * i) * PITCHH + lc0) * 2);
        boff[i] = aoff[i] + (unsigned)HBOFFB;
    }

    const __half* Ag = A + (size_t)lr * lda + lc0;
    const __half* Wg = W + (size_t)lr * ldb + lc0;
    const size_t a32 = (size_t)32 * lda;
    const size_t w32 = (size_t)32 * ldb;

    float acc[4][8][4] = {};
    const int NT = K >> 5;

    {
        #pragma unroll
        for (int i = 0; i < 4; ++i) { cp16(aoff[i], Ag + i * a32); cp16(boff[i], Wg + i * w32); }
        asm volatile("cp.async.commit_group;" ::: "memory");
        if (NT > 1) {
            #pragma unroll
            for (int i = 0; i < 4; ++i) { cp16(aoff[i] + HSTGB, Ag + i * a32 + 32); cp16(boff[i] + HSTGB, Wg + i * w32 + 32); }
        }
        asm volatile("cp.async.commit_group;" ::: "memory");
    }

    int s = 0;
    for (int kt = 0; kt < NT; ++kt) {
        if (kt + 2 < NT) {
            int s2 = s + 2; if (s2 >= STAGES) s2 -= STAGES;
            const unsigned d = (unsigned)(s2 * HSTGB);
            const int kb = (kt + 2) * 32;
            #pragma unroll
            for (int i = 0; i < 4; ++i) { cp16(aoff[i] + d, Ag + i * a32 + kb); cp16(boff[i] + d, Wg + i * w32 + kb); }
        }
        asm volatile("cp.async.commit_group;" ::: "memory");
        asm volatile("cp.async.wait_group 2;" ::: "memory");
        __syncthreads();

        const unsigned sA = sbase + (unsigned)(s * HSTGB);
        const unsigned sB = sA + (unsigned)HBOFFB;

        #pragma unroll
        for (int ks = 0; ks < 32; ks += 16) {
            unsigned af[4][4], bf[8][2];
            #pragma unroll
            for (int mi = 0; mi < 4; ++mi) {
                const int rb = wm * 64 + mi * 16;
                unsigned addr = sA + (unsigned)((((rb + la) * PITCHH) + ks + lka) * 2);
                ldsm4(af[mi][0], af[mi][1], af[mi][2], af[mi][3], addr);
            }
            #pragma unroll
            for (int ni = 0; ni < 8; ni += 2) {
                const int cb = wn * 64 + ni * 8;
                unsigned addr = sB + (unsigned)((((cb + lb) * PITCHH) + ks + lkb) * 2);
                ldsm4(bf[ni][0], bf[ni][1], bf[ni + 1][0], bf[ni + 1][1], addr);
            }
            #pragma unroll
            for (int mi = 0; mi < 4; ++mi)
                #pragma unroll
                for (int ni = 0; ni < 8; ++ni)
                    mma_f16(acc[mi][ni], af[mi][0], af[mi][1], af[mi][2], af[mi][3],
                            bf[ni][0], bf[ni][1]);
        }
        ++s; if (s == STAGES) s = 0;
    }

    if (DINV) {
        if (wn == 1 && q == 0) {
            #pragma unroll
            for (int mi = 0; mi < 4; ++mi) {
                Ds[wm * 64 + mi * 16 + g]     = acc[mi][0][0];
                Ds[wm * 64 + mi * 16 + g + 8] = acc[mi][0][2];
            }
        }
        __syncthreads();
    }

    #pragma unroll
    for (int mi = 0; mi < 4; ++mi) {
        const int r_ = wm * 64 + mi * 16 + g;
        float sc0 = 1.f, sc1 = 1.f;
        if (DINV) { sc0 = 1.f / Ds[r_]; sc1 = 1.f / Ds[r_ + 8]; }
        #pragma unroll
        for (int ni = 0; ni < 8; ++ni) {
            const int crel = wn * 64 + ni * 8 + (q << 1);
            if (crel < nvalid) {
                float2 v0 = make_float2(acc[mi][ni][0], acc[mi][ni][1]);
                float2 v1 = make_float2(acc[mi][ni][2], acc[mi][ni][3]);
                if (BIAS) {
                    v0.x += bias[crel]; v0.y += bias[crel + 1];
                    v1.x += bias[crel]; v1.y += bias[crel + 1];
                }
                if (DINV) {
                    v0.x *= sc0; v0.y *= sc0;
                    v1.x *= sc1; v1.y *= sc1;
                }
                if (Ch) {
                    *(__half2*)&Ch[(size_t)r_ * ldc + crel]       = __floats2half2_rn(v0.x, v0.y);
                    *(__half2*)&Ch[(size_t)(r_ + 8) * ldc + crel] = __floats2half2_rn(v1.x, v1.y);
                } else {
                    if (RNAF) {
                        v0.x = rna_tf32(v0.x); v0.y = rna_tf32(v0.y);
                        v1.x = rna_tf32(v1.x); v1.y = rna_tf32(v1.y);
                    }
                    *(float2*)&Cf[(size_t)r_ * ldc + crel]       = v0;
                    *(float2*)&Cf[(size_t)(r_ + 8) * ldc + crel] = v1;
                }
            }
        }
    }

    if (maxout) {
        float mx = -CUDART_INF_F;
        #pragma unroll
        for (int mi = 0; mi < 4; ++mi)
            #pragma unroll
            for (int ni = 0; ni < 8; ++ni)
                #pragma unroll
                for (int e = 0; e < 4; ++e) {
                    int crel = wn * 64 + ni * 8 + (q << 1) + (e & 1);
                    if (crel < maxcols) mx = fmaxf(mx, acc[mi][ni][e]);
                }
        #pragma unroll
        for (int o = 16; o > 0; o >>= 1)
            mx = fmaxf(mx, __shfl_xor_sync(0xffffffffu, mx, o));
        if (lid == 0) mred[wid] = mx;
        __syncthreads();
        if (tid == 0) {
            float bm = fmaxf(fmaxf(mred[0], mred[1]), fmaxf(mred[2], mred[3]));
            atomicMaxFloat(&maxout[bhidx], bm);
        }
    }
}

// ---------------- wrappers (128 threads) --------------------------------------------
__global__ void __launch_bounds__(128, 2) qk_h() {
    const int z = blockIdx.z;                     // 0 = q, 1 = k
    const __half* W = g_wh + (size_t)z * DIMM * DIMM;
    __half* C = (z == 0) ? g_qh : g_kh;
    const int row0 = blockIdx.y * 128, col0 = blockIdx.x * 128;
    mma_core_h<false, false, false>(g_xh + (size_t)row0 * DIMM, DIMM,
                    W + (size_t)col0 * DIMM, DIMM,
                    C + (size_t)row0 * DIMM + col0, nullptr, DIMM, DIMM, 128,
                    nullptr, nullptr, 0, 0);
}

__global__ void __launch_bounds__(128, 2) v_h() {
    const int row0 = blockIdx.y * 128, col0 = blockIdx.x * 128;
    mma_core_h<false, false, true>(g_xh + (size_t)row0 * DIMM, DIMM,
                    g_wh + 2 * (size_t)DIMM * DIMM + (size_t)col0 * DIMM, DIMM,
                    nullptr, g_v + (size_t)row0 * DIMM + col0, DIMM, DIMM, 128,
                    nullptr, nullptr, 0, 0);
}

__global__ void __launch_bounds__(128, 2) final_h(const float* __restrict__ bo,
                                                  float* __restrict__ out) {
    const int row0 = blockIdx.y * 128, col0 = blockIdx.x * 128;
    mma_core_h<true, false, false>(g_attnh + (size_t)row0 * DIMM, DIMM,
                   g_wh + 3 * (size_t)DIMM * DIMM + (size_t)col0 * DIMM, DIMM,
                   nullptr, out + (size_t)row0 * DIMM + col0, DIMM, DIMM, 128,
                   bo + col0, nullptr, 0, 0);
}

__global__ void __launch_bounds__(128, 2) dash_h() {
    const int z = blockIdx.z;                 // 0 = q, 1 = k
    const __half* src = z ? g_kh : g_qh;
    float* dst = z ? g_kp : g_qp;
    const int bh = blockIdx.y >> 5, nc = blockIdx.y & 31;
    const int b = bh >> 4, h = bh & 15;
    const int col0 = blockIdx.x * 128;
    const int row0 = nc * 128;
    mma_core_h<false, false, false>(src + ((size_t)(b * Nn) + row0) * DIMM + h * Dd, DIMM,
                    g_projh + (size_t)col0 * Dd, Dd,
                    nullptr, dst + ((size_t)bh * Nn + row0) * LDP + col0, LDP,
                    Dd, LDP - col0, nullptr,
                    z ? g_kmax : nullptr, Mm - col0, bh);
}

__global__ void __launch_bounds__(128, 2) out_mma_h() {
    const int t = blockIdx.y;
    const int bh = t >> 5, nt = t & 31;
    const int b = bh >> 4, h = bh & 15;
    const int row0 = nt * 128;
    mma_core_h<false, true, false>(g_qph + ((size_t)bh * Nn + row0) * LDP, LDP,
                    g_ctxTh + (size_t)bh * 128 * LDP, LDP,
                    g_attnh + ((size_t)(b * Nn) + row0) * DIMM + h * Dd, nullptr, DIMM,
                    LDP, Dd, nullptr, nullptr, 0, 0);
}

// ---------------- ctx via tensor cores (TF32, unchanged) ------------------------------
#define CPA 132
#define CPB 68
#define CST 4
__global__ void __launch_bounds__(256) ctx_mma() {
    __shared__ float sa[CST * 16 * CPA];
    __shared__ float sb[CST * 16 * CPB];

    const int tid = threadIdx.x;
    const int wid = tid >> 5, lid = tid & 31;
    const int wm = wid >> 1, wn = wid & 1;
    const int g = lid >> 2, q = lid & 3;
    const int bh = blockIdx.x, b = bh >> 4, h = bh & 15;
    const int m0 = blockIdx.y << 7;
    const int n0 = blockIdx.z << 9;

    const int ar0 = tid >> 5, ac0 = (tid & 31) << 2;
    const int ar1 = ar0 + 8;
    const int br0 = tid >> 4, bc0 = (tid & 15) << 2;

    const unsigned sab = smem_u32(sa);
    const unsigned sbb = smem_u32(sb);
    const unsigned a0off = sab + (unsigned)((ar0 * CPA + ac0) * 4);
    const unsigned a1off = sab + (unsigned)((ar1 * CPA + ac0) * 4);
    const unsigned boff  = sbb + (unsigned)((br0 * CPB + bc0) * 4);
    const unsigned stga = (unsigned)(16 * CPA * 4);
    const unsigned stgb = (unsigned)(16 * CPB * 4);

    const float* Ag0 = g_kp + ((size_t)bh * Nn + n0 + ar0) * LDP + m0 + ac0;
    const float* Ag1 = g_kp + ((size_t)bh * Nn + n0 + ar1) * LDP + m0 + ac0;
    const float* Bg  = g_v  + ((size_t)(b * Nn) + n0 + br0) * DIMM + h * Dd + bc0;

    float acc[2][4][4] = {};
    const int NT = 32;

    {
        cp16(a0off, Ag0); cp16(a1off, Ag1); cp16(boff, Bg);
        asm volatile("cp.async.commit_group;" ::: "memory");
        cp16(a0off + stga, Ag0 + 16 * LDP); cp16(a1off + stga, Ag1 + 16 * LDP);
        cp16(boff + stgb, Bg + 16 * DIMM);
        asm volatile("cp.async.commit_group;" ::: "memory");
    }

    int s = 0;
    for (int kt = 0; kt < NT; ++kt) {
        if (kt + 2 < NT) {
            int s2 = s + 2; if (s2 >= CST) s2 -= CST;
            const int kb = (kt + 2) * 16;
            cp16(a0off + s2 * stga, Ag0 + (size_t)kb * LDP);
            cp16(a1off + s2 * stga, Ag1 + (size_t)kb * LDP);
            cp16(boff  + s2 * stgb, Bg  + (size_t)kb * DIMM);
        }
        asm volatile("cp.async.commit_group;" ::: "memory");
        asm volatile("cp.async.wait_group 2;" ::: "memory");
        __syncthreads();

        const float* As_ = sa + s * 16 * CPA;
        const float* Bs_ = sb + s * 16 * CPB;

        #pragma unroll
        for (int ks = 0; ks < 16; ks += 8) {
            unsigned af[2][4], bf[4][2];
            #pragma unroll
            for (int mi = 0; mi < 2; ++mi) {
                const int rb = wm * 32 + mi * 16;
                af[mi][0] = __float_as_uint(As_[(ks + q) * CPA + rb + g]);
                af[mi][1] = __float_as_uint(As_[(ks + q) * CPA + rb + g + 8]);
                af[mi][2] = __float_as_uint(As_[(ks + q + 4) * CPA + rb + g]);
                af[mi][3] = __float_as_uint(As_[(ks + q + 4) * CPA + rb + g + 8]);
            }
            #pragma unroll
            for (int ni = 0; ni < 4; ++ni) {
                const int cb = wn * 32 + ni * 8;
                bf[ni][0] = __float_as_uint(Bs_[(ks + q) * CPB + cb + g]);
                bf[ni][1] = __float_as_uint(Bs_[(ks + q + 4) * CPB + cb + g]);
            }
            #pragma unroll
            for (int mi = 0; mi < 2; ++mi)
                #pragma unroll
                for (int ni = 0; ni < 4; ++ni)
                    mma_tf32(acc[mi][ni], af[mi][0], af[mi][1], af[mi][2], af[mi][3],
                             bf[ni][0], bf[ni][1]);
        }
        ++s; if (s == CST) s = 0;
    }
    asm volatile("cp.async.wait_group 0;" ::: "memory");

    #pragma unroll
    for (int mi = 0; mi < 2; ++mi) {
        const int mA = m0 + wm * 32 + mi * 16 + g;
        #pragma unroll
        for (int ni = 0; ni < 4; ++ni) {
            const int e0 = wn * 32 + ni * 8 + (q << 1);
            if (mA < Mm) {
                atomicAdd(&g_ctxT[((size_t)bh * 128 + e0) * LDP + mA], acc[mi][ni][0]);
                atomicAdd(&g_ctxT[((size_t)bh * 128 + e0 + 1) * LDP + mA], acc[mi][ni][1]);
            }
            if (mA + 8 < Mm) {
                atomicAdd(&g_ctxT[((size_t)bh * 128 + e0) * LDP + mA + 8], acc[mi][ni][2]);
                atomicAdd(&g_ctxT[((size_t)bh * 128 + e0 + 1) * LDP + mA + 8], acc[mi][ni][3]);
            }
        }
    }
}

// ---------------- exp_q ------------------------------------------------------------
__global__ void __launch_bounds__(256) expq_kernel() {
    const int warp = threadIdx.x >> 5, lane = threadIdx.x & 31;
    const int r = blockIdx.x * 8 + warp;
    const int bh = r >> 12, n = r & 4095;
    const int b = bh >> 4, h = bh & 15;

    const __half* qrow = g_qh + ((size_t)(b * Nn) + n) * DIMM + h * Dd;
    float q0 = __half2float(qrow[lane]), q1 = __half2float(qrow[lane + 32]);
    float s = q0 * q0 + q1 * q1;
    #pragma unroll
    for (int o = 16; o > 0; o >>= 1) s += __shfl_xor_sync(0xffffffffu, s, o);
    const float diag = 0.0625f * s;

    const float* row = g_qp + (size_t)r * LDP;
    __half* orow = g_qph + (size_t)r * LDP;
    float d[9];
    float mx = -CUDART_INF_F;
    #pragma unroll
    for (int i = 0; i < 9; ++i) {
        int m = lane + i * 32;
        d[i] = row[m];
        if (m < Mm) mx = fmaxf(mx, d[i]);
    }
    #pragma unroll
    for (int o = 16; o > 0; o >>= 1) mx = fmaxf(mx, __shfl_xor_sync(0xffffffffu, mx, o));
    const float sub = diag + mx;
    #pragma unroll
    for (int i = 0; i < 9; ++i) {
        int m = lane + i * 32;
        orow[m] = (m < Mm) ? __float2half_rn(RATIO * (fexp(d[i] - sub) + EPSV)) : __half(0.f);
    }
}

// ---------------- exp_k + fused k_cumsum ----------------------------------------------
__global__ void __launch_bounds__(256) expk_kernel() {
    __shared__ float sums[LDP];
    const int tid = threadIdx.x;
    for (int i = tid; i < LDP; i += 256) sums[i] = 0.f;
    __syncthreads();

    const int warp = tid >> 5, lane = tid & 31;
    const int r = blockIdx.x * 8 + warp;
    const int bh = r >> 12, n = r & 4095;
    const int b = bh >> 4, h = bh & 15;

    const __half* krow = g_kh + ((size_t)(b * Nn) + n) * DIMM + h * Dd;
    float k0 = __half2float(krow[lane]), k1 = __half2float(krow[lane + 32]);
    float s = k0 * k0 + k1 * k1;
    #pragma unroll
    for (int o = 16; o > 0; o >>= 1) s += __shfl_xor_sync(0xffffffffu, s, o);
    const float sub = 0.0625f * s + g_kmax[bh];

    float* row = g_kp + (size_t)r * LDP;
    #pragma unroll
    for (int i = 0; i < 9; ++i) {
        int m = lane + i * 32;
        float v = (m < Mm) ? rna_tf32(RATIO * (fexp(row[m] - sub) + EPSV)) : 0.f;
        row[m] = v;
        atomicAdd(&sums[m], v);
    }
    __syncthreads();
    for (int i = tid; i < LDP; i += 256)
        atomicAdd(&g_kcum[bh * LDP + i], sums[i]);
}

// ---------------- launcher --------------------------------------------------------------
extern "C" void kernel_launch(void* const* d_in, const int* in_sizes, int n_in,
                              void* d_out, int out_size) {
    const float* x    = (const float*)d_in[0];
    const float* Wq   = (const float*)d_in[1];
    const float* Wk   = (const float*)d_in[2];
    const float* Wv   = (const float*)d_in[3];
    const float* Wo   = (const float*)d_in[4];
    const float* bo   = (const float*)d_in[5];
    const float* proj = (const float*)d_in[6];
    float* out = (float*)d_out;

    static int init_done = 0;
    static cudaStream_t s1, s2;
    static cudaEvent_t evF, ev1, ev2, evB, evC, evQ, evV;
    if (!init_done) {
        cudaFuncSetAttribute(qk_h,      cudaFuncAttributeMaxDynamicSharedMemorySize, CORE_SMEM);
        cudaFuncSetAttribute(v_h,       cudaFuncAttributeMaxDynamicSharedMemorySize, CORE_SMEM);
        cudaFuncSetAttribute(final_h,   cudaFuncAttributeMaxDynamicSharedMemorySize, CORE_SMEM);
        cudaFuncSetAttribute(dash_h,    cudaFuncAttributeMaxDynamicSharedMemorySize, CORE_SMEM);
        cudaFuncSetAttribute(out_mma_h, cudaFuncAttributeMaxDynamicSharedMemorySize, CORE_SMEM);
        cudaStreamCreateWithFlags(&s1, cudaStreamNonBlocking);
        cudaStreamCreateWithFlags(&s2, cudaStreamNonBlocking);
        cudaEventCreateWithFlags(&evF, cudaEventDisableTiming);
        cudaEventCreateWithFlags(&ev1, cudaEventDisableTiming);
        cudaEventCreateWithFlags(&ev2, cudaEventDisableTiming);
        cudaEventCreateWithFlags(&evB, cudaEventDisableTiming);
        cudaEventCreateWithFlags(&evC, cudaEventDisableTiming);
        cudaEventCreateWithFlags(&evQ, cudaEventDisableTiming);
        cudaEventCreateWithFlags(&evV, cudaEventDisableTiming);
        init_done = 1;
    }

    // fork: rounds + prep in parallel
    cudaEventRecord(evF, 0);
    cudaStreamWaitEvent(s1, evF, 0);
    cudaStreamWaitEvent(s2, evF, 0);

    round_xh<<<ROWS * DIMM / 4 / 256, 256>>>(x);
    round_wh<<<dim3(DIMM * DIMM / 4 / 256, 4), 256, 0, s1>>>(Wq, Wk, Wv, Wo);
    prep_small<<<((unsigned)((size_t)BHh * Dd * LDP + 255) / 256), 256, 0, s2>>>(proj);

    cudaEventRecord(ev1, s1);
    cudaEventRecord(ev2, s2);
    cudaStreamWaitEvent(0, ev1, 0);
    cudaStreamWaitEvent(0, ev2, 0);

    // v projection runs concurrently with qk + downstream chain on s2
    cudaEventRecord(evB, 0);
    cudaStreamWaitEvent(s2, evB, 0);
    v_h<<<dim3(DIMM / 128, ROWS / 128), 128, CORE_SMEM, s2>>>();
    cudaEventRecord(evV, s2);

    qk_h<<<dim3(DIMM / 128, ROWS / 128, 2), 128, CORE_SMEM>>>();
    dash_h<<<dim3(3, BHh * 32, 2), 128, CORE_SMEM>>>();

    // expq on side stream, overlapped with expk -> ctx -> fix
    cudaEventRecord(evC, 0);
    cudaStreamWaitEvent(s1, evC, 0);
    expq_kernel<<<BHh * Nn / 8, 256, 0, s1>>>();
    cudaEventRecord(evQ, s1);

    expk_kernel<<<BHh * Nn / 8, 256>>>();
    cudaStreamWaitEvent(0, evV, 0);
    ctx_mma<<<dim3(BHh, 3, 8), 256>>>();
    fix_kernel<<<(unsigned)(((size_t)BHh * 65 * LDP + 255) / 256), 256>>>();

    cudaStreamWaitEvent(0, evQ, 0);
    out_mma_h<<<dim3(1, BHh * 32), 128, CORE_SMEM>>>();

    final_h<<<dim3(DIMM / 128, ROWS / 128), 128, CORE_SMEM>>>(bo, out);
}

// round 15
// speedup vs baseline: 2.7077x; 1.2249x over previous
#include <cuda_runtime.h>
#include <cuda_fp16.h>
#include <math.h>
#include <math_constants.h>

// Problem constants
#define Bz   2
#define Nn   4096
#define DIMM 1024
#define Hh   16
#define Dd   64
#define Mm   266
#define BHh  (Bz*Hh)        // 32
#define ROWS (Bz*Nn)        // 8192
#define LDP  288            // padded feature row length

#define NORMALIZER 0.35355339059327373f   // 64^-0.25
#define RATIO      0.061313933948496576f  // 266^-0.5
#define EPSV       1e-4f
#define LOG2E      1.4426950408889634f

#define STAGES  4
#define PITCHH  40
#define HSTGB   (128*PITCHH*2)                     // 10240 B per operand stage
#define HBOFFB  (STAGES*HSTGB)                     // 40960 B
#define CORE_SMEM (STAGES*HSTGB*2)                 // 81920 B

// ---------------- scratch -------------------------------------------------------
__device__ __half g_xh[ROWS*DIMM];
__device__ __half g_wh[4*(size_t)DIMM*DIMM];
__device__ __half g_projh[384*Dd];
__device__ __half g_qh[ROWS*DIMM];
__device__ __half g_kh[ROWS*DIMM];
__device__ __half g_vh[ROWS*DIMM];                 // fp16 v for ctx
__device__ __half g_attnh[ROWS*DIMM];
__device__ __half g_qpd[(size_t)BHh*Nn*LDP + 128]; // raw q dash -> features (in-place)
__device__ __half g_kpd[(size_t)BHh*Nn*LDP + 128]; // raw k dash -> features (in-place)
__device__ float  g_kmax[BHh];
__device__ float  g_kcum[BHh*LDP];
__device__ float  g_ctxT[(size_t)BHh*128*LDP];     // fp32 atomics target [e][m]
__device__ __half g_ctxTh[(size_t)BHh*128*LDP];    // row 64 = kcum; 65..127 stay 0

// ---------------- helpers -------------------------------------------------------
__device__ __forceinline__ unsigned smem_u32(const void* p) {
    unsigned a;
    asm("{ .reg .u64 t; cvta.to.shared.u64 t, %1; cvt.u32.u64 %0, t; }" : "=r"(a) : "l"(p));
    return a;
}
__device__ __forceinline__ float fexp(float x) {
    float y;
    asm("ex2.approx.f32 %0, %1;" : "=f"(y) : "f"(x * LOG2E));
    return y;
}
__device__ __forceinline__ void cp16(unsigned dst, const void* src) {
    asm volatile("cp.async.ca.shared.global [%0], [%1], 16;" :: "r"(dst), "l"(src));
}
__device__ __forceinline__ void ldsm4(unsigned& r0, unsigned& r1, unsigned& r2, unsigned& r3,
                                      unsigned addr) {
    asm volatile("ldmatrix.sync.aligned.m8n8.x4.shared.b16 {%0,%1,%2,%3}, [%4];"
        : "=r"(r0), "=r"(r1), "=r"(r2), "=r"(r3) : "r"(addr));
}
__device__ __forceinline__ void ldsm4t(unsigned& r0, unsigned& r1, unsigned& r2, unsigned& r3,
                                       unsigned addr) {
    asm volatile("ldmatrix.sync.aligned.m8n8.x4.trans.shared.b16 {%0,%1,%2,%3}, [%4];"
        : "=r"(r0), "=r"(r1), "=r"(r2), "=r"(r3) : "r"(addr));
}
__device__ __forceinline__ void mma_f16(float c[4],
                                        unsigned a0, unsigned a1, unsigned a2, unsigned a3,
                                        unsigned b0, unsigned b1) {
    asm volatile(
        "mma.sync.aligned.m16n8k16.row.col.f32.f16.f16.f32 "
        "{%0,%1,%2,%3}, {%4,%5,%6,%7}, {%8,%9}, {%0,%1,%2,%3};"
        : "+f"(c[0]), "+f"(c[1]), "+f"(c[2]), "+f"(c[3])
        : "r"(a0), "r"(a1), "r"(a2), "r"(a3), "r"(b0), "r"(b1));
}
__device__ __forceinline__ void atomicMaxFloat(float* addr, float val) {
    int* a = (int*)addr;
    int old = *a;
    while (__int_as_float(old) < val) {
        int assumed = old;
        old = atomicCAS(a, assumed, __float_as_int(val));
        if (old == assumed) break;
    }
}

// ---------------- prep / conversion passes -----------------------------------------
__global__ void prep_small(const float* __restrict__ proj) {
    size_t t = (size_t)blockIdx.x * blockDim.x + threadIdx.x;
    if (t < BHh) g_kmax[t] = -CUDART_INF_F;
    if (t < BHh * LDP) g_kcum[t] = 0.f;
    if (t < 384 * Dd) {
        int m = (int)(t >> 6);
        g_projh[t] = (m < Mm) ? __float2half_rn(proj[t] * NORMALIZER) : __half(0.f);
    }
    if (t < (size_t)BHh * Dd * LDP) {
        size_t bh = t / (Dd * LDP);
        size_t rem = t - bh * (Dd * LDP);
        g_ctxT[bh * 128 * LDP + rem] = 0.f;
    }
}
__global__ void round_xh(const float* __restrict__ in) {
    int i = blockIdx.x * blockDim.x + threadIdx.x;
    float4 v = ((const float4*)in)[i];
    ((__half2*)g_xh)[2*i]   = __floats2half2_rn(v.x, v.y);
    ((__half2*)g_xh)[2*i+1] = __floats2half2_rn(v.z, v.w);
}
__global__ void round_wh(const float* __restrict__ w0, const float* __restrict__ w1,
                         const float* __restrict__ w2, const float* __restrict__ w3) {
    int z = blockIdx.y;
    const float* w = (z == 0) ? w0 : (z == 1) ? w1 : (z == 2) ? w2 : w3;
    int i = blockIdx.x * blockDim.x + threadIdx.x;
    float4 v = ((const float4*)w)[i];
    __half2* o = (__half2*)(g_wh + (size_t)z * DIMM * DIMM);
    o[2*i]   = __floats2half2_rn(v.x, v.y);
    o[2*i+1] = __floats2half2_rn(v.z, v.w);
}
__global__ void fix_kernel() {
    size_t t = (size_t)blockIdx.x * 256 + threadIdx.x;
    const size_t per_bh = (size_t)65 * LDP;
    if (t >= (size_t)BHh * per_bh) return;
    size_t bh = t / per_bh;
    size_t rem = t - bh * per_bh;
    int row = (int)(rem / LDP), m = (int)(rem - (size_t)row * LDP);
    float v = (row < 64) ? g_ctxT[(bh * 128 + row) * LDP + m] : g_kcum[bh * LDP + m];
    g_ctxTh[(bh * 128 + row) * LDP + m] = __float2half_rn(v);
}

// ---------------- fp16 mma core (round-13 structure) -------------------------------
template<bool BIAS, bool DINV>
__device__ __forceinline__ void mma_core_h(const __half* __restrict__ A, int lda,
                                           const __half* __restrict__ W, int ldb,
                                           __half* __restrict__ Ch,
                                           float* __restrict__ Cf, int ldc,
                                           int K, int nvalid,
                                           const float* __restrict__ bias,
                                           float* __restrict__ maxout, int maxcols, int bhidx) {
    extern __shared__ char smc[];
    __shared__ float mred[4];
    __shared__ float Ds[128];

    const int tid = threadIdx.x;
    const int wid = tid >> 5, lid = tid & 31;
    const int wm = wid >> 1;
    const int wn = wid & 1;
    const int g = lid >> 2, q = lid & 3;

    const int la  = lid & 15;
    const int lka = (lid >> 4) << 3;
    const int lb  = (lid & 7) + ((lid >> 4) << 3);
    const int lkb = ((lid >> 3) & 1) << 3;

    const int lr = tid >> 2;
    const int lc0 = (tid & 3) << 3;

    const unsigned sbase = smem_u32(smc);
    unsigned aoff[4], boff[4];
    #pragma unroll
    for (int i = 0; i < 4; ++i) {
        aoff[i] = sbase + (unsigned)(((lr + 32 * i) * PITCHH + lc0) * 2);
        boff[i] = aoff[i] + (unsigned)HBOFFB;
    }

    const __half* Ag = A + (size_t)lr * lda + lc0;
    const __half* Wg = W + (size_t)lr * ldb + lc0;
    const size_t a32 = (size_t)32 * lda;
    const size_t w32 = (size_t)32 * ldb;

    float acc[4][8][4] = {};
    const int NT = K >> 5;

    {
        #pragma unroll
        for (int i = 0; i < 4; ++i) { cp16(aoff[i], Ag + i * a32); cp16(boff[i], Wg + i * w32); }
        asm volatile("cp.async.commit_group;" ::: "memory");
        if (NT > 1) {
            #pragma unroll
            for (int i = 0; i < 4; ++i) { cp16(aoff[i] + HSTGB, Ag + i * a32 + 32); cp16(boff[i] + HSTGB, Wg + i * w32 + 32); }
        }
        asm volatile("cp.async.commit_group;" ::: "memory");
    }

    int s = 0;
    for (int kt = 0; kt < NT; ++kt) {
        if (kt + 2 < NT) {
            int s2 = s + 2; if (s2 >= STAGES) s2 -= STAGES;
            const unsigned d = (unsigned)(s2 * HSTGB);
            const int kb = (kt + 2) * 32;
            #pragma unroll
            for (int i = 0; i < 4; ++i) { cp16(aoff[i] + d, Ag + i * a32 + kb); cp16(boff[i] + d, Wg + i * w32 + kb); }
        }
        asm volatile("cp.async.commit_group;" ::: "memory");
        asm volatile("cp.async.wait_group 2;" ::: "memory");
        __syncthreads();

        const unsigned sA = sbase + (unsigned)(s * HSTGB);
        const unsigned sB = sA + (unsigned)HBOFFB;

        #pragma unroll
        for (int ks = 0; ks < 32; ks += 16) {
            unsigned af[4][4], bf[8][2];
            #pragma unroll
            for (int mi = 0; mi < 4; ++mi) {
                const int rb = wm * 64 + mi * 16;
                unsigned addr = sA + (unsigned)((((rb + la) * PITCHH) + ks + lka) * 2);
                ldsm4(af[mi][0], af[mi][1], af[mi][2], af[mi][3], addr);
            }
            #pragma unroll
            for (int ni = 0; ni < 8; ni += 2) {
                const int cb = wn * 64 + ni * 8;
                unsigned addr = sB + (unsigned)((((cb + lb) * PITCHH) + ks + lkb) * 2);
                ldsm4(bf[ni][0], bf[ni][1], bf[ni + 1][0], bf[ni + 1][1], addr);
            }
            #pragma unroll
            for (int mi = 0; mi < 4; ++mi)
                #pragma unroll
                for (int ni = 0; ni < 8; ++ni)
                    mma_f16(acc[mi][ni], af[mi][0], af[mi][1], af[mi][2], af[mi][3],
                            bf[ni][0], bf[ni][1]);
        }
        ++s; if (s == STAGES) s = 0;
    }

    if (DINV) {
        if (wn == 1 && q == 0) {
            #pragma unroll
            for (int mi = 0; mi < 4; ++mi) {
                Ds[wm * 64 + mi * 16 + g]     = acc[mi][0][0];
                Ds[wm * 64 + mi * 16 + g + 8] = acc[mi][0][2];
            }
        }
        __syncthreads();
    }

    #pragma unroll
    for (int mi = 0; mi < 4; ++mi) {
        const int r_ = wm * 64 + mi * 16 + g;
        float sc0 = 1.f, sc1 = 1.f;
        if (DINV) { sc0 = 1.f / Ds[r_]; sc1 = 1.f / Ds[r_ + 8]; }
        #pragma unroll
        for (int ni = 0; ni < 8; ++ni) {
            const int crel = wn * 64 + ni * 8 + (q << 1);
            if (crel < nvalid) {
                float2 v0 = make_float2(acc[mi][ni][0], acc[mi][ni][1]);
                float2 v1 = make_float2(acc[mi][ni][2], acc[mi][ni][3]);
                if (BIAS) {
                    v0.x += bias[crel]; v0.y += bias[crel + 1];
                    v1.x += bias[crel]; v1.y += bias[crel + 1];
                }
                if (DINV) {
                    v0.x *= sc0; v0.y *= sc0;
                    v1.x *= sc1; v1.y *= sc1;
                }
                if (Ch) {
                    *(__half2*)&Ch[(size_t)r_ * ldc + crel]       = __floats2half2_rn(v0.x, v0.y);
                    *(__half2*)&Ch[(size_t)(r_ + 8) * ldc + crel] = __floats2half2_rn(v1.x, v1.y);
                } else {
                    *(float2*)&Cf[(size_t)r_ * ldc + crel]       = v0;
                    *(float2*)&Cf[(size_t)(r_ + 8) * ldc + crel] = v1;
                }
            }
        }
    }

    if (maxout) {
        float mx = -CUDART_INF_F;
        #pragma unroll
        for (int mi = 0; mi < 4; ++mi)
            #pragma unroll
            for (int ni = 0; ni < 8; ++ni)
                #pragma unroll
                for (int e = 0; e < 4; ++e) {
                    int crel = wn * 64 + ni * 8 + (q << 1) + (e & 1);
                    if (crel < maxcols) mx = fmaxf(mx, acc[mi][ni][e]);
                }
        #pragma unroll
        for (int o = 16; o > 0; o >>= 1)
            mx = fmaxf(mx, __shfl_xor_sync(0xffffffffu, mx, o));
        if (lid == 0) mred[wid] = mx;
        __syncthreads();
        if (tid == 0) {
            float bm = fmaxf(fmaxf(mred[0], mred[1]), fmaxf(mred[2], mred[3]));
            atomicMaxFloat(&maxout[bhidx], bm);
        }
    }
}

// ---------------- wrappers (128 threads) --------------------------------------------
__global__ void __launch_bounds__(128, 2) qk_h() {
    const int z = blockIdx.z;
    const __half* W = g_wh + (size_t)z * DIMM * DIMM;
    __half* C = (z == 0) ? g_qh : g_kh;
    const int row0 = blockIdx.y * 128, col0 = blockIdx.x * 128;
    mma_core_h<false, false>(g_xh + (size_t)row0 * DIMM, DIMM,
                    W + (size_t)col0 * DIMM, DIMM,
                    C + (size_t)row0 * DIMM + col0, nullptr, DIMM, DIMM, 128,
                    nullptr, nullptr, 0, 0);
}

__global__ void __launch_bounds__(128, 2) v_h() {
    const int row0 = blockIdx.y * 128, col0 = blockIdx.x * 128;
    mma_core_h<false, false>(g_xh + (size_t)row0 * DIMM, DIMM,
                    g_wh + 2 * (size_t)DIMM * DIMM + (size_t)col0 * DIMM, DIMM,
                    g_vh + (size_t)row0 * DIMM + col0, nullptr, DIMM, DIMM, 128,
                    nullptr, nullptr, 0, 0);
}

__global__ void __launch_bounds__(128, 2) final_h(const float* __restrict__ bo,
                                                  float* __restrict__ out) {
    const int row0 = blockIdx.y * 128, col0 = blockIdx.x * 128;
    mma_core_h<true, false>(g_attnh + (size_t)row0 * DIMM, DIMM,
                   g_wh + 3 * (size_t)DIMM * DIMM + (size_t)col0 * DIMM, DIMM,
                   nullptr, out + (size_t)row0 * DIMM + col0, DIMM, DIMM, 128,
                   bo + col0, nullptr, 0, 0);
}

__global__ void __launch_bounds__(128, 2) dash_h() {
    const int z = blockIdx.z;                 // 0 = q, 1 = k
    const __half* src = z ? g_kh : g_qh;
    __half* dst = z ? g_kpd : g_qpd;
    const int bh = blockIdx.y >> 5, nc = blockIdx.y & 31;
    const int b = bh >> 4, h = bh & 15;
    const int col0 = blockIdx.x * 128;
    const int row0 = nc * 128;
    mma_core_h<false, false>(src + ((size_t)(b * Nn) + row0) * DIMM + h * Dd, DIMM,
                    g_projh + (size_t)col0 * Dd, Dd,
                    dst + ((size_t)bh * Nn + row0) * LDP + col0, nullptr, LDP,
                    Dd, LDP - col0, nullptr,
                    z ? g_kmax : nullptr, Mm - col0, bh);
}

__global__ void __launch_bounds__(128, 2) out_mma_h() {
    const int t = blockIdx.y;
    const int bh = t >> 5, nt = t & 31;
    const int b = bh >> 4, h = bh & 15;
    const int row0 = nt * 128;
    mma_core_h<false, true>(g_qpd + ((size_t)bh * Nn + row0) * LDP, LDP,
                    g_ctxTh + (size_t)bh * 128 * LDP, LDP,
                    g_attnh + ((size_t)(b * Nn) + row0) * DIMM + h * Dd, nullptr, DIMM,
                    LDP, Dd, nullptr, nullptr, 0, 0);
}

// ---------------- ctx via fp16 tensor cores with ldmatrix.trans ------------------------
// ctx[m][e] = sum_n kp[n][m] * v[n][e].  A and B both from [n][*] tiles via trans frags.
#define PA 136
#define PB 72
#define CCT 4
__global__ void __launch_bounds__(256) ctx_mma_h() {
    __shared__ __half sa[CCT * 16 * PA];
    __shared__ __half sb[CCT * 16 * PB];

    const int tid = threadIdx.x;
    const int wid = tid >> 5, lid = tid & 31;
    const int wm = wid >> 1, wn = wid & 1;      // 4m x 2n
    const int g = lid >> 2, q = lid & 3;
    const int bh = blockIdx.x, b = bh >> 4, h = bh & 15;
    const int m0 = blockIdx.y << 7;             // 0,128,256
    const int n0 = blockIdx.z << 9;             // 512-slabs

    // loaders: A tile 16 x 128 halfs (1 cp16/thread); B tile 16 x 64 halfs (tid<128)
    const int arow = tid >> 4, ac = (tid & 15) << 3;
    const int brow = tid >> 3, bc = (tid & 7) << 3;

    const unsigned sab = smem_u32(sa);
    const unsigned sbb = smem_u32(sb);
    const unsigned aoff = sab + (unsigned)((arow * PA + ac) * 2);
    const unsigned boff = sbb + (unsigned)((brow * PB + bc) * 2);
    const unsigned stga = (unsigned)(16 * PA * 2);
    const unsigned stgb = (unsigned)(16 * PB * 2);

    const __half* Ag = g_kpd + ((size_t)bh * Nn + n0 + arow) * LDP + m0 + ac;
    const __half* Bg = g_vh + ((size_t)(b * Nn) + n0 + brow) * DIMM + h * Dd + bc;

    // trans fragment lane addressing
    const int krowA = (lid & 7) + ((lid >> 4) << 3);
    const int mcolo = ((lid >> 3) & 1) << 3;
    const int krowB = (lid & 7) + (((lid >> 3) & 1) << 3);
    const int ecolo = (lid >> 4) << 3;

    float acc[2][4][4] = {};
    const int NT = 32;                           // 512 / 16

    {
        cp16(aoff, Ag);
        if (tid < 128) cp16(boff, Bg);
        asm volatile("cp.async.commit_group;" ::: "memory");
        cp16(aoff + stga, Ag + 16 * LDP);
        if (tid < 128) cp16(boff + stgb, Bg + 16 * DIMM);
        asm volatile("cp.async.commit_group;" ::: "memory");
    }

    int s = 0;
    for (int kt = 0; kt < NT; ++kt) {
        if (kt + 2 < NT) {
            int s2 = s + 2; if (s2 >= CCT) s2 -= CCT;
            const int kb = (kt + 2) * 16;
            cp16(aoff + s2 * stga, Ag + (size_t)kb * LDP);
            if (tid < 128) cp16(boff + s2 * stgb, Bg + (size_t)kb * DIMM);
        }
        asm volatile("cp.async.commit_group;" ::: "memory");
        asm volatile("cp.async.wait_group 2;" ::: "memory");
        __syncthreads();

        const unsigned sA = sab + (unsigned)(s * stga);
        const unsigned sB = sbb + (unsigned)(s * stgb);

        unsigned af[2][4], bf[4][2];
        #pragma unroll
        for (int mi = 0; mi < 2; ++mi) {
            const int rb = wm * 32 + mi * 16;
            unsigned addr = sA + (unsigned)((krowA * PA + rb + mcolo) * 2);
            ldsm4t(af[mi][0], af[mi][1], af[mi][2], af[mi][3], addr);
        }
        #pragma unroll
        for (int nj = 0; nj < 2; ++nj) {
            const int cb = wn * 32 + nj * 16;
            unsigned addr = sB + (unsigned)((krowB * PB + cb + ecolo) * 2);
            ldsm4t(bf[2*nj][0], bf[2*nj][1], bf[2*nj+1][0], bf[2*nj+1][1], addr);
        }
        #pragma unroll
        for (int mi = 0; mi < 2; ++mi)
            #pragma unroll
            for (int ni = 0; ni < 4; ++ni)
                mma_f16(acc[mi][ni], af[mi][0], af[mi][1], af[mi][2], af[mi][3],
                        bf[ni][0], bf[ni][1]);

        ++s; if (s == CCT) s = 0;
    }
    asm volatile("cp.async.wait_group 0;" ::: "memory");

    #pragma unroll
    for (int mi = 0; mi < 2; ++mi) {
        const int mA = m0 + wm * 32 + mi * 16 + g;
        #pragma unroll
        for (int ni = 0; ni < 4; ++ni) {
            const int e0 = wn * 32 + ni * 8 + (q << 1);
            if (mA < Mm) {
                atomicAdd(&g_ctxT[((size_t)bh * 128 + e0) * LDP + mA], acc[mi][ni][0]);
                atomicAdd(&g_ctxT[((size_t)bh * 128 + e0 + 1) * LDP + mA], acc[mi][ni][1]);
            }
            if (mA + 8 < Mm) {
                atomicAdd(&g_ctxT[((size_t)bh * 128 + e0) * LDP + mA + 8], acc[mi][ni][2]);
                atomicAdd(&g_ctxT[((size_t)bh * 128 + e0 + 1) * LDP + mA + 8], acc[mi][ni][3]);
            }
        }
    }
}

// ---------------- exp_q: in-place half dash -> features --------------------------------
__global__ void __launch_bounds__(256) expq_kernel() {
    const int warp = threadIdx.x >> 5, lane = threadIdx.x & 31;
    const int r = blockIdx.x * 8 + warp;
    const int bh = r >> 12, n = r & 4095;
    const int b = bh >> 4, h = bh & 15;

    const __half* qrow = g_qh + ((size_t)(b * Nn) + n) * DIMM + h * Dd;
    float q0 = __half2float(qrow[lane]), q1 = __half2float(qrow[lane + 32]);
    float s = q0 * q0 + q1 * q1;
    #pragma unroll
    for (int o = 16; o > 0; o >>= 1) s += __shfl_xor_sync(0xffffffffu, s, o);
    const float diag = 0.0625f * s;

    __half* row = g_qpd + (size_t)r * LDP;
    float d[9];
    float mx = -CUDART_INF_F;
    #pragma unroll
    for (int i = 0; i < 9; ++i) {
        int m = lane + i * 32;
        d[i] = __half2float(row[m]);
        if (m < Mm) mx = fmaxf(mx, d[i]);
    }
    #pragma unroll
    for (int o = 16; o > 0; o >>= 1) mx = fmaxf(mx, __shfl_xor_sync(0xffffffffu, mx, o));
    const float sub = diag + mx;
    #pragma unroll
    for (int i = 0; i < 9; ++i) {
        int m = lane + i * 32;
        row[m] = (m < Mm) ? __float2half_rn(RATIO * (fexp(d[i] - sub) + EPSV)) : __half(0.f);
    }
}

// ---------------- exp_k + fused k_cumsum (in-place half) -------------------------------
__global__ void __launch_bounds__(256) expk_kernel() {
    __shared__ float sums[LDP];
    const int tid = threadIdx.x;
    for (int i = tid; i < LDP; i += 256) sums[i] = 0.f;
    __syncthreads();

    const int warp = tid >> 5, lane = tid & 31;
    const int r = blockIdx.x * 8 + warp;
    const int bh = r >> 12, n = r & 4095;
    const int b = bh >> 4, h = bh & 15;

    const __half* krow = g_kh + ((size_t)(b * Nn) + n) * DIMM + h * Dd;
    float k0 = __half2float(krow[lane]), k1 = __half2float(krow[lane + 32]);
    float s = k0 * k0 + k1 * k1;
    #pragma unroll
    for (int o = 16; o > 0; o >>= 1) s += __shfl_xor_sync(0xffffffffu, s, o);
    const float sub = 0.0625f * s + g_kmax[bh];

    __half* row = g_kpd + (size_t)r * LDP;
    #pragma unroll
    for (int i = 0; i < 9; ++i) {
        int m = lane + i * 32;
        if (m < Mm) {
            __half hv = __float2half_rn(RATIO * (fexp(__half2float(row[m]) - sub) + EPSV));
            row[m] = hv;
            atomicAdd(&sums[m], __half2float(hv));
        } else {
            row[m] = __half(0.f);
        }
    }
    __syncthreads();
    for (int i = tid; i < LDP; i += 256)
        atomicAdd(&g_kcum[bh * LDP + i], sums[i]);
}

// ---------------- launcher --------------------------------------------------------------
extern "C" void kernel_launch(void* const* d_in, const int* in_sizes, int n_in,
                              void* d_out, int out_size) {
    const float* x    = (const float*)d_in[0];
    const float* Wq   = (const float*)d_in[1];
    const float* Wk   = (const float*)d_in[2];
    const float* Wv   = (const float*)d_in[3];
    const float* Wo   = (const float*)d_in[4];
    const float* bo   = (const float*)d_in[5];
    const float* proj = (const float*)d_in[6];
    float* out = (float*)d_out;

    static int init_done = 0;
    static cudaStream_t s1, s2;
    static cudaEvent_t evF, ev1, ev2, evB, evC, evQ, evV;
    if (!init_done) {
        cudaFuncSetAttribute(qk_h,      cudaFuncAttributeMaxDynamicSharedMemorySize, CORE_SMEM);
        cudaFuncSetAttribute(v_h,       cudaFuncAttributeMaxDynamicSharedMemorySize, CORE_SMEM);
        cudaFuncSetAttribute(final_h,   cudaFuncAttributeMaxDynamicSharedMemorySize, CORE_SMEM);
        cudaFuncSetAttribute(dash_h,    cudaFuncAttributeMaxDynamicSharedMemorySize, CORE_SMEM);
        cudaFuncSetAttribute(out_mma_h, cudaFuncAttributeMaxDynamicSharedMemorySize, CORE_SMEM);
        cudaStreamCreateWithFlags(&s1, cudaStreamNonBlocking);
        cudaStreamCreateWithFlags(&s2, cudaStreamNonBlocking);
        cudaEventCreateWithFlags(&evF, cudaEventDisableTiming);
        cudaEventCreateWithFlags(&ev1, cudaEventDisableTiming);
        cudaEventCreateWithFlags(&ev2, cudaEventDisableTiming);
        cudaEventCreateWithFlags(&evB, cudaEventDisableTiming);
        cudaEventCreateWithFlags(&evC, cudaEventDisableTiming);
        cudaEventCreateWithFlags(&evQ, cudaEventDisableTiming);
        cudaEventCreateWithFlags(&evV, cudaEventDisableTiming);
        init_done = 1;
    }

    cudaEventRecord(evF, 0);
    cudaStreamWaitEvent(s1, evF, 0);
    cudaStreamWaitEvent(s2, evF, 0);

    round_xh<<<ROWS * DIMM / 4 / 256, 256>>>(x);
    round_wh<<<dim3(DIMM * DIMM / 4 / 256, 4), 256, 0, s1>>>(Wq, Wk, Wv, Wo);
    prep_small<<<((unsigned)((size_t)BHh * Dd * LDP + 255) / 256), 256, 0, s2>>>(proj);

    cudaEventRecord(ev1, s1);
    cudaEventRecord(ev2, s2);
    cudaStreamWaitEvent(0, ev1, 0);
    cudaStreamWaitEvent(0, ev2, 0);

    cudaEventRecord(evB, 0);
    cudaStreamWaitEvent(s2, evB, 0);
    v_h<<<dim3(DIMM / 128, ROWS / 128), 128, CORE_SMEM, s2>>>();
    cudaEventRecord(evV, s2);

    qk_h<<<dim3(DIMM / 128, ROWS / 128, 2), 128, CORE_SMEM>>>();
    dash_h<<<dim3(3, BHh * 32, 2), 128, CORE_SMEM>>>();

    cudaEventRecord(evC, 0);
    cudaStreamWaitEvent(s1, evC, 0);
    expq_kernel<<<BHh * Nn / 8, 256, 0, s1>>>();
    cudaEventRecord(evQ, s1);

    expk_kernel<<<BHh * Nn / 8, 256>>>();
    cudaStreamWaitEvent(0, evV, 0);
    ctx_mma_h<<<dim3(BHh, 3, 8), 256>>>();
    fix_kernel<<<(unsigned)(((size_t)BHh * 65 * LDP + 255) / 256), 256>>>();

    cudaStreamWaitEvent(0, evQ, 0);
    out_mma_h<<<dim3(1, BHh * 32), 128, CORE_SMEM>>>();

    final_h<<<dim3(DIMM / 128, ROWS / 128), 128, CORE_SMEM>>>(bo, out);
}